// round 4
// baseline (speedup 1.0000x reference)
#include <cuda_runtime.h>
#include <cuda_fp16.h>
#include <cstdint>

#define B_    64
#define P_    49
#define ENC_  1280
#define T_    25
#define V_    10000
#define E_    512
#define H_    1024
#define A_    512
#define GK_   2816   /* E + ENC + H */
#define K1_   1792   /* E + ENC */

#define BM 64
#define BN 64
#define BK 64
#define STG 4
#define RS 72        /* smem row stride in halves (64 + 8 pad) */
#define SMEM_BYTES (STG * (BM + BN) * RS * 2)

#define NLOGIT ((V_ + 63) / 64)   /* 157 */
#define G_ 296                     /* persistent grid: 2 blocks x 148 SMs */

// ---------------- static scratch (no allocs) ----------------
__device__ __align__(16) __half g_Wout [V_ * H_];
__device__ __align__(16) __half g_Wg   [4 * H_ * GK_];
__device__ __align__(16) __half g_Wdatt[A_ * H_];
__device__ __align__(16) __half g_Weatt[A_ * ENC_];
__device__ __align__(16) __half g_Wh0  [H_ * ENC_];
__device__ __align__(16) __half g_Wc0  [H_ * ENC_];
__device__ __align__(16) __half g_ench [B_ * P_ * ENC_];
__device__ __align__(16) __half g_meanh[B_ * ENC_];
__device__ __align__(16) __half g_hbuf [2 * B_ * H_];
__device__ __align__(16) __half g_gin  [B_ * GK_];
__device__ __align__(16) float  g_cbuf [2 * B_ * H_];
__device__ __align__(16) float  g_att1 [B_ * P_ * A_];
__device__ __align__(16) float  g_att2p[8 * B_ * A_];
__device__ __align__(16) float  g_gatesp[4 * B_ * 4 * H_];

__device__ unsigned g_bar;
__global__ void reset_bar() { g_bar = 0u; }

// ---------------- grid barrier (all G_ blocks co-resident) -----------------
__device__ __forceinline__ void gsync(unsigned& epoch) {
    __syncthreads();
    epoch += G_;
    if (threadIdx.x == 0) {
        __threadfence();
        atomicAdd(&g_bar, 1u);
        unsigned v;
        do {
            asm volatile("ld.volatile.global.u32 %0, [%1];" : "=r"(v) : "l"(&g_bar));
        } while (v < epoch);
        __threadfence();
    }
    __syncthreads();
}

// ---------------- setup: convert to fp16 ----------------
#define S0 (A_ * H_)
#define S1 (S0 + V_ * H_)
#define S2 (S1 + A_ * ENC_)
#define S3 (S2 + H_ * ENC_)
#define S4 (S3 + H_ * ENC_)
#define S5 (S4 + B_ * P_ * ENC_)
#define S6 (S5 + 4 * H_ * K1_)
#define S7 (S6 + 4 * H_ * H_)

__global__ void cvt_all(const float* __restrict__ Wd, const float* __restrict__ Wo,
                        const float* __restrict__ We, const float* __restrict__ Wh0,
                        const float* __restrict__ Wc0, const float* __restrict__ enc,
                        const float* __restrict__ Wih, const float* __restrict__ Whh)
{
    int i = blockIdx.x * 256 + threadIdx.x;
    if (i >= S7) return;
    if (i < S0)      g_Wdatt[i]      = __float2half(Wd[i]);
    else if (i < S1) g_Wout[i - S0]  = __float2half(Wo[i - S0]);
    else if (i < S2) g_Weatt[i - S1] = __float2half(We[i - S1]);
    else if (i < S3) g_Wh0[i - S2]   = __float2half(Wh0[i - S2]);
    else if (i < S4) g_Wc0[i - S3]   = __float2half(Wc0[i - S3]);
    else if (i < S5) g_ench[i - S4]  = __float2half(enc[i - S4]);
    else if (i < S6) {
        int j = i - S5; int r = j / K1_, c = j % K1_;
        g_Wg[(size_t)r * GK_ + c] = __float2half(Wih[j]);
    } else {
        int j = i - S6; int r = j / H_, c = j % H_;
        g_Wg[(size_t)r * GK_ + K1_ + c] = __float2half(Whh[j]);
    }
}

__global__ void mean_kernel(const float* __restrict__ enc) {
    int i = blockIdx.x * blockDim.x + threadIdx.x;
    if (i >= B_ * ENC_) return;
    int b = i / ENC_, e = i % ENC_;
    const float* p = enc + (size_t)b * P_ * ENC_ + e;
    float s = 0.f;
#pragma unroll 7
    for (int k = 0; k < P_; k++) s += p[k * ENC_];
    g_meanh[i] = __float2half(s * (1.0f / P_));
}

// ---------------- fp16 GEMM core ----------------
__device__ __forceinline__ void issue_tile(
    const __half* __restrict__ A, int lda,
    const __half* __restrict__ B, int ldb,
    int bm, int bn, int N, int kt,
    __half* as, __half* bs, int tid)
{
#pragma unroll
    for (int i = 0; i < 4; i++) {
        int idx = i * 128 + tid;
        int r = idx >> 3, c8 = (idx & 7) * 8;
        uint32_t da = (uint32_t)__cvta_generic_to_shared(as + r * RS + c8);
        const __half* pa = A + (size_t)(bm + r) * lda + kt + c8;
        asm volatile("cp.async.cg.shared.global [%0], [%1], 16;" :: "r"(da), "l"(pa));
        int n = bn + r;
        uint32_t db = (uint32_t)__cvta_generic_to_shared(bs + r * RS + c8);
        const __half* pb = B + (size_t)(n < N ? n : 0) * ldb + kt + c8;
        int sz = (n < N) ? 16 : 0;
        asm volatile("cp.async.cg.shared.global [%0], [%1], 16, %2;" :: "r"(db), "l"(pb), "r"(sz));
    }
    asm volatile("cp.async.commit_group;");
}

__device__ __forceinline__ void gemm_core(
    const __half* __restrict__ A, int lda,
    const __half* __restrict__ Bm, int ldb,
    const float* __restrict__ bias,
    float* __restrict__ Cf, __half* __restrict__ Ch,
    int ldc, int partStride, int N, int kChunk,
    int bm, int by, int z)
{
    extern __shared__ __half sm[];
    __half* Asm = sm;
    __half* Bsm = sm + STG * BM * RS;

    const int tid = threadIdx.x;
    const int warp = tid >> 5, lane = tid & 31;
    const int wm = warp >> 1, wn = warp & 1;
    const int bn = by * BN;
    const int k0 = z * kChunk;
    const int nk = kChunk / BK;

    float acc[2][4][4];
#pragma unroll
    for (int i = 0; i < 2; i++)
#pragma unroll
        for (int j = 0; j < 4; j++)
#pragma unroll
            for (int q = 0; q < 4; q++) acc[i][j][q] = 0.f;

#pragma unroll
    for (int s = 0; s < STG - 1; s++) {
        if (s < nk) issue_tile(A, lda, Bm, ldb, bm, bn, N, k0 + s * BK,
                               Asm + s * BM * RS, Bsm + s * BN * RS, tid);
        else asm volatile("cp.async.commit_group;");
    }

    for (int i = 0; i < nk; i++) {
        asm volatile("cp.async.wait_group %0;" :: "n"(STG - 2));
        __syncthreads();

        int ntile = i + STG - 1;
        if (ntile < nk) {
            int slot = ntile % STG;
            issue_tile(A, lda, Bm, ldb, bm, bn, N, k0 + ntile * BK,
                       Asm + slot * BM * RS, Bsm + slot * BN * RS, tid);
        } else {
            asm volatile("cp.async.commit_group;");
        }

        const uint32_t* aw = (const uint32_t*)(Asm + (i % STG) * BM * RS);
        const uint32_t* bw = (const uint32_t*)(Bsm + (i % STG) * BN * RS);

#pragma unroll
        for (int ks = 0; ks < 4; ks++) {
            uint32_t af[2][4], bf[4][2];
            const int c = ks * 8 + (lane & 3);
#pragma unroll
            for (int mt = 0; mt < 2; mt++) {
                int r = wm * 32 + mt * 16 + (lane >> 2);
                af[mt][0] = aw[r * 36 + c];
                af[mt][1] = aw[(r + 8) * 36 + c];
                af[mt][2] = aw[r * 36 + c + 4];
                af[mt][3] = aw[(r + 8) * 36 + c + 4];
            }
#pragma unroll
            for (int nt = 0; nt < 4; nt++) {
                int n = wn * 32 + nt * 8 + (lane >> 2);
                bf[nt][0] = bw[n * 36 + c];
                bf[nt][1] = bw[n * 36 + c + 4];
            }
#pragma unroll
            for (int mt = 0; mt < 2; mt++)
#pragma unroll
                for (int nt = 0; nt < 4; nt++)
                    asm volatile(
                        "mma.sync.aligned.m16n8k16.row.col.f32.f16.f16.f32 "
                        "{%0,%1,%2,%3}, {%4,%5,%6,%7}, {%8,%9}, {%0,%1,%2,%3};"
                        : "+f"(acc[mt][nt][0]), "+f"(acc[mt][nt][1]),
                          "+f"(acc[mt][nt][2]), "+f"(acc[mt][nt][3])
                        : "r"(af[mt][0]), "r"(af[mt][1]), "r"(af[mt][2]), "r"(af[mt][3]),
                          "r"(bf[nt][0]), "r"(bf[nt][1]));
        }
    }

    // drain pipeline: gemm_core may be re-invoked on the same smem by this block
    asm volatile("cp.async.wait_group 0;");
    __syncthreads();

    float* Cz = Cf + (size_t)z * partStride;
#pragma unroll
    for (int mt = 0; mt < 2; mt++) {
        int r0 = bm + wm * 32 + mt * 16 + (lane >> 2);
#pragma unroll
        for (int nt = 0; nt < 4; nt++) {
            int cg = bn + wn * 32 + nt * 8 + (lane & 3) * 2;
            float bv0 = 0.f, bv1 = 0.f;
            if (bias) {
                if (cg < N) bv0 = bias[cg];
                if (cg + 1 < N) bv1 = bias[cg + 1];
            }
            float v00 = acc[mt][nt][0] + bv0, v01 = acc[mt][nt][1] + bv1;
            float v10 = acc[mt][nt][2] + bv0, v11 = acc[mt][nt][3] + bv1;
            if (Ch) {
                if (cg < N) {
                    Ch[(size_t)r0 * ldc + cg]       = __float2half(v00);
                    Ch[(size_t)(r0 + 8) * ldc + cg] = __float2half(v10);
                }
                if (cg + 1 < N) {
                    Ch[(size_t)r0 * ldc + cg + 1]       = __float2half(v01);
                    Ch[(size_t)(r0 + 8) * ldc + cg + 1] = __float2half(v11);
                }
            } else {
                if (cg < N) {
                    Cz[(size_t)r0 * ldc + cg]       = v00;
                    Cz[(size_t)(r0 + 8) * ldc + cg] = v10;
                }
                if (cg + 1 < N) {
                    Cz[(size_t)r0 * ldc + cg + 1]       = v01;
                    Cz[(size_t)(r0 + 8) * ldc + cg + 1] = v11;
                }
            }
        }
    }
}

__global__ void __launch_bounds__(128)
hgemm(const __half* __restrict__ A, int lda,
      const __half* __restrict__ Bm, int ldb,
      const float* __restrict__ bias,
      float* __restrict__ Cf, __half* __restrict__ Ch,
      int ldc, int partStride, int N, int kChunk)
{
    gemm_core(A, lda, Bm, ldb, bias, Cf, Ch, ldc, partStride, N, kChunk,
              blockIdx.x * BM, blockIdx.y, blockIdx.z);
}

// ---------------- attention phase (128 threads, one task per batch b) ------
__device__ void attn_phase(int b, int t,
                           const int* __restrict__ captions,
                           const float* __restrict__ embed,
                           const float* __restrict__ b_datt,
                           const float* __restrict__ W_fatt,
                           const float* __restrict__ b_fatt,
                           const __half* __restrict__ hprev,
                           float* att2s, float* es)
{
    int tid = threadIdx.x;
    int warp = tid >> 5, lane = tid & 31;

    for (int a = tid; a < A_; a += 128) {
        float s = b_datt[a];
#pragma unroll
        for (int zz = 0; zz < 8; zz++) s += g_att2p[zz * B_ * A_ + b * A_ + a];
        att2s[a] = s;
    }
    __syncthreads();

    const float* att1b = g_att1 + (size_t)b * P_ * A_;
    for (int p = warp; p < P_; p += 4) {
        float s = 0.f;
        for (int a = lane; a < A_; a += 32) {
            float v = att1b[p * A_ + a] + att2s[a];
            s += fmaxf(v, 0.f) * W_fatt[a];
        }
#pragma unroll
        for (int o = 16; o; o >>= 1) s += __shfl_xor_sync(0xffffffffu, s, o);
        if (lane == 0) es[p] = s + b_fatt[0];
    }
    __syncthreads();

    if (warp == 0) {
        float v0 = (lane < P_) ? es[lane] : -1e30f;
        float v1 = (lane + 32 < P_) ? es[lane + 32] : -1e30f;
        float m = fmaxf(v0, v1);
#pragma unroll
        for (int o = 16; o; o >>= 1) m = fmaxf(m, __shfl_xor_sync(0xffffffffu, m, o));
        float e0 = (lane < P_) ? __expf(v0 - m) : 0.f;
        float e1 = (lane + 32 < P_) ? __expf(v1 - m) : 0.f;
        float s = e0 + e1;
#pragma unroll
        for (int o = 16; o; o >>= 1) s += __shfl_xor_sync(0xffffffffu, s, o);
        float inv = 1.0f / s;
        if (lane < P_) es[lane] = e0 * inv;
        if (lane + 32 < P_) es[lane + 32] = e1 * inv;
    }
    __syncthreads();

    __half* gin = g_gin + (size_t)b * GK_;
    int cap = captions[b * T_ + t];
    const float* erow = embed + (size_t)cap * E_;
    for (int i = tid; i < E_; i += 128) gin[i] = __float2half(erow[i]);

    const __half* encb = g_ench + (size_t)b * P_ * ENC_;
    for (int e = tid; e < ENC_; e += 128) {
        float s = 0.f;
#pragma unroll 7
        for (int p = 0; p < P_; p++) s += es[p] * __half2float(encb[p * ENC_ + e]);
        gin[E_ + e] = __float2half(s);
    }
    for (int j = tid; j < H_; j += 128) gin[K1_ + j] = hprev[b * H_ + j];
}

// ---------------- persistent mega-kernel: the whole 24-step loop -----------
__global__ void __launch_bounds__(128)
persist_kernel(const int* __restrict__ captions,
               const float* __restrict__ embed,
               const float* __restrict__ b_datt,
               const float* __restrict__ W_fatt,
               const float* __restrict__ b_fatt,
               const float* __restrict__ b_ih,
               const float* __restrict__ b_hh,
               const float* __restrict__ b_out,
               float* __restrict__ out)
{
    __shared__ float s_att2[A_];
    __shared__ float s_es[P_];

    const int bid = blockIdx.x;
    const int tid = threadIdx.x;
    const int BH = B_ * H_;
    unsigned epoch = 0;

    for (int t = 0; t < T_ - 1; t++) {
        const __half* h_cur = g_hbuf + (t & 1) * BH;
        const float*  c_cur = g_cbuf + (t & 1) * BH;
        __half* h_nxt = g_hbuf + ((t + 1) & 1) * BH;
        float*  c_nxt = g_cbuf + ((t + 1) & 1) * BH;

        // phase 1: attention + gin (64 tasks)
        if (bid < B_)
            attn_phase(bid, t, captions, embed, b_datt, W_fatt, b_fatt, h_cur,
                       s_att2, s_es);
        gsync(epoch);

        // phase 2: gates partials, split-K 4 (256 tasks)
        for (int task = bid; task < 256; task += G_) {
            int by = task & 63, z = task >> 6;
            gemm_core(g_gin, GK_, g_Wg, GK_, nullptr, g_gatesp, nullptr,
                      4 * H_, B_ * 4 * H_, 4 * H_, GK_ / 4, 0, by, z);
        }
        gsync(epoch);

        // phase 3: LSTM pointwise (grid-stride)
        for (int i = bid * 128 + tid; i < BH; i += G_ * 128) {
            int b = i >> 10, j = i & (H_ - 1);
            size_t base = (size_t)b * 4 * H_ + j;
            float gi = 0.f, gf = 0.f, gg = 0.f, go = 0.f;
#pragma unroll
            for (int zz = 0; zz < 4; zz++) {
                const float* gp = g_gatesp + (size_t)zz * B_ * 4 * H_ + base;
                gi += gp[0]; gf += gp[H_]; gg += gp[2 * H_]; go += gp[3 * H_];
            }
            gi += b_ih[j]          + b_hh[j];
            gf += b_ih[H_ + j]     + b_hh[H_ + j];
            gg += b_ih[2 * H_ + j] + b_hh[2 * H_ + j];
            go += b_ih[3 * H_ + j] + b_hh[3 * H_ + j];
            float si = 1.f / (1.f + __expf(-gi));
            float sf = 1.f / (1.f + __expf(-gf));
            float so = 1.f / (1.f + __expf(-go));
            float tg = tanhf(gg);
            float c  = sf * c_cur[i] + si * tg;
            c_nxt[i] = c;
            h_nxt[i] = __float2half(so * tanhf(c));
        }
        gsync(epoch);

        // phase 4: logits(t) + att2(t+1) (221 tasks)
        for (int task = bid; task < NLOGIT + 64; task += G_) {
            if (task < NLOGIT) {
                gemm_core(h_nxt, H_, g_Wout, H_, b_out, out + (size_t)t * V_, nullptr,
                          (T_ - 1) * V_, 0, V_, H_, 0, task, 0);
            } else {
                int i = task - NLOGIT;
                gemm_core(h_nxt, H_, g_Wdatt, H_, nullptr, g_att2p, nullptr,
                          A_, B_ * A_, A_, H_ / 8, 0, i & 7, i >> 3);
            }
        }
        gsync(epoch);
    }
}

// ---------------- host ----------------
template <typename T>
static T* sym_addr(const void* sym) {
    void* p = nullptr;
    cudaGetSymbolAddress(&p, sym);
    return (T*)p;
}

extern "C" void kernel_launch(void* const* d_in, const int* in_sizes, int n_in,
                              void* d_out, int out_size)
{
    const float* enc    = (const float*)d_in[0];
    const int*   caps   = (const int*)  d_in[1];
    const float* embed  = (const float*)d_in[2];
    const float* W_eatt = (const float*)d_in[3];
    const float* b_eatt = (const float*)d_in[4];
    const float* W_datt = (const float*)d_in[5];
    const float* b_datt = (const float*)d_in[6];
    const float* W_fatt = (const float*)d_in[7];
    const float* b_fatt = (const float*)d_in[8];
    const float* W_ih   = (const float*)d_in[9];
    const float* b_ih   = (const float*)d_in[10];
    const float* W_hh   = (const float*)d_in[11];
    const float* b_hh   = (const float*)d_in[12];
    const float* W_h0   = (const float*)d_in[13];
    const float* b_h0   = (const float*)d_in[14];
    const float* W_c0   = (const float*)d_in[15];
    const float* b_c0   = (const float*)d_in[16];
    const float* W_out  = (const float*)d_in[17];
    const float* b_out  = (const float*)d_in[18];
    float* out = (float*)d_out;

    cudaFuncSetAttribute(hgemm, cudaFuncAttributeMaxDynamicSharedMemorySize, SMEM_BYTES);
    cudaFuncSetAttribute(persist_kernel, cudaFuncAttributeMaxDynamicSharedMemorySize, SMEM_BYTES);

    __half* Wdth  = sym_addr<__half>(g_Wdatt);
    __half* Weth  = sym_addr<__half>(g_Weatt);
    __half* Wh0h  = sym_addr<__half>(g_Wh0);
    __half* Wc0h  = sym_addr<__half>(g_Wc0);
    __half* ench  = sym_addr<__half>(g_ench);
    __half* meanh = sym_addr<__half>(g_meanh);
    __half* hbuf  = sym_addr<__half>(g_hbuf);
    float*  cbuf  = sym_addr<float>(g_cbuf);
    float*  att1  = sym_addr<float>(g_att1);
    float*  att2p = sym_addr<float>(g_att2p);

    // ---- one-time setup ----
    mean_kernel<<<(B_ * ENC_ + 255) / 256, 256>>>(enc);
    cvt_all<<<(S7 + 255) / 256, 256>>>(W_datt, W_out, W_eatt, W_h0, W_c0, enc, W_ih, W_hh);
    hgemm<<<dim3(1, H_ / 64, 1), 128, SMEM_BYTES>>>(meanh, ENC_, Wh0h, ENC_, b_h0,
                                                    nullptr, hbuf, H_, 0, H_, ENC_);
    hgemm<<<dim3(1, H_ / 64, 1), 128, SMEM_BYTES>>>(meanh, ENC_, Wc0h, ENC_, b_c0,
                                                    cbuf, nullptr, H_, 0, H_, ENC_);
    hgemm<<<dim3((B_ * P_) / 64, A_ / 64, 1), 128, SMEM_BYTES>>>(ench, ENC_, Weth, ENC_, b_eatt,
                                                                 att1, nullptr, A_, 0, A_, ENC_);
    hgemm<<<dim3(1, A_ / 64, 8), 128, SMEM_BYTES>>>(hbuf, H_, Wdth, H_, nullptr,
                                                    att2p, nullptr, A_, B_ * A_, A_, H_ / 8);

    // ---- persistent loop: all 24 steps in one kernel ----
    reset_bar<<<1, 1>>>();
    persist_kernel<<<G_, 128, SMEM_BYTES>>>(caps, embed, b_datt, W_fatt, b_fatt,
                                            b_ih, b_hh, b_out, out);
}

// round 5
// speedup vs baseline: 1.2415x; 1.2415x over previous
#include <cuda_runtime.h>
#include <cuda_fp16.h>
#include <cstdint>

#define B_    64
#define P_    49
#define ENC_  1280
#define T_    25
#define V_    10000
#define E_    512
#define H_    1024
#define A_    512
#define GK_   2816   /* E + ENC + H */
#define K1_   1792   /* E + ENC */

#define BM 64
#define BN 128
#define BK 64
#define STG 3
#define RS 72        /* smem row stride in halves (64 + 8 pad) */
#define SMEM_BYTES (STG * (BM + BN) * RS * 2)

#define NLOGIT ((V_ + BN - 1) / BN)   /* 79 */

// ---------------- static scratch (no allocs) ----------------
__device__ __align__(16) __half g_Wout [V_ * H_];
__device__ __align__(16) __half g_Wg   [4 * H_ * GK_];
__device__ __align__(16) __half g_Wdatt[A_ * H_];
__device__ __align__(16) __half g_Weatt[A_ * ENC_];
__device__ __align__(16) __half g_Wh0  [H_ * ENC_];
__device__ __align__(16) __half g_Wc0  [H_ * ENC_];
__device__ __align__(16) __half g_ench [B_ * P_ * ENC_];
__device__ __align__(16) __half g_meanh[B_ * ENC_];
__device__ __align__(16) __half g_hbuf [2 * B_ * H_];
__device__ __align__(16) __half g_gin  [B_ * GK_];
__device__ __align__(16) float  g_cbuf [2 * B_ * H_];
__device__ __align__(16) float  g_att1 [B_ * P_ * A_];
__device__ __align__(16) float  g_att2p[8 * B_ * A_];
__device__ __align__(16) float  g_gatesp[4 * B_ * 4 * H_];

// ---------------- setup: convert to fp16 ----------------
#define S0 (A_ * H_)
#define S1 (S0 + V_ * H_)
#define S2 (S1 + A_ * ENC_)
#define S3 (S2 + H_ * ENC_)
#define S4 (S3 + H_ * ENC_)
#define S5 (S4 + B_ * P_ * ENC_)
#define S6 (S5 + 4 * H_ * K1_)
#define S7 (S6 + 4 * H_ * H_)

__global__ void cvt_all(const float* __restrict__ Wd, const float* __restrict__ Wo,
                        const float* __restrict__ We, const float* __restrict__ Wh0,
                        const float* __restrict__ Wc0, const float* __restrict__ enc,
                        const float* __restrict__ Wih, const float* __restrict__ Whh)
{
    int i = blockIdx.x * 256 + threadIdx.x;
    if (i >= S7) return;
    if (i < S0)      g_Wdatt[i]      = __float2half(Wd[i]);
    else if (i < S1) g_Wout[i - S0]  = __float2half(Wo[i - S0]);
    else if (i < S2) g_Weatt[i - S1] = __float2half(We[i - S1]);
    else if (i < S3) g_Wh0[i - S2]   = __float2half(Wh0[i - S2]);
    else if (i < S4) g_Wc0[i - S3]   = __float2half(Wc0[i - S3]);
    else if (i < S5) g_ench[i - S4]  = __float2half(enc[i - S4]);
    else if (i < S6) {
        int j = i - S5; int r = j / K1_, c = j % K1_;
        g_Wg[(size_t)r * GK_ + c] = __float2half(Wih[j]);
    } else {
        int j = i - S6; int r = j / H_, c = j % H_;
        g_Wg[(size_t)r * GK_ + K1_ + c] = __float2half(Whh[j]);
    }
}

__global__ void mean_kernel(const float* __restrict__ enc) {
    int i = blockIdx.x * blockDim.x + threadIdx.x;
    if (i >= B_ * ENC_) return;
    int b = i / ENC_, e = i % ENC_;
    const float* p = enc + (size_t)b * P_ * ENC_ + e;
    float s = 0.f;
#pragma unroll 7
    for (int k = 0; k < P_; k++) s += p[k * ENC_];
    g_meanh[i] = __float2half(s * (1.0f / P_));
}

// ---------------- fp16 GEMM core (256 thr, 64x128 tile, ldmatrix) ----------
__device__ __forceinline__ void issue_tile(
    const __half* __restrict__ A, int lda,
    const __half* __restrict__ B, int ldb,
    int bm, int bn, int N, int kt,
    __half* as, __half* bs, int tid)
{
#pragma unroll
    for (int i = 0; i < 2; i++) {          // A: 64x64 halves
        int idx = i * 256 + tid;
        int r = idx >> 3, c8 = (idx & 7) * 8;
        uint32_t da = (uint32_t)__cvta_generic_to_shared(as + r * RS + c8);
        const __half* pa = A + (size_t)(bm + r) * lda + kt + c8;
        asm volatile("cp.async.cg.shared.global [%0], [%1], 16;" :: "r"(da), "l"(pa));
    }
#pragma unroll
    for (int i = 0; i < 4; i++) {          // B: 128x64 halves
        int idx = i * 256 + tid;
        int r = idx >> 3, c8 = (idx & 7) * 8;
        int n = bn + r;
        uint32_t db = (uint32_t)__cvta_generic_to_shared(bs + r * RS + c8);
        const __half* pb = B + (size_t)(n < N ? n : 0) * ldb + kt + c8;
        int sz = (n < N) ? 16 : 0;
        asm volatile("cp.async.cg.shared.global [%0], [%1], 16, %2;" :: "r"(db), "l"(pb), "r"(sz));
    }
    asm volatile("cp.async.commit_group;");
}

__device__ __forceinline__ void gemm_core(
    const __half* __restrict__ A, int lda,
    const __half* __restrict__ Bm, int ldb,
    const float* __restrict__ bias,
    float* __restrict__ Cf, __half* __restrict__ Ch,
    int ldc, int partStride, int N, int kChunk,
    int bm, int by, int z)
{
    extern __shared__ __half sm[];
    __half* Asm = sm;
    __half* Bsm = sm + STG * BM * RS;

    const int tid = threadIdx.x;
    const int warp = tid >> 5, lane = tid & 31;
    const int wm = warp >> 2, wn = warp & 3;   // 2 x 4 warps, 32x32 each
    const int bn = by * BN;
    const int k0 = z * kChunk;
    const int nk = kChunk / BK;

    float acc[2][4][4];
#pragma unroll
    for (int i = 0; i < 2; i++)
#pragma unroll
        for (int j = 0; j < 4; j++)
#pragma unroll
            for (int q = 0; q < 4; q++) acc[i][j][q] = 0.f;

    // ldmatrix lane address components (constant across tiles)
    const int a_row_l = (lane & 7) + ((lane >> 3) & 1) * 8;  // + wm*32 + mt*16
    const int a_col_l = ((lane >> 4) & 1) * 8;               // + ks*16
    const int b_row_l = (lane & 7) + ((lane >> 4) & 1) * 8;  // + wn*32 + ntp*16
    const int b_col_l = ((lane >> 3) & 1) * 8;               // + ks*16

#pragma unroll
    for (int s = 0; s < STG - 1; s++) {
        if (s < nk) issue_tile(A, lda, Bm, ldb, bm, bn, N, k0 + s * BK,
                               Asm + s * BM * RS, Bsm + s * BN * RS, tid);
        else asm volatile("cp.async.commit_group;");
    }

    for (int i = 0; i < nk; i++) {
        asm volatile("cp.async.wait_group %0;" :: "n"(STG - 2));
        __syncthreads();

        int ntile = i + STG - 1;
        if (ntile < nk) {
            int slot = ntile % STG;
            issue_tile(A, lda, Bm, ldb, bm, bn, N, k0 + ntile * BK,
                       Asm + slot * BM * RS, Bsm + slot * BN * RS, tid);
        } else {
            asm volatile("cp.async.commit_group;");
        }

        const __half* at = Asm + (i % STG) * BM * RS;
        const __half* bt = Bsm + (i % STG) * BN * RS;

#pragma unroll
        for (int ks = 0; ks < 4; ks++) {
            uint32_t a[2][4], b[4][2];
#pragma unroll
            for (int mt = 0; mt < 2; mt++) {
                int row = wm * 32 + mt * 16 + a_row_l;
                int col = ks * 16 + a_col_l;
                uint32_t ad = (uint32_t)__cvta_generic_to_shared(at + row * RS + col);
                asm volatile("ldmatrix.sync.aligned.m8n8.x4.shared.b16 {%0,%1,%2,%3}, [%4];"
                             : "=r"(a[mt][0]), "=r"(a[mt][1]), "=r"(a[mt][2]), "=r"(a[mt][3])
                             : "r"(ad));
            }
#pragma unroll
            for (int ntp = 0; ntp < 2; ntp++) {
                int row = wn * 32 + ntp * 16 + b_row_l;
                int col = ks * 16 + b_col_l;
                uint32_t bd = (uint32_t)__cvta_generic_to_shared(bt + row * RS + col);
                asm volatile("ldmatrix.sync.aligned.m8n8.x4.shared.b16 {%0,%1,%2,%3}, [%4];"
                             : "=r"(b[2 * ntp][0]), "=r"(b[2 * ntp][1]),
                               "=r"(b[2 * ntp + 1][0]), "=r"(b[2 * ntp + 1][1])
                             : "r"(bd));
            }
#pragma unroll
            for (int mt = 0; mt < 2; mt++)
#pragma unroll
                for (int nt = 0; nt < 4; nt++)
                    asm volatile(
                        "mma.sync.aligned.m16n8k16.row.col.f32.f16.f16.f32 "
                        "{%0,%1,%2,%3}, {%4,%5,%6,%7}, {%8,%9}, {%0,%1,%2,%3};"
                        : "+f"(acc[mt][nt][0]), "+f"(acc[mt][nt][1]),
                          "+f"(acc[mt][nt][2]), "+f"(acc[mt][nt][3])
                        : "r"(a[mt][0]), "r"(a[mt][1]), "r"(a[mt][2]), "r"(a[mt][3]),
                          "r"(b[nt][0]), "r"(b[nt][1]));
        }
    }

    float* Cz = Cf + (size_t)z * partStride;
#pragma unroll
    for (int mt = 0; mt < 2; mt++) {
        int r0 = bm + wm * 32 + mt * 16 + (lane >> 2);
#pragma unroll
        for (int nt = 0; nt < 4; nt++) {
            int cg = bn + wn * 32 + nt * 8 + (lane & 3) * 2;
            float bv0 = 0.f, bv1 = 0.f;
            if (bias) {
                if (cg < N) bv0 = bias[cg];
                if (cg + 1 < N) bv1 = bias[cg + 1];
            }
            float v00 = acc[mt][nt][0] + bv0, v01 = acc[mt][nt][1] + bv1;
            float v10 = acc[mt][nt][2] + bv0, v11 = acc[mt][nt][3] + bv1;
            if (Ch) {
                if (cg < N) {
                    Ch[(size_t)r0 * ldc + cg]       = __float2half(v00);
                    Ch[(size_t)(r0 + 8) * ldc + cg] = __float2half(v10);
                }
                if (cg + 1 < N) {
                    Ch[(size_t)r0 * ldc + cg + 1]       = __float2half(v01);
                    Ch[(size_t)(r0 + 8) * ldc + cg + 1] = __float2half(v11);
                }
            } else {
                if (cg < N) {
                    Cz[(size_t)r0 * ldc + cg]       = v00;
                    Cz[(size_t)(r0 + 8) * ldc + cg] = v10;
                }
                if (cg + 1 < N) {
                    Cz[(size_t)r0 * ldc + cg + 1]       = v01;
                    Cz[(size_t)(r0 + 8) * ldc + cg + 1] = v11;
                }
            }
        }
    }
}

__global__ void __launch_bounds__(256)
hgemm(const __half* __restrict__ A, int lda,
      const __half* __restrict__ Bm, int ldb,
      const float* __restrict__ bias,
      float* __restrict__ Cf, __half* __restrict__ Ch,
      int ldc, int partStride, int N, int kChunk)
{
    gemm_core(A, lda, Bm, ldb, bias, Cf, Ch, ldc, partStride, N, kChunk,
              blockIdx.x * BM, blockIdx.y, blockIdx.z);
}

// combo: logits(t) [79 blocks] + att2(t+1) split-K8 [32 blocks]
__global__ void __launch_bounds__(256)
combo_kernel(const __half* __restrict__ h,
             const float* __restrict__ b_out,
             float* __restrict__ outT)
{
    int bi = blockIdx.x;
    if (bi < NLOGIT) {
        gemm_core(h, H_, g_Wout, H_, b_out, outT, nullptr,
                  (T_ - 1) * V_, 0, V_, H_, 0, bi, 0);
    } else {
        int i = bi - NLOGIT;
        gemm_core(h, H_, g_Wdatt, H_, nullptr, g_att2p, nullptr,
                  A_, B_ * A_, A_, H_ / 8, 0, i & 3, i >> 2);
    }
}

// ---------------- attention + gin assembly (one block per batch b) ---------
__global__ void __launch_bounds__(256)
attn_kernel(const int* __restrict__ captions,
            const float* __restrict__ embed,
            const float* __restrict__ b_datt,
            const float* __restrict__ W_fatt,
            const float* __restrict__ b_fatt,
            const __half* __restrict__ hprev,
            int t)
{
    int b = blockIdx.x;
    int tid = threadIdx.x;
    int warp = tid >> 5, lane = tid & 31;

    __shared__ float att2s[A_];
    __shared__ float es[P_];

    for (int a = tid; a < A_; a += 256) {
        float s = b_datt[a];
#pragma unroll
        for (int zz = 0; zz < 8; zz++) s += g_att2p[zz * B_ * A_ + b * A_ + a];
        att2s[a] = s;
    }
    __syncthreads();

    const float* att1b = g_att1 + (size_t)b * P_ * A_;
    for (int p = warp; p < P_; p += 8) {
        float s = 0.f;
        for (int a = lane; a < A_; a += 32) {
            float v = att1b[p * A_ + a] + att2s[a];
            s += fmaxf(v, 0.f) * W_fatt[a];
        }
#pragma unroll
        for (int o = 16; o; o >>= 1) s += __shfl_xor_sync(0xffffffffu, s, o);
        if (lane == 0) es[p] = s + b_fatt[0];
    }
    __syncthreads();

    if (warp == 0) {
        float v0 = (lane < P_) ? es[lane] : -1e30f;
        float v1 = (lane + 32 < P_) ? es[lane + 32] : -1e30f;
        float m = fmaxf(v0, v1);
#pragma unroll
        for (int o = 16; o; o >>= 1) m = fmaxf(m, __shfl_xor_sync(0xffffffffu, m, o));
        float e0 = (lane < P_) ? __expf(v0 - m) : 0.f;
        float e1 = (lane + 32 < P_) ? __expf(v1 - m) : 0.f;
        float s = e0 + e1;
#pragma unroll
        for (int o = 16; o; o >>= 1) s += __shfl_xor_sync(0xffffffffu, s, o);
        float inv = 1.0f / s;
        if (lane < P_) es[lane] = e0 * inv;
        if (lane + 32 < P_) es[lane + 32] = e1 * inv;
    }
    __syncthreads();

    __half* gin = g_gin + (size_t)b * GK_;
    int cap = captions[b * T_ + t];
    const float* erow = embed + (size_t)cap * E_;
    for (int i = tid; i < E_; i += 256) gin[i] = __float2half(erow[i]);

    const __half* encb = g_ench + (size_t)b * P_ * ENC_;
    for (int e = tid; e < ENC_; e += 256) {
        float s = 0.f;
#pragma unroll 7
        for (int p = 0; p < P_; p++) s += es[p] * __half2float(encb[p * ENC_ + e]);
        gin[E_ + e] = __float2half(s);
    }
    for (int j = tid; j < H_; j += 256) gin[K1_ + j] = hprev[b * H_ + j];
}

// ---------------- LSTM pointwise (reduces 4 gates partials) ----------------
__global__ void __launch_bounds__(256)
lstm_kernel(const float* __restrict__ b_ih, const float* __restrict__ b_hh,
            const float* __restrict__ cprev,
            __half* __restrict__ hnew, float* __restrict__ cnew)
{
    int i = blockIdx.x * blockDim.x + threadIdx.x;
    if (i >= B_ * H_) return;
    int b = i >> 10, j = i & (H_ - 1);
    size_t base = (size_t)b * 4 * H_ + j;
    float gi = 0.f, gf = 0.f, gg = 0.f, go = 0.f;
#pragma unroll
    for (int zz = 0; zz < 4; zz++) {
        const float* gp = g_gatesp + (size_t)zz * B_ * 4 * H_ + base;
        gi += gp[0]; gf += gp[H_]; gg += gp[2 * H_]; go += gp[3 * H_];
    }
    gi += b_ih[j]          + b_hh[j];
    gf += b_ih[H_ + j]     + b_hh[H_ + j];
    gg += b_ih[2 * H_ + j] + b_hh[2 * H_ + j];
    go += b_ih[3 * H_ + j] + b_hh[3 * H_ + j];
    float si = 1.f / (1.f + __expf(-gi));
    float sf = 1.f / (1.f + __expf(-gf));
    float so = 1.f / (1.f + __expf(-go));
    float tg = tanhf(gg);
    float c  = sf * cprev[i] + si * tg;
    cnew[i] = c;
    hnew[i] = __float2half(so * tanhf(c));
}

// ---------------- host ----------------
template <typename T>
static T* sym_addr(const void* sym) {
    void* p = nullptr;
    cudaGetSymbolAddress(&p, sym);
    return (T*)p;
}

extern "C" void kernel_launch(void* const* d_in, const int* in_sizes, int n_in,
                              void* d_out, int out_size)
{
    const float* enc    = (const float*)d_in[0];
    const int*   caps   = (const int*)  d_in[1];
    const float* embed  = (const float*)d_in[2];
    const float* W_eatt = (const float*)d_in[3];
    const float* b_eatt = (const float*)d_in[4];
    const float* W_datt = (const float*)d_in[5];
    const float* b_datt = (const float*)d_in[6];
    const float* W_fatt = (const float*)d_in[7];
    const float* b_fatt = (const float*)d_in[8];
    const float* W_ih   = (const float*)d_in[9];
    const float* b_ih   = (const float*)d_in[10];
    const float* W_hh   = (const float*)d_in[11];
    const float* b_hh   = (const float*)d_in[12];
    const float* W_h0   = (const float*)d_in[13];
    const float* b_h0   = (const float*)d_in[14];
    const float* W_c0   = (const float*)d_in[15];
    const float* b_c0   = (const float*)d_in[16];
    const float* W_out  = (const float*)d_in[17];
    const float* b_out  = (const float*)d_in[18];
    float* out = (float*)d_out;

    cudaFuncSetAttribute(hgemm, cudaFuncAttributeMaxDynamicSharedMemorySize, SMEM_BYTES);
    cudaFuncSetAttribute(combo_kernel, cudaFuncAttributeMaxDynamicSharedMemorySize, SMEM_BYTES);

    __half* Wdth  = sym_addr<__half>(g_Wdatt);
    __half* Weth  = sym_addr<__half>(g_Weatt);
    __half* Wh0h  = sym_addr<__half>(g_Wh0);
    __half* Wc0h  = sym_addr<__half>(g_Wc0);
    __half* ench  = sym_addr<__half>(g_ench);
    __half* meanh = sym_addr<__half>(g_meanh);
    __half* hbuf  = sym_addr<__half>(g_hbuf);
    __half* gin   = sym_addr<__half>(g_gin);
    __half* Wgh   = sym_addr<__half>(g_Wg);
    float*  cbuf  = sym_addr<float>(g_cbuf);
    float*  att1  = sym_addr<float>(g_att1);
    float*  att2p = sym_addr<float>(g_att2p);
    float*  gatesp= sym_addr<float>(g_gatesp);

    const int BH = B_ * H_;

    // ---- one-time setup ----
    mean_kernel<<<(B_ * ENC_ + 255) / 256, 256>>>(enc);
    cvt_all<<<(S7 + 255) / 256, 256>>>(W_datt, W_out, W_eatt, W_h0, W_c0, enc, W_ih, W_hh);
    hgemm<<<dim3(1, H_ / BN, 1), 256, SMEM_BYTES>>>(meanh, ENC_, Wh0h, ENC_, b_h0,
                                                    nullptr, hbuf, H_, 0, H_, ENC_);
    hgemm<<<dim3(1, H_ / BN, 1), 256, SMEM_BYTES>>>(meanh, ENC_, Wc0h, ENC_, b_c0,
                                                    cbuf, nullptr, H_, 0, H_, ENC_);
    hgemm<<<dim3((B_ * P_) / BM, A_ / BN, 1), 256, SMEM_BYTES>>>(ench, ENC_, Weth, ENC_, b_eatt,
                                                                 att1, nullptr, A_, 0, A_, ENC_);
    // att2 for t=0 (split-K 8, kChunk=128 -> nk=2)
    hgemm<<<dim3(1, A_ / BN, 8), 256, SMEM_BYTES>>>(hbuf, H_, Wdth, H_, nullptr,
                                                    att2p, nullptr, A_, B_ * A_, A_, H_ / 8);

    for (int t = 0; t < T_ - 1; t++) {
        __half* h_cur = hbuf + (t & 1) * BH;
        float*  c_cur = cbuf + (t & 1) * BH;
        __half* h_nxt = hbuf + ((t + 1) & 1) * BH;
        float*  c_nxt = cbuf + ((t + 1) & 1) * BH;

        // attention + gin (consumes att2p from previous combo)
        attn_kernel<<<B_, 256>>>(caps, embed, b_datt, W_fatt, b_fatt, h_cur, t);

        // gates partials: gin @ Wg^T, split-K 4 (grid 128, kChunk=704 -> nk=11)
        hgemm<<<dim3(1, (4 * H_) / BN, 4), 256, SMEM_BYTES>>>(gin, GK_, Wgh, GK_, nullptr,
                                                              gatesp, nullptr, 4 * H_,
                                                              B_ * 4 * H_, 4 * H_, GK_ / 4);

        // LSTM pointwise
        lstm_kernel<<<(B_ * H_ + 255) / 256, 256>>>(b_ih, b_hh, c_cur, h_nxt, c_nxt);

        // logits(t) + att2(t+1) fused (111 blocks)
        combo_kernel<<<NLOGIT + 32, 256, SMEM_BYTES>>>(h_nxt, b_out, out + (size_t)t * V_);
    }
}

// round 6
// speedup vs baseline: 1.3473x; 1.0853x over previous
#include <cuda_runtime.h>
#include <cuda_fp16.h>
#include <cstdint>

#define B_    64
#define P_    49
#define ENC_  1280
#define T_    25
#define V_    10000
#define E_    512
#define H_    1024
#define A_    512
#define GK_   2816   /* E + ENC + H */
#define GKP_  3072   /* padded to make split-K 8 divide evenly */
#define K1_   1792   /* E + ENC */

#define BM 64
#define BN 128
#define BK 64
#define STG 4
#define RS 72        /* smem row stride in halves (64 + 8 pad) */
#define SMEM_BYTES (STG * (BM + BN) * RS * 2)

#define NLOGIT ((V_ + BN - 1) / BN)   /* 79 */

// ---------------- static scratch (no allocs) ----------------
__device__ __align__(16) __half g_Wout [V_ * H_];
__device__ __align__(16) __half g_Wg   [4 * H_ * GKP_];
__device__ __align__(16) __half g_Wdatt[A_ * H_];
__device__ __align__(16) __half g_Weatt[A_ * ENC_];
__device__ __align__(16) __half g_Wh0  [H_ * ENC_];
__device__ __align__(16) __half g_Wc0  [H_ * ENC_];
__device__ __align__(16) __half g_ench [B_ * P_ * ENC_];
__device__ __align__(16) __half g_meanh[B_ * ENC_];
__device__ __align__(16) __half g_hall [T_ * B_ * H_];     /* h_0 .. h_24 */
__device__ __align__(16) __half g_gin  [B_ * GKP_];
__device__ __align__(16) float  g_cbuf [2 * B_ * H_];
__device__ __align__(16) float  g_att1 [B_ * P_ * A_];
__device__ __align__(16) float  g_att2p[8 * B_ * A_];
__device__ __align__(16) float  g_gatesp[8 * B_ * 4 * H_];

// ---------------- setup: convert to fp16 ----------------
#define S0 (A_ * H_)
#define S1 (S0 + V_ * H_)
#define S2 (S1 + A_ * ENC_)
#define S3 (S2 + H_ * ENC_)
#define S4 (S3 + H_ * ENC_)
#define S5 (S4 + B_ * P_ * ENC_)
#define S6 (S5 + 4 * H_ * K1_)
#define S7 (S6 + 4 * H_ * H_)
#define S8 (S7 + 4 * H_ * (GKP_ - GK_))   /* zero pad of Wg */

__global__ void cvt_all(const float* __restrict__ Wd, const float* __restrict__ Wo,
                        const float* __restrict__ We, const float* __restrict__ Wh0,
                        const float* __restrict__ Wc0, const float* __restrict__ enc,
                        const float* __restrict__ Wih, const float* __restrict__ Whh)
{
    int i = blockIdx.x * 256 + threadIdx.x;
    if (i >= S8) return;
    if (i < S0)      g_Wdatt[i]      = __float2half(Wd[i]);
    else if (i < S1) g_Wout[i - S0]  = __float2half(Wo[i - S0]);
    else if (i < S2) g_Weatt[i - S1] = __float2half(We[i - S1]);
    else if (i < S3) g_Wh0[i - S2]   = __float2half(Wh0[i - S2]);
    else if (i < S4) g_Wc0[i - S3]   = __float2half(Wc0[i - S3]);
    else if (i < S5) g_ench[i - S4]  = __float2half(enc[i - S4]);
    else if (i < S6) {
        int j = i - S5; int r = j / K1_, c = j % K1_;
        g_Wg[(size_t)r * GKP_ + c] = __float2half(Wih[j]);
    } else if (i < S7) {
        int j = i - S6; int r = j / H_, c = j % H_;
        g_Wg[(size_t)r * GKP_ + K1_ + c] = __float2half(Whh[j]);
    } else {
        int j = i - S7; int r = j / (GKP_ - GK_), c = j % (GKP_ - GK_);
        g_Wg[(size_t)r * GKP_ + GK_ + c] = __half(0.f);
    }
}

__global__ void mean_kernel(const float* __restrict__ enc) {
    int i = blockIdx.x * blockDim.x + threadIdx.x;
    if (i >= B_ * ENC_) return;
    int b = i / ENC_, e = i % ENC_;
    const float* p = enc + (size_t)b * P_ * ENC_ + e;
    float s = 0.f;
#pragma unroll 7
    for (int k = 0; k < P_; k++) s += p[k * ENC_];
    g_meanh[i] = __float2half(s * (1.0f / P_));
}

// ---------------- fp16 GEMM core (256 thr, 64x128 tile, ldmatrix) ----------
__device__ __forceinline__ void issue_tile(
    const __half* __restrict__ A, int lda,
    const __half* __restrict__ B, int ldb,
    int bm, int bn, int N, int kt,
    __half* as, __half* bs, int tid)
{
#pragma unroll
    for (int i = 0; i < 2; i++) {          // A: 64x64 halves
        int idx = i * 256 + tid;
        int r = idx >> 3, c8 = (idx & 7) * 8;
        uint32_t da = (uint32_t)__cvta_generic_to_shared(as + r * RS + c8);
        const __half* pa = A + (size_t)(bm + r) * lda + kt + c8;
        asm volatile("cp.async.cg.shared.global [%0], [%1], 16;" :: "r"(da), "l"(pa));
    }
#pragma unroll
    for (int i = 0; i < 4; i++) {          // B: 128x64 halves
        int idx = i * 256 + tid;
        int r = idx >> 3, c8 = (idx & 7) * 8;
        int n = bn + r;
        uint32_t db = (uint32_t)__cvta_generic_to_shared(bs + r * RS + c8);
        const __half* pb = B + (size_t)(n < N ? n : 0) * ldb + kt + c8;
        int sz = (n < N) ? 16 : 0;
        asm volatile("cp.async.cg.shared.global [%0], [%1], 16, %2;" :: "r"(db), "l"(pb), "r"(sz));
    }
    asm volatile("cp.async.commit_group;");
}

// capmap: if true, output row r (= t*64+b) maps to Cf[b][t][col] with shape [B,T-1,V]
__device__ __forceinline__ void gemm_core(
    const __half* __restrict__ A, int lda,
    const __half* __restrict__ Bm, int ldb,
    const float* __restrict__ bias,
    float* __restrict__ Cf, __half* __restrict__ Ch,
    int ldc, int partStride, int N, int kChunk,
    int bm, int by, int z, bool capmap)
{
    extern __shared__ __half sm[];
    __half* Asm = sm;
    __half* Bsm = sm + STG * BM * RS;

    const int tid = threadIdx.x;
    const int warp = tid >> 5, lane = tid & 31;
    const int wm = warp >> 2, wn = warp & 3;   // 2 x 4 warps, 32x32 each
    const int bn = by * BN;
    const int k0 = z * kChunk;
    const int nk = kChunk / BK;

    float acc[2][4][4];
#pragma unroll
    for (int i = 0; i < 2; i++)
#pragma unroll
        for (int j = 0; j < 4; j++)
#pragma unroll
            for (int q = 0; q < 4; q++) acc[i][j][q] = 0.f;

    const int a_row_l = (lane & 7) + ((lane >> 3) & 1) * 8;
    const int a_col_l = ((lane >> 4) & 1) * 8;
    const int b_row_l = (lane & 7) + ((lane >> 4) & 1) * 8;
    const int b_col_l = ((lane >> 3) & 1) * 8;

#pragma unroll
    for (int s = 0; s < STG - 1; s++) {
        if (s < nk) issue_tile(A, lda, Bm, ldb, bm, bn, N, k0 + s * BK,
                               Asm + s * BM * RS, Bsm + s * BN * RS, tid);
        else asm volatile("cp.async.commit_group;");
    }

    for (int i = 0; i < nk; i++) {
        asm volatile("cp.async.wait_group %0;" :: "n"(STG - 2));
        __syncthreads();

        int ntile = i + STG - 1;
        if (ntile < nk) {
            int slot = ntile % STG;
            issue_tile(A, lda, Bm, ldb, bm, bn, N, k0 + ntile * BK,
                       Asm + slot * BM * RS, Bsm + slot * BN * RS, tid);
        } else {
            asm volatile("cp.async.commit_group;");
        }

        const __half* at = Asm + (i % STG) * BM * RS;
        const __half* bt = Bsm + (i % STG) * BN * RS;

#pragma unroll
        for (int ks = 0; ks < 4; ks++) {
            uint32_t a[2][4], b[4][2];
#pragma unroll
            for (int mt = 0; mt < 2; mt++) {
                int row = wm * 32 + mt * 16 + a_row_l;
                int col = ks * 16 + a_col_l;
                uint32_t ad = (uint32_t)__cvta_generic_to_shared(at + row * RS + col);
                asm volatile("ldmatrix.sync.aligned.m8n8.x4.shared.b16 {%0,%1,%2,%3}, [%4];"
                             : "=r"(a[mt][0]), "=r"(a[mt][1]), "=r"(a[mt][2]), "=r"(a[mt][3])
                             : "r"(ad));
            }
#pragma unroll
            for (int ntp = 0; ntp < 2; ntp++) {
                int row = wn * 32 + ntp * 16 + b_row_l;
                int col = ks * 16 + b_col_l;
                uint32_t bd = (uint32_t)__cvta_generic_to_shared(bt + row * RS + col);
                asm volatile("ldmatrix.sync.aligned.m8n8.x4.shared.b16 {%0,%1,%2,%3}, [%4];"
                             : "=r"(b[2 * ntp][0]), "=r"(b[2 * ntp][1]),
                               "=r"(b[2 * ntp + 1][0]), "=r"(b[2 * ntp + 1][1])
                             : "r"(bd));
            }
#pragma unroll
            for (int mt = 0; mt < 2; mt++)
#pragma unroll
                for (int nt = 0; nt < 4; nt++)
                    asm volatile(
                        "mma.sync.aligned.m16n8k16.row.col.f32.f16.f16.f32 "
                        "{%0,%1,%2,%3}, {%4,%5,%6,%7}, {%8,%9}, {%0,%1,%2,%3};"
                        : "+f"(acc[mt][nt][0]), "+f"(acc[mt][nt][1]),
                          "+f"(acc[mt][nt][2]), "+f"(acc[mt][nt][3])
                        : "r"(a[mt][0]), "r"(a[mt][1]), "r"(a[mt][2]), "r"(a[mt][3]),
                          "r"(b[nt][0]), "r"(b[nt][1]));
        }
    }

    float* Cz = Cf + (size_t)z * partStride;
#pragma unroll
    for (int mt = 0; mt < 2; mt++) {
        int r0 = bm + wm * 32 + mt * 16 + (lane >> 2);
        int r1 = r0 + 8;
#pragma unroll
        for (int nt = 0; nt < 4; nt++) {
            int cg = bn + wn * 32 + nt * 8 + (lane & 3) * 2;
            float bv0 = 0.f, bv1 = 0.f;
            if (bias) {
                if (cg < N) bv0 = bias[cg];
                if (cg + 1 < N) bv1 = bias[cg + 1];
            }
            float v00 = acc[mt][nt][0] + bv0, v01 = acc[mt][nt][1] + bv1;
            float v10 = acc[mt][nt][2] + bv0, v11 = acc[mt][nt][3] + bv1;
            if (capmap) {
                float* p0 = Cf + (size_t)(r0 & 63) * ((T_ - 1) * V_) + (size_t)(r0 >> 6) * V_;
                float* p1 = Cf + (size_t)(r1 & 63) * ((T_ - 1) * V_) + (size_t)(r1 >> 6) * V_;
                if (cg < N) { p0[cg] = v00; p1[cg] = v10; }
                if (cg + 1 < N) { p0[cg + 1] = v01; p1[cg + 1] = v11; }
            } else if (Ch) {
                if (cg < N) {
                    Ch[(size_t)r0 * ldc + cg] = __float2half(v00);
                    Ch[(size_t)r1 * ldc + cg] = __float2half(v10);
                }
                if (cg + 1 < N) {
                    Ch[(size_t)r0 * ldc + cg + 1] = __float2half(v01);
                    Ch[(size_t)r1 * ldc + cg + 1] = __float2half(v11);
                }
            } else {
                if (cg < N) {
                    Cz[(size_t)r0 * ldc + cg] = v00;
                    Cz[(size_t)r1 * ldc + cg] = v10;
                }
                if (cg + 1 < N) {
                    Cz[(size_t)r0 * ldc + cg + 1] = v01;
                    Cz[(size_t)r1 * ldc + cg + 1] = v11;
                }
            }
        }
    }
}

__global__ void __launch_bounds__(256)
hgemm(const __half* __restrict__ A, int lda,
      const __half* __restrict__ Bm, int ldb,
      const float* __restrict__ bias,
      float* __restrict__ Cf, __half* __restrict__ Ch,
      int ldc, int partStride, int N, int kChunk)
{
    gemm_core(A, lda, Bm, ldb, bias, Cf, Ch, ldc, partStride, N, kChunk,
              blockIdx.x * BM, blockIdx.y, blockIdx.z, false);
}

// batched logits: A = g_hall rows 64..1600 (h_1..h_24), M=1536, N=10000, K=1024
__global__ void __launch_bounds__(256)
logits_kernel(const float* __restrict__ b_out, float* __restrict__ out)
{
    gemm_core(g_hall + B_ * H_, H_, g_Wout, H_, b_out, out, nullptr,
              0, 0, V_, H_, blockIdx.x * BM, blockIdx.y, 0, true);
}

// ---------------- attention + gin assembly (one block per batch b) ---------
__global__ void __launch_bounds__(256)
attn_kernel(const int* __restrict__ captions,
            const float* __restrict__ embed,
            const float* __restrict__ b_datt,
            const float* __restrict__ W_fatt,
            const float* __restrict__ b_fatt,
            const __half* __restrict__ hprev,
            int t)
{
    int b = blockIdx.x;
    int tid = threadIdx.x;
    int warp = tid >> 5, lane = tid & 31;

    __shared__ float att2s[A_];
    __shared__ float es[P_];

    for (int a = tid; a < A_; a += 256) {
        float s = b_datt[a];
#pragma unroll
        for (int zz = 0; zz < 8; zz++) s += g_att2p[zz * B_ * A_ + b * A_ + a];
        att2s[a] = s;
    }
    __syncthreads();

    const float* att1b = g_att1 + (size_t)b * P_ * A_;
    for (int p = warp; p < P_; p += 8) {
        float s = 0.f;
        for (int a = lane; a < A_; a += 32) {
            float v = att1b[p * A_ + a] + att2s[a];
            s += fmaxf(v, 0.f) * W_fatt[a];
        }
#pragma unroll
        for (int o = 16; o; o >>= 1) s += __shfl_xor_sync(0xffffffffu, s, o);
        if (lane == 0) es[p] = s + b_fatt[0];
    }
    __syncthreads();

    if (warp == 0) {
        float v0 = (lane < P_) ? es[lane] : -1e30f;
        float v1 = (lane + 32 < P_) ? es[lane + 32] : -1e30f;
        float m = fmaxf(v0, v1);
#pragma unroll
        for (int o = 16; o; o >>= 1) m = fmaxf(m, __shfl_xor_sync(0xffffffffu, m, o));
        float e0 = (lane < P_) ? __expf(v0 - m) : 0.f;
        float e1 = (lane + 32 < P_) ? __expf(v1 - m) : 0.f;
        float s = e0 + e1;
#pragma unroll
        for (int o = 16; o; o >>= 1) s += __shfl_xor_sync(0xffffffffu, s, o);
        float inv = 1.0f / s;
        if (lane < P_) es[lane] = e0 * inv;
        if (lane + 32 < P_) es[lane + 32] = e1 * inv;
    }
    __syncthreads();

    __half* gin = g_gin + (size_t)b * GKP_;
    int cap = captions[b * T_ + t];
    const float* erow = embed + (size_t)cap * E_;
    for (int i = tid; i < E_; i += 256) gin[i] = __float2half(erow[i]);

    const __half* encb = g_ench + (size_t)b * P_ * ENC_;
    for (int e = tid; e < ENC_; e += 256) {
        float s = 0.f;
#pragma unroll 7
        for (int p = 0; p < P_; p++) s += es[p] * __half2float(encb[p * ENC_ + e]);
        gin[E_ + e] = __float2half(s);
    }
    for (int j = tid; j < H_; j += 256) gin[K1_ + j] = hprev[b * H_ + j];
    for (int j = tid; j < GKP_ - GK_; j += 256) gin[GK_ + j] = __half(0.f);
}

// ---------------- LSTM pointwise (reduces 8 gates partials) ----------------
__global__ void __launch_bounds__(256)
lstm_kernel(const float* __restrict__ b_ih, const float* __restrict__ b_hh,
            const float* __restrict__ cprev,
            __half* __restrict__ hnew, float* __restrict__ cnew)
{
    int i = blockIdx.x * blockDim.x + threadIdx.x;
    if (i >= B_ * H_) return;
    int b = i >> 10, j = i & (H_ - 1);
    size_t base = (size_t)b * 4 * H_ + j;
    float gi = 0.f, gf = 0.f, gg = 0.f, go = 0.f;
#pragma unroll
    for (int zz = 0; zz < 8; zz++) {
        const float* gp = g_gatesp + (size_t)zz * B_ * 4 * H_ + base;
        gi += gp[0]; gf += gp[H_]; gg += gp[2 * H_]; go += gp[3 * H_];
    }
    gi += b_ih[j]          + b_hh[j];
    gf += b_ih[H_ + j]     + b_hh[H_ + j];
    gg += b_ih[2 * H_ + j] + b_hh[2 * H_ + j];
    go += b_ih[3 * H_ + j] + b_hh[3 * H_ + j];
    float si = 1.f / (1.f + __expf(-gi));
    float sf = 1.f / (1.f + __expf(-gf));
    float so = 1.f / (1.f + __expf(-go));
    float tg = tanhf(gg);
    float c  = sf * cprev[i] + si * tg;
    cnew[i] = c;
    hnew[i] = __float2half(so * tanhf(c));
}

// ---------------- host ----------------
template <typename T>
static T* sym_addr(const void* sym) {
    void* p = nullptr;
    cudaGetSymbolAddress(&p, sym);
    return (T*)p;
}

extern "C" void kernel_launch(void* const* d_in, const int* in_sizes, int n_in,
                              void* d_out, int out_size)
{
    const float* enc    = (const float*)d_in[0];
    const int*   caps   = (const int*)  d_in[1];
    const float* embed  = (const float*)d_in[2];
    const float* W_eatt = (const float*)d_in[3];
    const float* b_eatt = (const float*)d_in[4];
    const float* W_datt = (const float*)d_in[5];
    const float* b_datt = (const float*)d_in[6];
    const float* W_fatt = (const float*)d_in[7];
    const float* b_fatt = (const float*)d_in[8];
    const float* W_ih   = (const float*)d_in[9];
    const float* b_ih   = (const float*)d_in[10];
    const float* W_hh   = (const float*)d_in[11];
    const float* b_hh   = (const float*)d_in[12];
    const float* W_h0   = (const float*)d_in[13];
    const float* b_h0   = (const float*)d_in[14];
    const float* W_c0   = (const float*)d_in[15];
    const float* b_c0   = (const float*)d_in[16];
    const float* W_out  = (const float*)d_in[17];
    const float* b_out  = (const float*)d_in[18];
    float* out = (float*)d_out;

    cudaFuncSetAttribute(hgemm, cudaFuncAttributeMaxDynamicSharedMemorySize, SMEM_BYTES);
    cudaFuncSetAttribute(logits_kernel, cudaFuncAttributeMaxDynamicSharedMemorySize, SMEM_BYTES);

    __half* Wdth  = sym_addr<__half>(g_Wdatt);
    __half* Weth  = sym_addr<__half>(g_Weatt);
    __half* Wh0h  = sym_addr<__half>(g_Wh0);
    __half* Wc0h  = sym_addr<__half>(g_Wc0);
    __half* ench  = sym_addr<__half>(g_ench);
    __half* meanh = sym_addr<__half>(g_meanh);
    __half* hall  = sym_addr<__half>(g_hall);
    __half* gin   = sym_addr<__half>(g_gin);
    __half* Wgh   = sym_addr<__half>(g_Wg);
    float*  cbuf  = sym_addr<float>(g_cbuf);
    float*  att1  = sym_addr<float>(g_att1);
    float*  att2p = sym_addr<float>(g_att2p);
    float*  gatesp= sym_addr<float>(g_gatesp);

    const int BH = B_ * H_;

    // ---- one-time setup ----
    mean_kernel<<<(B_ * ENC_ + 255) / 256, 256>>>(enc);
    cvt_all<<<(S8 + 255) / 256, 256>>>(W_datt, W_out, W_eatt, W_h0, W_c0, enc, W_ih, W_hh);
    // h0 -> g_hall[0] (fp16), c0 -> cbuf[0] (fp32)
    hgemm<<<dim3(1, H_ / BN, 1), 256, SMEM_BYTES>>>(meanh, ENC_, Wh0h, ENC_, b_h0,
                                                    nullptr, hall, H_, 0, H_, ENC_);
    hgemm<<<dim3(1, H_ / BN, 1), 256, SMEM_BYTES>>>(meanh, ENC_, Wc0h, ENC_, b_c0,
                                                    cbuf, nullptr, H_, 0, H_, ENC_);
    // att1
    hgemm<<<dim3((B_ * P_) / BM, A_ / BN, 1), 256, SMEM_BYTES>>>(ench, ENC_, Weth, ENC_, b_eatt,
                                                                 att1, nullptr, A_, 0, A_, ENC_);
    // att2 for t=0 (split-K 8)
    hgemm<<<dim3(1, A_ / BN, 8), 256, SMEM_BYTES>>>(hall, H_, Wdth, H_, nullptr,
                                                    att2p, nullptr, A_, B_ * A_, A_, H_ / 8);

    // ---- recurrent loop (logits deferred) ----
    for (int t = 0; t < T_ - 1; t++) {
        __half* h_cur = hall + (size_t)t * BH;
        __half* h_nxt = hall + (size_t)(t + 1) * BH;
        float*  c_cur = cbuf + (t & 1) * BH;
        float*  c_nxt = cbuf + ((t + 1) & 1) * BH;

        attn_kernel<<<B_, 256>>>(caps, embed, b_datt, W_fatt, b_fatt, h_cur, t);

        // gates partials: gin @ Wg^T, K padded to 3072, split-K 8 (grid 256, nk=6)
        hgemm<<<dim3(1, (4 * H_) / BN, 8), 256, SMEM_BYTES>>>(gin, GKP_, Wgh, GKP_, nullptr,
                                                              gatesp, nullptr, 4 * H_,
                                                              B_ * 4 * H_, 4 * H_, GKP_ / 8);

        lstm_kernel<<<(B_ * H_ + 255) / 256, 256>>>(b_ih, b_hh, c_cur, h_nxt, c_nxt);

        // att2(t+1) split-K 8 (grid 32, nk=2) — not needed after last step
        if (t < T_ - 2)
            hgemm<<<dim3(1, A_ / BN, 8), 256, SMEM_BYTES>>>(h_nxt, H_, Wdth, H_, nullptr,
                                                            att2p, nullptr, A_, B_ * A_, A_, H_ / 8);
    }

    // ---- batched logits: [1536 x 10000] = h_all[1..24] @ W_out^T + b_out ----
    logits_kernel<<<dim3((T_ - 1) * B_ / BM, NLOGIT, 1), 256, SMEM_BYTES>>>(b_out, out);
}

// round 8
// speedup vs baseline: 1.4965x; 1.1107x over previous
#include <cuda_runtime.h>
#include <cuda_fp16.h>
#include <cstdint>

#define B_    64
#define P_    49
#define ENC_  1280
#define T_    25
#define V_    10000
#define E_    512
#define H_    1024
#define A_    512
#define G4_   4096           /* 4*H */
#define NCAT  4608           /* 4*H + A : [W_hh | W_datt] fused */
#define WIH_LD 1792          /* W_ih row stride: E + ENC */

#define BM 64
#define BN 128
#define BK 64
#define STG 4
#define RS 72
#define SMEM_BYTES (STG * (BM + BN) * RS * 2)

#define NLOGIT ((V_ + BN - 1) / BN)   /* 79 */

// ---------------- static scratch ----------------
__device__ __align__(16) __half g_Wout [V_ * H_];
__device__ __align__(16) __half g_Weatt[A_ * ENC_];
__device__ __align__(16) __half g_Wh0c0[2048 * ENC_];     /* [Wh0 ; Wc0] */
__device__ __align__(16) __half g_Wihx [G4_ * E_];
__device__ __align__(16) __half g_Wihc [G4_ * ENC_];
__device__ __align__(16) __half g_Wcat [NCAT * H_];       /* [W_hh ; W_datt] */
__device__ __align__(16) __half g_ench [B_ * P_ * ENC_];
__device__ __align__(16) __half g_meanh[B_ * ENC_];
__device__ __align__(16) __half g_embX [(T_ - 1) * B_ * E_];
__device__ __align__(16) __half g_hall [T_ * B_ * H_];
__device__ __align__(16) __half g_encW [B_ * P_ * G4_];   /* 25.7 MB fp16 */
__device__ __align__(16) __half g_gatesX[(T_ - 1) * B_ * G4_];
__device__ __align__(16) float  g_cbuf [2 * B_ * H_];
__device__ __align__(16) float  g_att1 [B_ * P_ * A_];
__device__ __align__(16) float  g_ghp  [4 * B_ * NCAT];   /* split-K partials */
__device__ __align__(16) float  g_bh0c0[2048];
__device__ __align__(16) float  g_bsum [G4_];             /* b_ih + b_hh */

// ---------------- setup conversions ----------------
#define T0 (V_ * H_)
#define T1 (T0 + A_ * ENC_)
#define T2 (T1 + 2048 * ENC_)
#define T3 (T2 + B_ * P_ * ENC_)
#define T4 (T3 + G4_ * E_)
#define T5 (T4 + G4_ * ENC_)
#define T6 (T5 + NCAT * H_)
#define T7 (T6 + 2048)
#define T8 (T7 + G4_)

__global__ void cvt_all(const float* __restrict__ Wo, const float* __restrict__ We,
                        const float* __restrict__ Wh0, const float* __restrict__ Wc0,
                        const float* __restrict__ enc, const float* __restrict__ Wih,
                        const float* __restrict__ Whh, const float* __restrict__ Wd,
                        const float* __restrict__ bh0, const float* __restrict__ bc0,
                        const float* __restrict__ bih, const float* __restrict__ bhh)
{
    int i = blockIdx.x * 256 + threadIdx.x;
    if (i >= T8) return;
    if (i < T0) { g_Wout[i] = __float2half(Wo[i]); return; }
    if (i < T1) { g_Weatt[i - T0] = __float2half(We[i - T0]); return; }
    if (i < T2) {
        int j = i - T1; int r = j / ENC_, c = j % ENC_;
        g_Wh0c0[j] = __float2half(r < 1024 ? Wh0[r * ENC_ + c] : Wc0[(r - 1024) * ENC_ + c]);
        return;
    }
    if (i < T3) { g_ench[i - T2] = __float2half(enc[i - T2]); return; }
    if (i < T4) {
        int j = i - T3; int r = j / E_, c = j % E_;
        g_Wihx[j] = __float2half(Wih[(size_t)r * WIH_LD + c]);          /* FIXED stride */
        return;
    }
    if (i < T5) {
        int j = i - T4; int r = j / ENC_, c = j % ENC_;
        g_Wihc[j] = __float2half(Wih[(size_t)r * WIH_LD + E_ + c]);     /* FIXED stride */
        return;
    }
    if (i < T6) {
        int j = i - T5; int r = j / H_, c = j % H_;
        g_Wcat[j] = __float2half(r < G4_ ? Whh[(size_t)r * H_ + c] : Wd[(size_t)(r - G4_) * H_ + c]);
        return;
    }
    if (i < T7) {
        int j = i - T6;
        g_bh0c0[j] = (j < 1024) ? bh0[j] : bc0[j - 1024];
        return;
    }
    int j = i - T7;
    g_bsum[j] = bih[j] + bhh[j];
}

__global__ void mean_kernel(const float* __restrict__ enc) {
    int i = blockIdx.x * blockDim.x + threadIdx.x;
    if (i >= B_ * ENC_) return;
    int b = i / ENC_, e = i % ENC_;
    const float* p = enc + (size_t)b * P_ * ENC_ + e;
    float s = 0.f;
#pragma unroll 7
    for (int k = 0; k < P_; k++) s += p[k * ENC_];
    g_meanh[i] = __float2half(s * (1.0f / P_));
}

__global__ void embx_kernel(const int* __restrict__ captions,
                            const float* __restrict__ embed)
{
    int i = blockIdx.x * 256 + threadIdx.x;
    if (i >= (T_ - 1) * B_ * E_) return;
    int r = i / E_, c = i % E_;
    int t = r / B_, b = r % B_;
    int cap = captions[b * T_ + t];
    g_embX[i] = __float2half(embed[(size_t)cap * E_ + c]);
}

// ---------------- fp16 GEMM core (256 thr, 64x128 tile, ldmatrix) ----------
__device__ __forceinline__ void issue_tile(
    const __half* __restrict__ A, int lda,
    const __half* __restrict__ B, int ldb,
    int bm, int bn, int N, int kt,
    __half* as, __half* bs, int tid)
{
#pragma unroll
    for (int i = 0; i < 2; i++) {
        int idx = i * 256 + tid;
        int r = idx >> 3, c8 = (idx & 7) * 8;
        uint32_t da = (uint32_t)__cvta_generic_to_shared(as + r * RS + c8);
        const __half* pa = A + (size_t)(bm + r) * lda + kt + c8;
        asm volatile("cp.async.cg.shared.global [%0], [%1], 16;" :: "r"(da), "l"(pa));
    }
#pragma unroll
    for (int i = 0; i < 4; i++) {
        int idx = i * 256 + tid;
        int r = idx >> 3, c8 = (idx & 7) * 8;
        int n = bn + r;
        uint32_t db = (uint32_t)__cvta_generic_to_shared(bs + r * RS + c8);
        const __half* pb = B + (size_t)(n < N ? n : 0) * ldb + kt + c8;
        int sz = (n < N) ? 16 : 0;
        asm volatile("cp.async.cg.shared.global [%0], [%1], 16, %2;" :: "r"(db), "l"(pb), "r"(sz));
    }
    asm volatile("cp.async.commit_group;");
}

// mode: 0 = fp32 Cf (+bias, split-K via z), 1 = fp16 Ch (+bias)
//       2 = logits capmap (row t*64+b -> out[b][t][:], bias), 3 = h0c0 split
__device__ __forceinline__ void gemm_core(
    const __half* __restrict__ A, int lda,
    const __half* __restrict__ Bm, int ldb,
    const float* __restrict__ bias,
    float* __restrict__ Cf, __half* __restrict__ Ch,
    int ldc, int partStride, int N, int kChunk,
    int bm, int by, int z, int mode)
{
    extern __shared__ __half sm[];
    __half* Asm = sm;
    __half* Bsm = sm + STG * BM * RS;

    const int tid = threadIdx.x;
    const int warp = tid >> 5, lane = tid & 31;
    const int wm = warp >> 2, wn = warp & 3;
    const int bn = by * BN;
    const int k0 = z * kChunk;
    const int nk = kChunk / BK;

    float acc[2][4][4];
#pragma unroll
    for (int i = 0; i < 2; i++)
#pragma unroll
        for (int j = 0; j < 4; j++)
#pragma unroll
            for (int q = 0; q < 4; q++) acc[i][j][q] = 0.f;

    const int a_row_l = (lane & 7) + ((lane >> 3) & 1) * 8;
    const int a_col_l = ((lane >> 4) & 1) * 8;
    const int b_row_l = (lane & 7) + ((lane >> 4) & 1) * 8;
    const int b_col_l = ((lane >> 3) & 1) * 8;

#pragma unroll
    for (int s = 0; s < STG - 1; s++) {
        if (s < nk) issue_tile(A, lda, Bm, ldb, bm, bn, N, k0 + s * BK,
                               Asm + s * BM * RS, Bsm + s * BN * RS, tid);
        else asm volatile("cp.async.commit_group;");
    }

    for (int i = 0; i < nk; i++) {
        asm volatile("cp.async.wait_group %0;" :: "n"(STG - 2));
        __syncthreads();

        int ntile = i + STG - 1;
        if (ntile < nk) {
            int slot = ntile % STG;
            issue_tile(A, lda, Bm, ldb, bm, bn, N, k0 + ntile * BK,
                       Asm + slot * BM * RS, Bsm + slot * BN * RS, tid);
        } else {
            asm volatile("cp.async.commit_group;");
        }

        const __half* at = Asm + (i % STG) * BM * RS;
        const __half* bt = Bsm + (i % STG) * BN * RS;

#pragma unroll
        for (int ks = 0; ks < 4; ks++) {
            uint32_t a[2][4], b[4][2];
#pragma unroll
            for (int mt = 0; mt < 2; mt++) {
                int row = wm * 32 + mt * 16 + a_row_l;
                int col = ks * 16 + a_col_l;
                uint32_t ad = (uint32_t)__cvta_generic_to_shared(at + row * RS + col);
                asm volatile("ldmatrix.sync.aligned.m8n8.x4.shared.b16 {%0,%1,%2,%3}, [%4];"
                             : "=r"(a[mt][0]), "=r"(a[mt][1]), "=r"(a[mt][2]), "=r"(a[mt][3])
                             : "r"(ad));
            }
#pragma unroll
            for (int ntp = 0; ntp < 2; ntp++) {
                int row = wn * 32 + ntp * 16 + b_row_l;
                int col = ks * 16 + b_col_l;
                uint32_t bd = (uint32_t)__cvta_generic_to_shared(bt + row * RS + col);
                asm volatile("ldmatrix.sync.aligned.m8n8.x4.shared.b16 {%0,%1,%2,%3}, [%4];"
                             : "=r"(b[2 * ntp][0]), "=r"(b[2 * ntp][1]),
                               "=r"(b[2 * ntp + 1][0]), "=r"(b[2 * ntp + 1][1])
                             : "r"(bd));
            }
#pragma unroll
            for (int mt = 0; mt < 2; mt++)
#pragma unroll
                for (int nt = 0; nt < 4; nt++)
                    asm volatile(
                        "mma.sync.aligned.m16n8k16.row.col.f32.f16.f16.f32 "
                        "{%0,%1,%2,%3}, {%4,%5,%6,%7}, {%8,%9}, {%0,%1,%2,%3};"
                        : "+f"(acc[mt][nt][0]), "+f"(acc[mt][nt][1]),
                          "+f"(acc[mt][nt][2]), "+f"(acc[mt][nt][3])
                        : "r"(a[mt][0]), "r"(a[mt][1]), "r"(a[mt][2]), "r"(a[mt][3]),
                          "r"(b[nt][0]), "r"(b[nt][1]));
        }
    }

    float* Cz = Cf + (size_t)z * partStride;
#pragma unroll
    for (int mt = 0; mt < 2; mt++) {
        int r0 = bm + wm * 32 + mt * 16 + (lane >> 2);
        int r1 = r0 + 8;
#pragma unroll
        for (int nt = 0; nt < 4; nt++) {
            int cg = bn + wn * 32 + nt * 8 + (lane & 3) * 2;
            float bv0 = 0.f, bv1 = 0.f;
            if (bias && mode != 3) {
                if (cg < N) bv0 = bias[cg];
                if (cg + 1 < N) bv1 = bias[cg + 1];
            }
            float v00 = acc[mt][nt][0] + bv0, v01 = acc[mt][nt][1] + bv1;
            float v10 = acc[mt][nt][2] + bv0, v11 = acc[mt][nt][3] + bv1;
            if (mode == 2) {
                float* p0 = Cf + (size_t)(r0 & 63) * ((T_ - 1) * V_) + (size_t)(r0 >> 6) * V_;
                float* p1 = Cf + (size_t)(r1 & 63) * ((T_ - 1) * V_) + (size_t)(r1 >> 6) * V_;
                if (cg < N) { p0[cg] = v00; p1[cg] = v10; }
                if (cg + 1 < N) { p0[cg + 1] = v01; p1[cg + 1] = v11; }
            } else if (mode == 3) {
#pragma unroll
                for (int e = 0; e < 2; e++) {
                    int c = cg + e;
                    float va = e ? v01 : v00, vb = e ? v11 : v10;
                    float bb = g_bh0c0[c];
                    if (c < 1024) {
                        g_hall[r0 * H_ + c] = __float2half(va + bb);
                        g_hall[r1 * H_ + c] = __float2half(vb + bb);
                    } else {
                        g_cbuf[r0 * H_ + c - 1024] = va + bb;
                        g_cbuf[r1 * H_ + c - 1024] = vb + bb;
                    }
                }
            } else if (mode == 1) {
                if (cg < N) {
                    Ch[(size_t)r0 * ldc + cg] = __float2half(v00);
                    Ch[(size_t)r1 * ldc + cg] = __float2half(v10);
                }
                if (cg + 1 < N) {
                    Ch[(size_t)r0 * ldc + cg + 1] = __float2half(v01);
                    Ch[(size_t)r1 * ldc + cg + 1] = __float2half(v11);
                }
            } else {
                if (cg < N) {
                    Cz[(size_t)r0 * ldc + cg] = v00;
                    Cz[(size_t)r1 * ldc + cg] = v10;
                }
                if (cg + 1 < N) {
                    Cz[(size_t)r0 * ldc + cg + 1] = v01;
                    Cz[(size_t)r1 * ldc + cg + 1] = v11;
                }
            }
        }
    }
}

__global__ void __launch_bounds__(256)
hgemm(const __half* __restrict__ A, int lda,
      const __half* __restrict__ Bm, int ldb,
      const float* __restrict__ bias,
      float* __restrict__ Cf, __half* __restrict__ Ch,
      int ldc, int partStride, int N, int kChunk, int mode)
{
    gemm_core(A, lda, Bm, ldb, bias, Cf, Ch, ldc, partStride, N, kChunk,
              blockIdx.x * BM, blockIdx.y, blockIdx.z, mode);
}

// per-step fused GEMM: h_t @ [W_hh | W_datt]^T -> g_ghp partials (split-K 4)
__global__ void __launch_bounds__(256)
hw_kernel(const __half* __restrict__ h)
{
    gemm_core(h, H_, g_Wcat, H_, nullptr, g_ghp, nullptr,
              NCAT, B_ * NCAT, NCAT, H_ / 4, 0, blockIdx.x, blockIdx.y, 0);
}

// batched logits
__global__ void __launch_bounds__(256)
logits_kernel(const float* __restrict__ b_out, float* __restrict__ out)
{
    gemm_core(g_hall + B_ * H_, H_, g_Wout, H_, b_out, out, nullptr,
              0, 0, V_, H_, blockIdx.x * BM, blockIdx.y, 0, 2);
}

// ---------------- fused step: att2 reduce + softmax + gates + LSTM ---------
__global__ void __launch_bounds__(512)
step_kernel(const float* __restrict__ b_datt,
            const float* __restrict__ W_fatt,
            const float* __restrict__ b_fatt,
            int t)
{
    const int b = blockIdx.x;
    const int tid = threadIdx.x;
    const int warp = tid >> 5, lane = tid & 31;

    __shared__ float att2s[A_];
    __shared__ float alpha[P_];
    __shared__ float gates[G4_];

    // A: reduce att2 split-K partials (columns 4096..4607 of ghp)
    for (int a = tid; a < A_; a += 512) {
        float s = b_datt[a];
#pragma unroll
        for (int z = 0; z < 4; z++)
            s += g_ghp[(size_t)z * B_ * NCAT + b * NCAT + G4_ + a];
        att2s[a] = s;
    }
    __syncthreads();

    // B: e_p then softmax
    const float* att1b = g_att1 + (size_t)b * P_ * A_;
    for (int p = warp; p < P_; p += 16) {
        float s = 0.f;
        for (int a = lane; a < A_; a += 32) {
            float v = att1b[p * A_ + a] + att2s[a];
            s += fmaxf(v, 0.f) * W_fatt[a];
        }
#pragma unroll
        for (int o = 16; o; o >>= 1) s += __shfl_xor_sync(0xffffffffu, s, o);
        if (lane == 0) alpha[p] = s + b_fatt[0];
    }
    __syncthreads();

    if (warp == 0) {
        float v0 = (lane < P_) ? alpha[lane] : -1e30f;
        float v1 = (lane + 32 < P_) ? alpha[lane + 32] : -1e30f;
        float m = fmaxf(v0, v1);
#pragma unroll
        for (int o = 16; o; o >>= 1) m = fmaxf(m, __shfl_xor_sync(0xffffffffu, m, o));
        float e0 = (lane < P_) ? __expf(v0 - m) : 0.f;
        float e1 = (lane + 32 < P_) ? __expf(v1 - m) : 0.f;
        float s = e0 + e1;
#pragma unroll
        for (int o = 16; o; o >>= 1) s += __shfl_xor_sync(0xffffffffu, s, o);
        float inv = 1.0f / s;
        if (lane < P_) alpha[lane] = e0 * inv;
        if (lane + 32 < P_) alpha[lane + 32] = e1 * inv;
    }
    __syncthreads();

    // C: gates[j] = sum_p alpha_p*encW[b,p,j] + gatesX[t,b,j] + sum_z ghp[z,b,j] + bsum[j]
    const __half2* encW2 = (const __half2*)(g_encW + (size_t)b * P_ * G4_);
    const __half2* gx2   = (const __half2*)(g_gatesX + ((size_t)t * B_ + b) * G4_);
#pragma unroll
    for (int u = 0; u < 4; u++) {
        int jj = tid + u * 512;          // half2 index, 0..2047
        float sx = 0.f, sy = 0.f;
#pragma unroll 7
        for (int p = 0; p < P_; p++) {
            float2 w = __half22float2(encW2[(size_t)p * (G4_ / 2) + jj]);
            float ap = alpha[p];
            sx += ap * w.x;
            sy += ap * w.y;
        }
        int j = jj * 2;
        float2 gx = __half22float2(gx2[jj]);
        sx += gx.x + g_bsum[j];
        sy += gx.y + g_bsum[j + 1];
#pragma unroll
        for (int z = 0; z < 4; z++) {
            const float2 gh = *(const float2*)(g_ghp + (size_t)z * B_ * NCAT + b * NCAT + j);
            sx += gh.x; sy += gh.y;
        }
        gates[j] = sx;
        gates[j + 1] = sy;
    }
    __syncthreads();

    // D: LSTM pointwise -> h_{t+1}, c_{t+1}
    const float* c_cur = g_cbuf + (t & 1) * B_ * H_;
    float* c_nxt = g_cbuf + ((t + 1) & 1) * B_ * H_;
    __half* h_nxt = g_hall + (size_t)(t + 1) * B_ * H_;
#pragma unroll
    for (int v = 0; v < 2; v++) {
        int j = tid + v * 512;
        float gi = gates[j];
        float gf = gates[H_ + j];
        float gg = gates[2 * H_ + j];
        float go = gates[3 * H_ + j];
        float si = 1.f / (1.f + __expf(-gi));
        float sf = 1.f / (1.f + __expf(-gf));
        float so = 1.f / (1.f + __expf(-go));
        float tg = tanhf(gg);
        float c  = sf * c_cur[b * H_ + j] + si * tg;
        c_nxt[b * H_ + j] = c;
        h_nxt[b * H_ + j] = __float2half(so * tanhf(c));
    }
}

// ---------------- host ----------------
template <typename T>
static T* sym_addr(const void* sym) {
    void* p = nullptr;
    cudaGetSymbolAddress(&p, sym);
    return (T*)p;
}

extern "C" void kernel_launch(void* const* d_in, const int* in_sizes, int n_in,
                              void* d_out, int out_size)
{
    const float* enc    = (const float*)d_in[0];
    const int*   caps   = (const int*)  d_in[1];
    const float* embed  = (const float*)d_in[2];
    const float* W_eatt = (const float*)d_in[3];
    const float* b_eatt = (const float*)d_in[4];
    const float* W_datt = (const float*)d_in[5];
    const float* b_datt = (const float*)d_in[6];
    const float* W_fatt = (const float*)d_in[7];
    const float* b_fatt = (const float*)d_in[8];
    const float* W_ih   = (const float*)d_in[9];
    const float* b_ih   = (const float*)d_in[10];
    const float* W_hh   = (const float*)d_in[11];
    const float* b_hh   = (const float*)d_in[12];
    const float* W_h0   = (const float*)d_in[13];
    const float* b_h0   = (const float*)d_in[14];
    const float* W_c0   = (const float*)d_in[15];
    const float* b_c0   = (const float*)d_in[16];
    const float* W_out  = (const float*)d_in[17];
    const float* b_out  = (const float*)d_in[18];
    float* out = (float*)d_out;

    cudaFuncSetAttribute(hgemm, cudaFuncAttributeMaxDynamicSharedMemorySize, SMEM_BYTES);
    cudaFuncSetAttribute(hw_kernel, cudaFuncAttributeMaxDynamicSharedMemorySize, SMEM_BYTES);
    cudaFuncSetAttribute(logits_kernel, cudaFuncAttributeMaxDynamicSharedMemorySize, SMEM_BYTES);

    __half* Weth  = sym_addr<__half>(g_Weatt);
    __half* Wh0c0 = sym_addr<__half>(g_Wh0c0);
    __half* Wihx  = sym_addr<__half>(g_Wihx);
    __half* Wihc  = sym_addr<__half>(g_Wihc);
    __half* ench  = sym_addr<__half>(g_ench);
    __half* meanh = sym_addr<__half>(g_meanh);
    __half* embX  = sym_addr<__half>(g_embX);
    __half* hall  = sym_addr<__half>(g_hall);
    __half* encW  = sym_addr<__half>(g_encW);
    __half* gatesX= sym_addr<__half>(g_gatesX);
    float*  att1  = sym_addr<float>(g_att1);

    // ---- one-time setup ----
    mean_kernel<<<(B_ * ENC_ + 255) / 256, 256>>>(enc);
    cvt_all<<<(T8 + 255) / 256, 256>>>(W_out, W_eatt, W_h0, W_c0, enc, W_ih, W_hh,
                                       W_datt, b_h0, b_c0, b_ih, b_hh);
    embx_kernel<<<((T_ - 1) * B_ * E_ + 255) / 256, 256>>>(caps, embed);

    // h0/c0 fused: mean @ [Wh0;Wc0]^T, N=2048, mode 3
    hgemm<<<dim3(1, 2048 / BN, 1), 256, SMEM_BYTES>>>(meanh, ENC_, Wh0c0, ENC_, nullptr,
                                                      nullptr, nullptr, 0, 0, 2048, ENC_, 3);
    // att1 = ench @ Weatt^T + b_eatt (fp32)
    hgemm<<<dim3((B_ * P_) / BM, A_ / BN, 1), 256, SMEM_BYTES>>>(ench, ENC_, Weth, ENC_, b_eatt,
                                                                 att1, nullptr, A_, 0, A_, ENC_, 0);
    // gatesX = embX @ Wihx^T (fp16 out)
    hgemm<<<dim3((T_ - 1) * B_ / BM, G4_ / BN, 1), 256, SMEM_BYTES>>>(embX, E_, Wihx, E_, nullptr,
                                                                      nullptr, gatesX, G4_, 0, G4_, E_, 1);
    // encW = ench @ Wihc^T (fp16 out)  [3136 x 4096]
    hgemm<<<dim3((B_ * P_) / BM, G4_ / BN, 1), 256, SMEM_BYTES>>>(ench, ENC_, Wihc, ENC_, nullptr,
                                                                  nullptr, encW, G4_, 0, G4_, ENC_, 1);

    // ---- recurrent loop: 2 launches per step ----
    for (int t = 0; t < T_ - 1; t++) {
        hw_kernel<<<dim3(NCAT / BN, 4, 1), 256, SMEM_BYTES>>>(hall + (size_t)t * B_ * H_);
        step_kernel<<<B_, 512>>>(b_datt, W_fatt, b_fatt, t);
    }

    // ---- batched logits ----
    logits_kernel<<<dim3((T_ - 1) * B_ / BM, NLOGIT, 1), 256, SMEM_BYTES>>>(b_out, out);
}

// round 9
// speedup vs baseline: 1.9323x; 1.2912x over previous
#include <cuda_runtime.h>
#include <cuda_fp16.h>
#include <cstdint>

#define B_    64
#define P_    49
#define ENC_  1280
#define T_    25
#define V_    10000
#define E_    512
#define H_    1024
#define A_    512
#define G4_   4096           /* 4*H */
#define NCAT  4608           /* 4*H + A : [W_hh | W_datt] fused */
#define WIH_LD 1792          /* W_ih row stride: E + ENC */

#define BM 64
#define BN 128
#define BK 64
#define STG 4
#define RS 72
#define SMEM_BYTES (STG * (BM + BN) * RS * 2)

#define NLOGIT ((V_ + BN - 1) / BN)   /* 79 */

// ---------------- static scratch ----------------
__device__ __align__(16) __half g_Wout [V_ * H_];
__device__ __align__(16) __half g_Weatt[A_ * ENC_];
__device__ __align__(16) __half g_Wh0c0[2048 * ENC_];     /* [Wh0 ; Wc0] */
__device__ __align__(16) __half g_Wihx [G4_ * E_];
__device__ __align__(16) __half g_Wihc [G4_ * ENC_];
__device__ __align__(16) __half g_Wcat [NCAT * H_];       /* [W_hh ; W_datt] */
__device__ __align__(16) __half g_ench [B_ * P_ * ENC_];
__device__ __align__(16) __half g_meanh[B_ * ENC_];
__device__ __align__(16) __half g_embX [(T_ - 1) * B_ * E_];
__device__ __align__(16) __half g_hall [T_ * B_ * H_];
__device__ __align__(16) __half g_encW [B_ * P_ * G4_];   /* 25.7 MB fp16 */
__device__ __align__(16) __half g_gatesX[(T_ - 1) * B_ * G4_];
__device__ __align__(16) __half g_att1h[B_ * P_ * A_];
__device__ __align__(16) float  g_cbuf [2 * B_ * H_];
__device__ __align__(16) float  g_ghp  [8 * B_ * NCAT];   /* split-K partials */
__device__ __align__(16) float  g_bh0c0[2048];
__device__ __align__(16) float  g_bsum [G4_];             /* b_ih + b_hh */

// ---------------- setup conversions ----------------
#define T0 (V_ * H_)
#define T1 (T0 + A_ * ENC_)
#define T2 (T1 + 2048 * ENC_)
#define T3 (T2 + B_ * P_ * ENC_)
#define T4 (T3 + G4_ * E_)
#define T5 (T4 + G4_ * ENC_)
#define T6 (T5 + NCAT * H_)
#define T7 (T6 + 2048)
#define T8 (T7 + G4_)

__global__ void cvt_all(const float* __restrict__ Wo, const float* __restrict__ We,
                        const float* __restrict__ Wh0, const float* __restrict__ Wc0,
                        const float* __restrict__ enc, const float* __restrict__ Wih,
                        const float* __restrict__ Whh, const float* __restrict__ Wd,
                        const float* __restrict__ bh0, const float* __restrict__ bc0,
                        const float* __restrict__ bih, const float* __restrict__ bhh)
{
    int i = blockIdx.x * 256 + threadIdx.x;
    if (i >= T8) return;
    if (i < T0) { g_Wout[i] = __float2half(Wo[i]); return; }
    if (i < T1) { g_Weatt[i - T0] = __float2half(We[i - T0]); return; }
    if (i < T2) {
        int j = i - T1; int r = j / ENC_, c = j % ENC_;
        g_Wh0c0[j] = __float2half(r < 1024 ? Wh0[r * ENC_ + c] : Wc0[(r - 1024) * ENC_ + c]);
        return;
    }
    if (i < T3) { g_ench[i - T2] = __float2half(enc[i - T2]); return; }
    if (i < T4) {
        int j = i - T3; int r = j / E_, c = j % E_;
        g_Wihx[j] = __float2half(Wih[(size_t)r * WIH_LD + c]);
        return;
    }
    if (i < T5) {
        int j = i - T4; int r = j / ENC_, c = j % ENC_;
        g_Wihc[j] = __float2half(Wih[(size_t)r * WIH_LD + E_ + c]);
        return;
    }
    if (i < T6) {
        int j = i - T5; int r = j / H_, c = j % H_;
        g_Wcat[j] = __float2half(r < G4_ ? Whh[(size_t)r * H_ + c] : Wd[(size_t)(r - G4_) * H_ + c]);
        return;
    }
    if (i < T7) {
        int j = i - T6;
        g_bh0c0[j] = (j < 1024) ? bh0[j] : bc0[j - 1024];
        return;
    }
    int j = i - T7;
    g_bsum[j] = bih[j] + bhh[j];
}

__global__ void mean_kernel(const float* __restrict__ enc) {
    int i = blockIdx.x * blockDim.x + threadIdx.x;
    if (i >= B_ * ENC_) return;
    int b = i / ENC_, e = i % ENC_;
    const float* p = enc + (size_t)b * P_ * ENC_ + e;
    float s = 0.f;
#pragma unroll 7
    for (int k = 0; k < P_; k++) s += p[k * ENC_];
    g_meanh[i] = __float2half(s * (1.0f / P_));
}

__global__ void embx_kernel(const int* __restrict__ captions,
                            const float* __restrict__ embed)
{
    int i = blockIdx.x * 256 + threadIdx.x;
    if (i >= (T_ - 1) * B_ * E_) return;
    int r = i / E_, c = i % E_;
    int t = r / B_, b = r % B_;
    int cap = captions[b * T_ + t];
    g_embX[i] = __float2half(embed[(size_t)cap * E_ + c]);
}

// ---------------- fp16 GEMM core (256 thr, 64x128 tile, ldmatrix) ----------
__device__ __forceinline__ void issue_tile(
    const __half* __restrict__ A, int lda,
    const __half* __restrict__ B, int ldb,
    int bm, int bn, int N, int kt,
    __half* as, __half* bs, int tid)
{
#pragma unroll
    for (int i = 0; i < 2; i++) {
        int idx = i * 256 + tid;
        int r = idx >> 3, c8 = (idx & 7) * 8;
        uint32_t da = (uint32_t)__cvta_generic_to_shared(as + r * RS + c8);
        const __half* pa = A + (size_t)(bm + r) * lda + kt + c8;
        asm volatile("cp.async.cg.shared.global [%0], [%1], 16;" :: "r"(da), "l"(pa));
    }
#pragma unroll
    for (int i = 0; i < 4; i++) {
        int idx = i * 256 + tid;
        int r = idx >> 3, c8 = (idx & 7) * 8;
        int n = bn + r;
        uint32_t db = (uint32_t)__cvta_generic_to_shared(bs + r * RS + c8);
        const __half* pb = B + (size_t)(n < N ? n : 0) * ldb + kt + c8;
        int sz = (n < N) ? 16 : 0;
        asm volatile("cp.async.cg.shared.global [%0], [%1], 16, %2;" :: "r"(db), "l"(pb), "r"(sz));
    }
    asm volatile("cp.async.commit_group;");
}

// mode: 0 = fp32 Cf split-K partials, 1 = fp16 Ch (+bias),
//       2 = logits capmap, 3 = h0c0 split
__device__ __forceinline__ void gemm_core(
    const __half* __restrict__ A, int lda,
    const __half* __restrict__ Bm, int ldb,
    const float* __restrict__ bias,
    float* __restrict__ Cf, __half* __restrict__ Ch,
    int ldc, int partStride, int N, int kChunk,
    int bm, int by, int z, int mode)
{
    extern __shared__ __half sm[];
    __half* Asm = sm;
    __half* Bsm = sm + STG * BM * RS;

    const int tid = threadIdx.x;
    const int warp = tid >> 5, lane = tid & 31;
    const int wm = warp >> 2, wn = warp & 3;
    const int bn = by * BN;
    const int k0 = z * kChunk;
    const int nk = kChunk / BK;

    float acc[2][4][4];
#pragma unroll
    for (int i = 0; i < 2; i++)
#pragma unroll
        for (int j = 0; j < 4; j++)
#pragma unroll
            for (int q = 0; q < 4; q++) acc[i][j][q] = 0.f;

    const int a_row_l = (lane & 7) + ((lane >> 3) & 1) * 8;
    const int a_col_l = ((lane >> 4) & 1) * 8;
    const int b_row_l = (lane & 7) + ((lane >> 4) & 1) * 8;
    const int b_col_l = ((lane >> 3) & 1) * 8;

#pragma unroll
    for (int s = 0; s < STG - 1; s++) {
        if (s < nk) issue_tile(A, lda, Bm, ldb, bm, bn, N, k0 + s * BK,
                               Asm + s * BM * RS, Bsm + s * BN * RS, tid);
        else asm volatile("cp.async.commit_group;");
    }

    for (int i = 0; i < nk; i++) {
        asm volatile("cp.async.wait_group %0;" :: "n"(STG - 2));
        __syncthreads();

        int ntile = i + STG - 1;
        if (ntile < nk) {
            int slot = ntile % STG;
            issue_tile(A, lda, Bm, ldb, bm, bn, N, k0 + ntile * BK,
                       Asm + slot * BM * RS, Bsm + slot * BN * RS, tid);
        } else {
            asm volatile("cp.async.commit_group;");
        }

        const __half* at = Asm + (i % STG) * BM * RS;
        const __half* bt = Bsm + (i % STG) * BN * RS;

#pragma unroll
        for (int ks = 0; ks < 4; ks++) {
            uint32_t a[2][4], b[4][2];
#pragma unroll
            for (int mt = 0; mt < 2; mt++) {
                int row = wm * 32 + mt * 16 + a_row_l;
                int col = ks * 16 + a_col_l;
                uint32_t ad = (uint32_t)__cvta_generic_to_shared(at + row * RS + col);
                asm volatile("ldmatrix.sync.aligned.m8n8.x4.shared.b16 {%0,%1,%2,%3}, [%4];"
                             : "=r"(a[mt][0]), "=r"(a[mt][1]), "=r"(a[mt][2]), "=r"(a[mt][3])
                             : "r"(ad));
            }
#pragma unroll
            for (int ntp = 0; ntp < 2; ntp++) {
                int row = wn * 32 + ntp * 16 + b_row_l;
                int col = ks * 16 + b_col_l;
                uint32_t bd = (uint32_t)__cvta_generic_to_shared(bt + row * RS + col);
                asm volatile("ldmatrix.sync.aligned.m8n8.x4.shared.b16 {%0,%1,%2,%3}, [%4];"
                             : "=r"(b[2 * ntp][0]), "=r"(b[2 * ntp][1]),
                               "=r"(b[2 * ntp + 1][0]), "=r"(b[2 * ntp + 1][1])
                             : "r"(bd));
            }
#pragma unroll
            for (int mt = 0; mt < 2; mt++)
#pragma unroll
                for (int nt = 0; nt < 4; nt++)
                    asm volatile(
                        "mma.sync.aligned.m16n8k16.row.col.f32.f16.f16.f32 "
                        "{%0,%1,%2,%3}, {%4,%5,%6,%7}, {%8,%9}, {%0,%1,%2,%3};"
                        : "+f"(acc[mt][nt][0]), "+f"(acc[mt][nt][1]),
                          "+f"(acc[mt][nt][2]), "+f"(acc[mt][nt][3])
                        : "r"(a[mt][0]), "r"(a[mt][1]), "r"(a[mt][2]), "r"(a[mt][3]),
                          "r"(b[nt][0]), "r"(b[nt][1]));
        }
    }

    float* Cz = Cf + (size_t)z * partStride;
#pragma unroll
    for (int mt = 0; mt < 2; mt++) {
        int r0 = bm + wm * 32 + mt * 16 + (lane >> 2);
        int r1 = r0 + 8;
#pragma unroll
        for (int nt = 0; nt < 4; nt++) {
            int cg = bn + wn * 32 + nt * 8 + (lane & 3) * 2;
            float bv0 = 0.f, bv1 = 0.f;
            if (bias && mode != 3) {
                if (cg < N) bv0 = bias[cg];
                if (cg + 1 < N) bv1 = bias[cg + 1];
            }
            float v00 = acc[mt][nt][0] + bv0, v01 = acc[mt][nt][1] + bv1;
            float v10 = acc[mt][nt][2] + bv0, v11 = acc[mt][nt][3] + bv1;
            if (mode == 2) {
                float* p0 = Cf + (size_t)(r0 & 63) * ((T_ - 1) * V_) + (size_t)(r0 >> 6) * V_;
                float* p1 = Cf + (size_t)(r1 & 63) * ((T_ - 1) * V_) + (size_t)(r1 >> 6) * V_;
                if (cg < N) { p0[cg] = v00; p1[cg] = v10; }
                if (cg + 1 < N) { p0[cg + 1] = v01; p1[cg + 1] = v11; }
            } else if (mode == 3) {
#pragma unroll
                for (int e = 0; e < 2; e++) {
                    int c = cg + e;
                    float va = e ? v01 : v00, vb = e ? v11 : v10;
                    float bb = g_bh0c0[c];
                    if (c < 1024) {
                        g_hall[r0 * H_ + c] = __float2half(va + bb);
                        g_hall[r1 * H_ + c] = __float2half(vb + bb);
                    } else {
                        g_cbuf[r0 * H_ + c - 1024] = va + bb;
                        g_cbuf[r1 * H_ + c - 1024] = vb + bb;
                    }
                }
            } else if (mode == 1) {
                if (cg < N) {
                    Ch[(size_t)r0 * ldc + cg] = __float2half(v00);
                    Ch[(size_t)r1 * ldc + cg] = __float2half(v10);
                }
                if (cg + 1 < N) {
                    Ch[(size_t)r0 * ldc + cg + 1] = __float2half(v01);
                    Ch[(size_t)r1 * ldc + cg + 1] = __float2half(v11);
                }
            } else {
                if (cg < N) {
                    Cz[(size_t)r0 * ldc + cg] = v00;
                    Cz[(size_t)r1 * ldc + cg] = v10;
                }
                if (cg + 1 < N) {
                    Cz[(size_t)r0 * ldc + cg + 1] = v01;
                    Cz[(size_t)r1 * ldc + cg + 1] = v11;
                }
            }
        }
    }
}

// one big setup launch: h0c0 [16] + att1 [196] + gatesX [768] + encW [1568]
#define CB0 16
#define CB1 (CB0 + 196)
#define CB2 (CB1 + 768)
#define CB3 (CB2 + 1568)

__global__ void __launch_bounds__(256)
setup_combo(const float* __restrict__ b_eatt)
{
    int bi = blockIdx.x;
    if (bi < CB0) {
        gemm_core(g_meanh, ENC_, g_Wh0c0, ENC_, nullptr, nullptr, nullptr,
                  0, 0, 2048, ENC_, 0, bi, 0, 3);
    } else if (bi < CB1) {
        int i = bi - CB0;                    // 49 x 4
        gemm_core(g_ench, ENC_, g_Weatt, ENC_, b_eatt, nullptr, g_att1h,
                  A_, 0, A_, ENC_, (i % 49) * BM, i / 49, 0, 1);
    } else if (bi < CB2) {
        int i = bi - CB1;                    // 24 x 32
        gemm_core(g_embX, E_, g_Wihx, E_, nullptr, nullptr, g_gatesX,
                  G4_, 0, G4_, E_, (i % 24) * BM, i / 24, 0, 1);
    } else {
        int i = bi - CB2;                    // 49 x 32
        gemm_core(g_ench, ENC_, g_Wihc, ENC_, nullptr, nullptr, g_encW,
                  G4_, 0, G4_, ENC_, (i % 49) * BM, i / 49, 0, 1);
    }
}

// per-step fused GEMM: h_t @ [W_hh | W_datt]^T -> g_ghp partials (split-K 8)
__global__ void __launch_bounds__(256)
hw_kernel(const __half* __restrict__ h)
{
    gemm_core(h, H_, g_Wcat, H_, nullptr, g_ghp, nullptr,
              NCAT, B_ * NCAT, NCAT, H_ / 8, 0, blockIdx.x, blockIdx.y, 0);
}

// batched logits
__global__ void __launch_bounds__(256)
logits_kernel(const float* __restrict__ b_out, float* __restrict__ out)
{
    gemm_core(g_hall + B_ * H_, H_, g_Wout, H_, b_out, out, nullptr,
              0, 0, V_, H_, blockIdx.x * BM, blockIdx.y, 0, 2);
}

// ---------------- gate+LSTM: 4 stripes x 64 b = 256 blocks ------------------
__global__ void __launch_bounds__(256)
gatelstm_kernel(const float* __restrict__ b_datt,
                const float* __restrict__ W_fatt,
                const float* __restrict__ b_fatt,
                int t)
{
    const int z = blockIdx.x;     // j-stripe 0..3
    const int b = blockIdx.y;     // batch
    const int tid = threadIdx.x;
    const int warp = tid >> 5, lane = tid & 31;

    __shared__ float att2s[A_];
    __shared__ float alpha[P_];

    // att2 reduce (8 split-K partials, columns G4_..G4_+511 of ghp)
    for (int a = tid; a < A_; a += 256) {
        float s = b_datt[a];
#pragma unroll
        for (int zz = 0; zz < 8; zz++)
            s += g_ghp[(size_t)zz * B_ * NCAT + b * NCAT + G4_ + a];
        att2s[a] = s;
    }
    __syncthreads();

    // e_p (att1 fp16)
    const __half* att1b = g_att1h + (size_t)b * P_ * A_;
#pragma unroll 7
    for (int p = warp; p < P_; p += 8) {
        float s = 0.f;
#pragma unroll
        for (int a = lane; a < A_; a += 32) {
            float v = __half2float(att1b[p * A_ + a]) + att2s[a];
            s += fmaxf(v, 0.f) * W_fatt[a];
        }
#pragma unroll
        for (int o = 16; o; o >>= 1) s += __shfl_xor_sync(0xffffffffu, s, o);
        if (lane == 0) alpha[p] = s + b_fatt[0];
    }
    __syncthreads();

    if (warp == 0) {
        float v0 = (lane < P_) ? alpha[lane] : -1e30f;
        float v1 = (lane + 32 < P_) ? alpha[lane + 32] : -1e30f;
        float m = fmaxf(v0, v1);
#pragma unroll
        for (int o = 16; o; o >>= 1) m = fmaxf(m, __shfl_xor_sync(0xffffffffu, m, o));
        float e0 = (lane < P_) ? __expf(v0 - m) : 0.f;
        float e1 = (lane + 32 < P_) ? __expf(v1 - m) : 0.f;
        float s = e0 + e1;
#pragma unroll
        for (int o = 16; o; o >>= 1) s += __shfl_xor_sync(0xffffffffu, s, o);
        float inv = 1.0f / s;
        if (lane < P_) alpha[lane] = e0 * inv;
        if (lane + 32 < P_) alpha[lane + 32] = e1 * inv;
    }
    __syncthreads();

    // gates for stripe j = z*256 + tid  (one j per thread, all 4 gates)
    const int j = z * 256 + tid;
    const __half* encWb = g_encW + (size_t)b * P_ * G4_;
    float gi = 0.f, gf = 0.f, gg = 0.f, go = 0.f;
#pragma unroll 7
    for (int p = 0; p < P_; p++) {
        const __half* row = encWb + (size_t)p * G4_;
        float ap = alpha[p];
        gi += ap * __half2float(row[j]);
        gf += ap * __half2float(row[H_ + j]);
        gg += ap * __half2float(row[2 * H_ + j]);
        go += ap * __half2float(row[3 * H_ + j]);
    }
    const __half* gx = g_gatesX + ((size_t)t * B_ + b) * G4_;
    gi += __half2float(gx[j])          + g_bsum[j];
    gf += __half2float(gx[H_ + j])     + g_bsum[H_ + j];
    gg += __half2float(gx[2 * H_ + j]) + g_bsum[2 * H_ + j];
    go += __half2float(gx[3 * H_ + j]) + g_bsum[3 * H_ + j];
#pragma unroll
    for (int zz = 0; zz < 8; zz++) {
        const float* gp = g_ghp + (size_t)zz * B_ * NCAT + b * NCAT;
        gi += gp[j]; gf += gp[H_ + j]; gg += gp[2 * H_ + j]; go += gp[3 * H_ + j];
    }

    // LSTM pointwise
    const float* c_cur = g_cbuf + (t & 1) * B_ * H_;
    float* c_nxt = g_cbuf + ((t + 1) & 1) * B_ * H_;
    __half* h_nxt = g_hall + (size_t)(t + 1) * B_ * H_;
    float si = 1.f / (1.f + __expf(-gi));
    float sf = 1.f / (1.f + __expf(-gf));
    float so = 1.f / (1.f + __expf(-go));
    float tg = tanhf(gg);
    float c  = sf * c_cur[b * H_ + j] + si * tg;
    c_nxt[b * H_ + j] = c;
    h_nxt[b * H_ + j] = __float2half(so * tanhf(c));
}

// ---------------- host ----------------
extern "C" void kernel_launch(void* const* d_in, const int* in_sizes, int n_in,
                              void* d_out, int out_size)
{
    const float* enc    = (const float*)d_in[0];
    const int*   caps   = (const int*)  d_in[1];
    const float* embed  = (const float*)d_in[2];
    const float* W_eatt = (const float*)d_in[3];
    const float* b_eatt = (const float*)d_in[4];
    const float* W_datt = (const float*)d_in[5];
    const float* b_datt = (const float*)d_in[6];
    const float* W_fatt = (const float*)d_in[7];
    const float* b_fatt = (const float*)d_in[8];
    const float* W_ih   = (const float*)d_in[9];
    const float* b_ih   = (const float*)d_in[10];
    const float* W_hh   = (const float*)d_in[11];
    const float* b_hh   = (const float*)d_in[12];
    const float* W_h0   = (const float*)d_in[13];
    const float* b_h0   = (const float*)d_in[14];
    const float* W_c0   = (const float*)d_in[15];
    const float* b_c0   = (const float*)d_in[16];
    const float* W_out  = (const float*)d_in[17];
    const float* b_out  = (const float*)d_in[18];
    float* out = (float*)d_out;

    cudaFuncSetAttribute(setup_combo, cudaFuncAttributeMaxDynamicSharedMemorySize, SMEM_BYTES);
    cudaFuncSetAttribute(hw_kernel, cudaFuncAttributeMaxDynamicSharedMemorySize, SMEM_BYTES);
    cudaFuncSetAttribute(logits_kernel, cudaFuncAttributeMaxDynamicSharedMemorySize, SMEM_BYTES);

    void* hall_p = nullptr;
    cudaGetSymbolAddress(&hall_p, g_hall);
    __half* hall = (__half*)hall_p;

    // ---- one-time setup ----
    mean_kernel<<<(B_ * ENC_ + 255) / 256, 256>>>(enc);
    cvt_all<<<(T8 + 255) / 256, 256>>>(W_out, W_eatt, W_h0, W_c0, enc, W_ih, W_hh,
                                       W_datt, b_h0, b_c0, b_ih, b_hh);
    embx_kernel<<<((T_ - 1) * B_ * E_ + 255) / 256, 256>>>(caps, embed);

    // all independent setup GEMMs in one full-chip launch
    setup_combo<<<CB3, 256, SMEM_BYTES>>>(b_eatt);

    // ---- recurrent loop: 2 launches per step ----
    for (int t = 0; t < T_ - 1; t++) {
        hw_kernel<<<dim3(NCAT / BN, 8, 1), 256, SMEM_BYTES>>>(hall + (size_t)t * B_ * H_);
        gatelstm_kernel<<<dim3(4, B_, 1), 256>>>(b_datt, W_fatt, b_fatt, t);
    }

    // ---- batched logits ----
    logits_kernel<<<dim3((T_ - 1) * B_ / BM, NLOGIT, 1), 256, SMEM_BYTES>>>(b_out, out);
}

// round 10
// speedup vs baseline: 2.1455x; 1.1103x over previous
#include <cuda_runtime.h>
#include <cuda_fp16.h>
#include <cstdint>

#define B_    64
#define P_    49
#define ENC_  1280
#define T_    25
#define V_    10000
#define E_    512
#define H_    1024
#define A_    512
#define G4_   4096
#define NCAT  4608           /* 4*H + A */
#define WIH_LD 1792

#define BK 64
#define RS 72
#define STG64  4
#define STG128 3
#define SMEM_BYTES 110592    /* = 4*(64+128)*72*2 = 3*(128+128)*72*2 */

// ---------------- static scratch ----------------
__device__ __align__(16) __half g_Wout [V_ * H_];
__device__ __align__(16) __half g_Weatt[A_ * ENC_];
__device__ __align__(16) __half g_Wh0c0[2048 * ENC_];
__device__ __align__(16) __half g_Wihx [G4_ * E_];
__device__ __align__(16) __half g_Wihc [G4_ * ENC_];
__device__ __align__(16) __half g_Wcat [NCAT * H_];
__device__ __align__(16) __half g_ench [(B_ * P_ + 64) * ENC_];   /* +64 pad rows */
__device__ __align__(16) __half g_meanh[B_ * ENC_];
__device__ __align__(16) __half g_embX [(T_ - 1) * B_ * E_];
__device__ __align__(16) __half g_hall [T_ * B_ * H_];
__device__ __align__(16) __half g_encW [B_ * P_ * G4_];
__device__ __align__(16) __half g_gatesX[(T_ - 1) * B_ * G4_];
__device__ __align__(16) __half g_att1h[B_ * P_ * A_];
__device__ __align__(16) float  g_cbuf [2 * B_ * H_];
__device__ __align__(16) float  g_ghp  [8 * B_ * NCAT];
__device__ __align__(16) float  g_bh0c0[2048];
__device__ __align__(16) float  g_bsum [G4_];

// ---------------- setup conversions (4 elems / thread) ----------------
#define T0 (V_ * H_)
#define T1 (T0 + A_ * ENC_)
#define T2 (T1 + 2048 * ENC_)
#define T3 (T2 + B_ * P_ * ENC_)
#define T4 (T3 + G4_ * E_)
#define T5 (T4 + G4_ * ENC_)
#define T6 (T5 + NCAT * H_)
#define T7 (T6 + 2048)
#define T8 (T7 + G4_)

__device__ __forceinline__ void cvt4(__half* d, const float* s) {
    float4 v = *(const float4*)s;
    __half2* d2 = (__half2*)d;
    d2[0] = __floats2half2_rn(v.x, v.y);
    d2[1] = __floats2half2_rn(v.z, v.w);
}

__global__ void cvt_all(const float* __restrict__ Wo, const float* __restrict__ We,
                        const float* __restrict__ Wh0, const float* __restrict__ Wc0,
                        const float* __restrict__ enc, const float* __restrict__ Wih,
                        const float* __restrict__ Whh, const float* __restrict__ Wd,
                        const float* __restrict__ bh0, const float* __restrict__ bc0,
                        const float* __restrict__ bih, const float* __restrict__ bhh)
{
    int i = (blockIdx.x * 256 + threadIdx.x) * 4;
    if (i >= T8) return;
    if (i < T0) { cvt4(g_Wout + i, Wo + i); return; }
    if (i < T1) { cvt4(g_Weatt + (i - T0), We + (i - T0)); return; }
    if (i < T2) {
        int j = i - T1; int r = j / ENC_, c = j % ENC_;
        cvt4(g_Wh0c0 + j, (r < 1024 ? Wh0 + (size_t)r * ENC_ : Wc0 + (size_t)(r - 1024) * ENC_) + c);
        return;
    }
    if (i < T3) { cvt4(g_ench + (i - T2), enc + (i - T2)); return; }
    if (i < T4) {
        int j = i - T3; int r = j / E_, c = j % E_;
        cvt4(g_Wihx + j, Wih + (size_t)r * WIH_LD + c);
        return;
    }
    if (i < T5) {
        int j = i - T4; int r = j / ENC_, c = j % ENC_;
        cvt4(g_Wihc + j, Wih + (size_t)r * WIH_LD + E_ + c);
        return;
    }
    if (i < T6) {
        int j = i - T5; int r = j / H_, c = j % H_;
        cvt4(g_Wcat + j, (r < G4_ ? Whh + (size_t)r * H_ : Wd + (size_t)(r - G4_) * H_) + c);
        return;
    }
    if (i < T7) {
        int j = i - T6;
        *(float4*)(g_bh0c0 + j) = (j < 1024) ? *(const float4*)(bh0 + j)
                                             : *(const float4*)(bc0 + (j - 1024));
        return;
    }
    int j = i - T7;
    float4 a = *(const float4*)(bih + j), bv = *(const float4*)(bhh + j);
    *(float4*)(g_bsum + j) = make_float4(a.x + bv.x, a.y + bv.y, a.z + bv.z, a.w + bv.w);
}

__global__ void mean_kernel(const float* __restrict__ enc) {
    int i = blockIdx.x * blockDim.x + threadIdx.x;
    if (i >= B_ * ENC_) return;
    int b = i / ENC_, e = i % ENC_;
    const float* p = enc + (size_t)b * P_ * ENC_ + e;
    float s = 0.f;
#pragma unroll 7
    for (int k = 0; k < P_; k++) s += p[k * ENC_];
    g_meanh[i] = __float2half(s * (1.0f / P_));
}

__global__ void embx_kernel(const int* __restrict__ captions,
                            const float* __restrict__ embed)
{
    int i = (blockIdx.x * 256 + threadIdx.x) * 4;
    if (i >= (T_ - 1) * B_ * E_) return;
    int r = i / E_, c = i % E_;
    int t = r / B_, b = r % B_;
    int cap = captions[b * T_ + t];
    cvt4(g_embX + i, embed + (size_t)cap * E_ + c);
}

// ============ gemm64: 64x128 tile, 256 thr (M=64 GEMMs) =====================
__device__ __forceinline__ void issue_tile64(
    const __half* __restrict__ A, int lda,
    const __half* __restrict__ B, int ldb,
    int bm, int bn, int N, int kt,
    __half* as, __half* bs, int tid)
{
#pragma unroll
    for (int i = 0; i < 2; i++) {
        int idx = i * 256 + tid;
        int r = idx >> 3, c8 = (idx & 7) * 8;
        uint32_t da = (uint32_t)__cvta_generic_to_shared(as + r * RS + c8);
        const __half* pa = A + (size_t)(bm + r) * lda + kt + c8;
        asm volatile("cp.async.cg.shared.global [%0], [%1], 16;" :: "r"(da), "l"(pa));
    }
#pragma unroll
    for (int i = 0; i < 4; i++) {
        int idx = i * 256 + tid;
        int r = idx >> 3, c8 = (idx & 7) * 8;
        int n = bn + r;
        uint32_t db = (uint32_t)__cvta_generic_to_shared(bs + r * RS + c8);
        const __half* pb = B + (size_t)(n < N ? n : 0) * ldb + kt + c8;
        int sz = (n < N) ? 16 : 0;
        asm volatile("cp.async.cg.shared.global [%0], [%1], 16, %2;" :: "r"(db), "l"(pb), "r"(sz));
    }
    asm volatile("cp.async.commit_group;");
}

// mode: 0 = fp32 split-K partials, 3 = h0c0 split
__device__ __forceinline__ void gemm_core64(
    const __half* __restrict__ A, int lda,
    const __half* __restrict__ Bm, int ldb,
    float* __restrict__ Cf, int ldc, int partStride, int N, int kChunk,
    int bm, int by, int z, int mode)
{
    extern __shared__ __half sm[];
    __half* Asm = sm;
    __half* Bsm = sm + STG64 * 64 * RS;

    const int tid = threadIdx.x;
    const int warp = tid >> 5, lane = tid & 31;
    const int wm = warp >> 2, wn = warp & 3;
    const int bn = by * 128;
    const int k0 = z * kChunk;
    const int nk = kChunk / BK;

    float acc[2][4][4];
#pragma unroll
    for (int i = 0; i < 2; i++)
#pragma unroll
        for (int j = 0; j < 4; j++)
#pragma unroll
            for (int q = 0; q < 4; q++) acc[i][j][q] = 0.f;

    const int a_row_l = (lane & 7) + ((lane >> 3) & 1) * 8;
    const int a_col_l = ((lane >> 4) & 1) * 8;
    const int b_row_l = (lane & 7) + ((lane >> 4) & 1) * 8;
    const int b_col_l = ((lane >> 3) & 1) * 8;

#pragma unroll
    for (int s = 0; s < STG64 - 1; s++) {
        if (s < nk) issue_tile64(A, lda, Bm, ldb, bm, bn, N, k0 + s * BK,
                                 Asm + s * 64 * RS, Bsm + s * 128 * RS, tid);
        else asm volatile("cp.async.commit_group;");
    }

    for (int i = 0; i < nk; i++) {
        asm volatile("cp.async.wait_group %0;" :: "n"(STG64 - 2));
        __syncthreads();

        int ntile = i + STG64 - 1;
        if (ntile < nk) {
            int slot = ntile % STG64;
            issue_tile64(A, lda, Bm, ldb, bm, bn, N, k0 + ntile * BK,
                         Asm + slot * 64 * RS, Bsm + slot * 128 * RS, tid);
        } else {
            asm volatile("cp.async.commit_group;");
        }

        const __half* at = Asm + (i % STG64) * 64 * RS;
        const __half* bt = Bsm + (i % STG64) * 128 * RS;

#pragma unroll
        for (int ks = 0; ks < 4; ks++) {
            uint32_t a[2][4], b[4][2];
#pragma unroll
            for (int mt = 0; mt < 2; mt++) {
                int row = wm * 32 + mt * 16 + a_row_l;
                int col = ks * 16 + a_col_l;
                uint32_t ad = (uint32_t)__cvta_generic_to_shared(at + row * RS + col);
                asm volatile("ldmatrix.sync.aligned.m8n8.x4.shared.b16 {%0,%1,%2,%3}, [%4];"
                             : "=r"(a[mt][0]), "=r"(a[mt][1]), "=r"(a[mt][2]), "=r"(a[mt][3])
                             : "r"(ad));
            }
#pragma unroll
            for (int ntp = 0; ntp < 2; ntp++) {
                int row = wn * 32 + ntp * 16 + b_row_l;
                int col = ks * 16 + b_col_l;
                uint32_t bd = (uint32_t)__cvta_generic_to_shared(bt + row * RS + col);
                asm volatile("ldmatrix.sync.aligned.m8n8.x4.shared.b16 {%0,%1,%2,%3}, [%4];"
                             : "=r"(b[2 * ntp][0]), "=r"(b[2 * ntp][1]),
                               "=r"(b[2 * ntp + 1][0]), "=r"(b[2 * ntp + 1][1])
                             : "r"(bd));
            }
#pragma unroll
            for (int mt = 0; mt < 2; mt++)
#pragma unroll
                for (int nt = 0; nt < 4; nt++)
                    asm volatile(
                        "mma.sync.aligned.m16n8k16.row.col.f32.f16.f16.f32 "
                        "{%0,%1,%2,%3}, {%4,%5,%6,%7}, {%8,%9}, {%0,%1,%2,%3};"
                        : "+f"(acc[mt][nt][0]), "+f"(acc[mt][nt][1]),
                          "+f"(acc[mt][nt][2]), "+f"(acc[mt][nt][3])
                        : "r"(a[mt][0]), "r"(a[mt][1]), "r"(a[mt][2]), "r"(a[mt][3]),
                          "r"(b[nt][0]), "r"(b[nt][1]));
        }
    }

    float* Cz = Cf + (size_t)z * partStride;
#pragma unroll
    for (int mt = 0; mt < 2; mt++) {
        int r0 = bm + wm * 32 + mt * 16 + (lane >> 2);
        int r1 = r0 + 8;
#pragma unroll
        for (int nt = 0; nt < 4; nt++) {
            int cg = bn + wn * 32 + nt * 8 + (lane & 3) * 2;
            float v00 = acc[mt][nt][0], v01 = acc[mt][nt][1];
            float v10 = acc[mt][nt][2], v11 = acc[mt][nt][3];
            if (mode == 3) {
#pragma unroll
                for (int e = 0; e < 2; e++) {
                    int c = cg + e;
                    float va = e ? v01 : v00, vb = e ? v11 : v10;
                    float bb = g_bh0c0[c];
                    if (c < 1024) {
                        g_hall[r0 * H_ + c] = __float2half(va + bb);
                        g_hall[r1 * H_ + c] = __float2half(vb + bb);
                    } else {
                        g_cbuf[r0 * H_ + c - 1024] = va + bb;
                        g_cbuf[r1 * H_ + c - 1024] = vb + bb;
                    }
                }
            } else {
                if (cg < N) {
                    Cz[(size_t)r0 * ldc + cg] = v00;
                    Cz[(size_t)r1 * ldc + cg] = v10;
                }
                if (cg + 1 < N) {
                    Cz[(size_t)r0 * ldc + cg + 1] = v01;
                    Cz[(size_t)r1 * ldc + cg + 1] = v11;
                }
            }
        }
    }
}

// ============ gemm128: 128x128 tile, 256 thr, warp-tile 32x64 ===============
__device__ __forceinline__ void issue_tile128(
    const __half* __restrict__ A, int lda,
    const __half* __restrict__ B, int ldb,
    int bm, int bn, int N, int kt,
    __half* as, __half* bs, int tid)
{
#pragma unroll
    for (int i = 0; i < 4; i++) {
        int idx = i * 256 + tid;
        int r = idx >> 3, c8 = (idx & 7) * 8;
        uint32_t da = (uint32_t)__cvta_generic_to_shared(as + r * RS + c8);
        const __half* pa = A + (size_t)(bm + r) * lda + kt + c8;
        asm volatile("cp.async.cg.shared.global [%0], [%1], 16;" :: "r"(da), "l"(pa));
    }
#pragma unroll
    for (int i = 0; i < 4; i++) {
        int idx = i * 256 + tid;
        int r = idx >> 3, c8 = (idx & 7) * 8;
        int n = bn + r;
        uint32_t db = (uint32_t)__cvta_generic_to_shared(bs + r * RS + c8);
        const __half* pb = B + (size_t)(n < N ? n : 0) * ldb + kt + c8;
        int sz = (n < N) ? 16 : 0;
        asm volatile("cp.async.cg.shared.global [%0], [%1], 16, %2;" :: "r"(db), "l"(pb), "r"(sz));
    }
    asm volatile("cp.async.commit_group;");
}

// mode: 1 = fp16 out (+bias), 2 = logits capmap (+bias)
__device__ __forceinline__ void gemm_core128(
    const __half* __restrict__ A, int lda,
    const __half* __restrict__ Bm, int ldb,
    const float* __restrict__ bias,
    float* __restrict__ Cf, __half* __restrict__ Ch,
    int ldc, int M, int N, int K,
    int bm, int by, int mode)
{
    extern __shared__ __half sm[];
    __half* Asm = sm;
    __half* Bsm = sm + STG128 * 128 * RS;

    const int tid = threadIdx.x;
    const int warp = tid >> 5, lane = tid & 31;
    const int wm = warp >> 1, wn = warp & 1;
    const int bn = by * 128;
    const int nk = K / BK;

    float acc[2][8][4];
#pragma unroll
    for (int i = 0; i < 2; i++)
#pragma unroll
        for (int j = 0; j < 8; j++)
#pragma unroll
            for (int q = 0; q < 4; q++) acc[i][j][q] = 0.f;

    const int a_row_l = (lane & 7) + ((lane >> 3) & 1) * 8;
    const int a_col_l = ((lane >> 4) & 1) * 8;
    const int b_row_l = (lane & 7) + ((lane >> 4) & 1) * 8;
    const int b_col_l = ((lane >> 3) & 1) * 8;

#pragma unroll
    for (int s = 0; s < STG128 - 1; s++) {
        if (s < nk) issue_tile128(A, lda, Bm, ldb, bm, bn, N, s * BK,
                                  Asm + s * 128 * RS, Bsm + s * 128 * RS, tid);
        else asm volatile("cp.async.commit_group;");
    }

    for (int i = 0; i < nk; i++) {
        asm volatile("cp.async.wait_group %0;" :: "n"(STG128 - 2));
        __syncthreads();

        int ntile = i + STG128 - 1;
        if (ntile < nk) {
            int slot = ntile % STG128;
            issue_tile128(A, lda, Bm, ldb, bm, bn, N, ntile * BK,
                          Asm + slot * 128 * RS, Bsm + slot * 128 * RS, tid);
        } else {
            asm volatile("cp.async.commit_group;");
        }

        const __half* at = Asm + (i % STG128) * 128 * RS;
        const __half* bt = Bsm + (i % STG128) * 128 * RS;

#pragma unroll
        for (int ks = 0; ks < 4; ks++) {
            uint32_t a[2][4], b[8][2];
#pragma unroll
            for (int mt = 0; mt < 2; mt++) {
                int row = wm * 32 + mt * 16 + a_row_l;
                int col = ks * 16 + a_col_l;
                uint32_t ad = (uint32_t)__cvta_generic_to_shared(at + row * RS + col);
                asm volatile("ldmatrix.sync.aligned.m8n8.x4.shared.b16 {%0,%1,%2,%3}, [%4];"
                             : "=r"(a[mt][0]), "=r"(a[mt][1]), "=r"(a[mt][2]), "=r"(a[mt][3])
                             : "r"(ad));
            }
#pragma unroll
            for (int ntp = 0; ntp < 4; ntp++) {
                int row = wn * 64 + ntp * 16 + b_row_l;
                int col = ks * 16 + b_col_l;
                uint32_t bd = (uint32_t)__cvta_generic_to_shared(bt + row * RS + col);
                asm volatile("ldmatrix.sync.aligned.m8n8.x4.shared.b16 {%0,%1,%2,%3}, [%4];"
                             : "=r"(b[2 * ntp][0]), "=r"(b[2 * ntp][1]),
                               "=r"(b[2 * ntp + 1][0]), "=r"(b[2 * ntp + 1][1])
                             : "r"(bd));
            }
#pragma unroll
            for (int mt = 0; mt < 2; mt++)
#pragma unroll
                for (int nt = 0; nt < 8; nt++)
                    asm volatile(
                        "mma.sync.aligned.m16n8k16.row.col.f32.f16.f16.f32 "
                        "{%0,%1,%2,%3}, {%4,%5,%6,%7}, {%8,%9}, {%0,%1,%2,%3};"
                        : "+f"(acc[mt][nt][0]), "+f"(acc[mt][nt][1]),
                          "+f"(acc[mt][nt][2]), "+f"(acc[mt][nt][3])
                        : "r"(a[mt][0]), "r"(a[mt][1]), "r"(a[mt][2]), "r"(a[mt][3]),
                          "r"(b[nt][0]), "r"(b[nt][1]));
        }
    }

#pragma unroll
    for (int mt = 0; mt < 2; mt++) {
        int r0 = bm + wm * 32 + mt * 16 + (lane >> 2);
        int r1 = r0 + 8;
#pragma unroll
        for (int nt = 0; nt < 8; nt++) {
            int cg = bn + wn * 64 + nt * 8 + (lane & 3) * 2;
            float bv0 = 0.f, bv1 = 0.f;
            if (bias) {
                if (cg < N) bv0 = bias[cg];
                if (cg + 1 < N) bv1 = bias[cg + 1];
            }
            float v00 = acc[mt][nt][0] + bv0, v01 = acc[mt][nt][1] + bv1;
            float v10 = acc[mt][nt][2] + bv0, v11 = acc[mt][nt][3] + bv1;
            if (mode == 2) {
                float* p0 = Cf + (size_t)(r0 & 63) * ((T_ - 1) * V_) + (size_t)(r0 >> 6) * V_;
                float* p1 = Cf + (size_t)(r1 & 63) * ((T_ - 1) * V_) + (size_t)(r1 >> 6) * V_;
                if (cg < N) {
                    if (r0 < M) p0[cg] = v00;
                    if (r1 < M) p1[cg] = v10;
                }
                if (cg + 1 < N) {
                    if (r0 < M) p0[cg + 1] = v01;
                    if (r1 < M) p1[cg + 1] = v11;
                }
            } else {
                if (cg < N) {
                    if (r0 < M) Ch[(size_t)r0 * ldc + cg] = __float2half(v00);
                    if (r1 < M) Ch[(size_t)r1 * ldc + cg] = __float2half(v10);
                }
                if (cg + 1 < N) {
                    if (r0 < M) Ch[(size_t)r0 * ldc + cg + 1] = __float2half(v01);
                    if (r1 < M) Ch[(size_t)r1 * ldc + cg + 1] = __float2half(v11);
                }
            }
        }
    }
}

// setup: h0c0 [16] + att1 [100] + gatesX [384] + encW [800] = 1300 blocks
#define CB0 16
#define CB1 (CB0 + 25 * 4)
#define CB2 (CB1 + 12 * 32)
#define CB3 (CB2 + 25 * 32)

__global__ void __launch_bounds__(256)
setup_combo(const float* __restrict__ b_eatt)
{
    int bi = blockIdx.x;
    if (bi < CB0) {
        gemm_core64(g_meanh, ENC_, g_Wh0c0, ENC_, nullptr,
                    0, 0, 2048, ENC_, 0, bi, 0, 3);
    } else if (bi < CB1) {
        int i = bi - CB0;
        gemm_core128(g_ench, ENC_, g_Weatt, ENC_, b_eatt, nullptr, g_att1h,
                     A_, B_ * P_, A_, ENC_, (i % 25) * 128, i / 25, 1);
    } else if (bi < CB2) {
        int i = bi - CB1;
        gemm_core128(g_embX, E_, g_Wihx, E_, nullptr, nullptr, g_gatesX,
                     G4_, (T_ - 1) * B_, G4_, E_, (i % 12) * 128, i / 12, 1);
    } else {
        int i = bi - CB2;
        gemm_core128(g_ench, ENC_, g_Wihc, ENC_, nullptr, nullptr, g_encW,
                     G4_, B_ * P_, G4_, ENC_, (i % 25) * 128, i / 25, 1);
    }
}

// per-step fused GEMM: h_t @ [W_hh | W_datt]^T -> ghp partials (split-K 8)
__global__ void __launch_bounds__(256)
hw_kernel(const __half* __restrict__ h)
{
    gemm_core64(h, H_, g_Wcat, H_, g_ghp,
                NCAT, B_ * NCAT, NCAT, H_ / 8, 0, blockIdx.x, blockIdx.y, 0);
}

// batched logits: M=1536, N=10000, K=1024 — grid (12, 79)
__global__ void __launch_bounds__(256)
logits_kernel(const float* __restrict__ b_out, float* __restrict__ out)
{
    gemm_core128(g_hall + B_ * H_, H_, g_Wout, H_, b_out, out, nullptr,
                 0, 1536, V_, H_, blockIdx.x * 128, blockIdx.y, 2);
}

// ---------------- gate+LSTM: 4 stripes x 64 b = 256 blocks ------------------
__global__ void __launch_bounds__(256)
gatelstm_kernel(const float* __restrict__ b_datt,
                const float* __restrict__ W_fatt,
                const float* __restrict__ b_fatt,
                int t)
{
    const int z = blockIdx.x;
    const int b = blockIdx.y;
    const int tid = threadIdx.x;
    const int warp = tid >> 5, lane = tid & 31;

    __shared__ float att2s[A_];
    __shared__ float alpha[P_];

    for (int a = tid; a < A_; a += 256) {
        float s = b_datt[a];
#pragma unroll
        for (int zz = 0; zz < 8; zz++)
            s += g_ghp[(size_t)zz * B_ * NCAT + b * NCAT + G4_ + a];
        att2s[a] = s;
    }
    __syncthreads();

    const __half* att1b = g_att1h + (size_t)b * P_ * A_;
#pragma unroll 7
    for (int p = warp; p < P_; p += 8) {
        float s = 0.f;
#pragma unroll
        for (int a = lane; a < A_; a += 32) {
            float v = __half2float(att1b[p * A_ + a]) + att2s[a];
            s += fmaxf(v, 0.f) * W_fatt[a];
        }
#pragma unroll
        for (int o = 16; o; o >>= 1) s += __shfl_xor_sync(0xffffffffu, s, o);
        if (lane == 0) alpha[p] = s + b_fatt[0];
    }
    __syncthreads();

    if (warp == 0) {
        float v0 = (lane < P_) ? alpha[lane] : -1e30f;
        float v1 = (lane + 32 < P_) ? alpha[lane + 32] : -1e30f;
        float m = fmaxf(v0, v1);
#pragma unroll
        for (int o = 16; o; o >>= 1) m = fmaxf(m, __shfl_xor_sync(0xffffffffu, m, o));
        float e0 = (lane < P_) ? __expf(v0 - m) : 0.f;
        float e1 = (lane + 32 < P_) ? __expf(v1 - m) : 0.f;
        float s = e0 + e1;
#pragma unroll
        for (int o = 16; o; o >>= 1) s += __shfl_xor_sync(0xffffffffu, s, o);
        float inv = 1.0f / s;
        if (lane < P_) alpha[lane] = e0 * inv;
        if (lane + 32 < P_) alpha[lane + 32] = e1 * inv;
    }
    __syncthreads();

    const int j = z * 256 + tid;
    const __half* encWb = g_encW + (size_t)b * P_ * G4_;
    float gi = 0.f, gf = 0.f, gg = 0.f, go = 0.f;
#pragma unroll 7
    for (int p = 0; p < P_; p++) {
        const __half* row = encWb + (size_t)p * G4_;
        float ap = alpha[p];
        gi += ap * __half2float(row[j]);
        gf += ap * __half2float(row[H_ + j]);
        gg += ap * __half2float(row[2 * H_ + j]);
        go += ap * __half2float(row[3 * H_ + j]);
    }
    const __half* gx = g_gatesX + ((size_t)t * B_ + b) * G4_;
    gi += __half2float(gx[j])          + g_bsum[j];
    gf += __half2float(gx[H_ + j])     + g_bsum[H_ + j];
    gg += __half2float(gx[2 * H_ + j]) + g_bsum[2 * H_ + j];
    go += __half2float(gx[3 * H_ + j]) + g_bsum[3 * H_ + j];
#pragma unroll
    for (int zz = 0; zz < 8; zz++) {
        const float* gp = g_ghp + (size_t)zz * B_ * NCAT + b * NCAT;
        gi += gp[j]; gf += gp[H_ + j]; gg += gp[2 * H_ + j]; go += gp[3 * H_ + j];
    }

    const float* c_cur = g_cbuf + (t & 1) * B_ * H_;
    float* c_nxt = g_cbuf + ((t + 1) & 1) * B_ * H_;
    __half* h_nxt = g_hall + (size_t)(t + 1) * B_ * H_;
    float si = 1.f / (1.f + __expf(-gi));
    float sf = 1.f / (1.f + __expf(-gf));
    float so = 1.f / (1.f + __expf(-go));
    float tg = tanhf(gg);
    float c  = sf * c_cur[b * H_ + j] + si * tg;
    c_nxt[b * H_ + j] = c;
    h_nxt[b * H_ + j] = __float2half(so * tanhf(c));
}

// ---------------- host ----------------
extern "C" void kernel_launch(void* const* d_in, const int* in_sizes, int n_in,
                              void* d_out, int out_size)
{
    const float* enc    = (const float*)d_in[0];
    const int*   caps   = (const int*)  d_in[1];
    const float* embed  = (const float*)d_in[2];
    const float* W_eatt = (const float*)d_in[3];
    const float* b_eatt = (const float*)d_in[4];
    const float* W_datt = (const float*)d_in[5];
    const float* b_datt = (const float*)d_in[6];
    const float* W_fatt = (const float*)d_in[7];
    const float* b_fatt = (const float*)d_in[8];
    const float* W_ih   = (const float*)d_in[9];
    const float* b_ih   = (const float*)d_in[10];
    const float* W_hh   = (const float*)d_in[11];
    const float* b_hh   = (const float*)d_in[12];
    const float* W_h0   = (const float*)d_in[13];
    const float* b_h0   = (const float*)d_in[14];
    const float* W_c0   = (const float*)d_in[15];
    const float* b_c0   = (const float*)d_in[16];
    const float* W_out  = (const float*)d_in[17];
    const float* b_out  = (const float*)d_in[18];
    float* out = (float*)d_out;

    cudaFuncSetAttribute(setup_combo, cudaFuncAttributeMaxDynamicSharedMemorySize, SMEM_BYTES);
    cudaFuncSetAttribute(hw_kernel, cudaFuncAttributeMaxDynamicSharedMemorySize, SMEM_BYTES);
    cudaFuncSetAttribute(logits_kernel, cudaFuncAttributeMaxDynamicSharedMemorySize, SMEM_BYTES);

    void* hall_p = nullptr;
    cudaGetSymbolAddress(&hall_p, g_hall);
    __half* hall = (__half*)hall_p;

    // ---- one-time setup ----
    mean_kernel<<<(B_ * ENC_ + 255) / 256, 256>>>(enc);
    cvt_all<<<(T8 / 4 + 255) / 256, 256>>>(W_out, W_eatt, W_h0, W_c0, enc, W_ih, W_hh,
                                           W_datt, b_h0, b_c0, b_ih, b_hh);
    embx_kernel<<<((T_ - 1) * B_ * E_ / 4 + 255) / 256, 256>>>(caps, embed);

    setup_combo<<<CB3, 256, SMEM_BYTES>>>(b_eatt);

    // ---- recurrent loop: 2 launches per step ----
    for (int t = 0; t < T_ - 1; t++) {
        hw_kernel<<<dim3(NCAT / 128, 8, 1), 256, SMEM_BYTES>>>(hall + (size_t)t * B_ * H_);
        gatelstm_kernel<<<dim3(4, B_, 1), 256>>>(b_datt, W_fatt, b_fatt, t);
    }

    // ---- batched logits: grid (12, ceil(10000/128)=79) ----
    logits_kernel<<<dim3(12, (V_ + 127) / 128, 1), 256, SMEM_BYTES>>>(b_out, out);
}

// round 11
// speedup vs baseline: 2.2039x; 1.0272x over previous
#include <cuda_runtime.h>
#include <cuda_fp16.h>
#include <cstdint>

#define B_    64
#define P_    49
#define ENC_  1280
#define T_    25
#define V_    10000
#define E_    512
#define H_    1024
#define A_    512
#define G4_   4096
#define NCAT  4608           /* 4*H + A */
#define WIH_LD 1792

#define BK 64
#define STG64  4
#define STG128 3
#define SMEM_BYTES 98304     /* = 4*(64+128)*64*2 = 3*(128+128)*64*2 */

// swizzled smem offset (halves): row r, 16B-chunk c (0..7)
__device__ __forceinline__ int sw(int r, int c) {
    return r * 64 + (((c ^ r) & 7) << 3) + ((c & ~7) << 3);
}

// ---------------- static scratch ----------------
__device__ __align__(16) __half g_Wout [V_ * H_];
__device__ __align__(16) __half g_Weatt[A_ * ENC_];
__device__ __align__(16) __half g_Wh0c0[2048 * ENC_];
__device__ __align__(16) __half g_Wihx [G4_ * E_];
__device__ __align__(16) __half g_Wihc [G4_ * ENC_];
__device__ __align__(16) __half g_Wcat [NCAT * H_];
__device__ __align__(16) __half g_ench [(B_ * P_ + 64) * ENC_];   /* +64 pad rows */
__device__ __align__(16) __half g_meanh[B_ * ENC_];
__device__ __align__(16) __half g_embX [(T_ - 1) * B_ * E_];
__device__ __align__(16) __half g_hall [T_ * B_ * H_];
__device__ __align__(16) __half g_encW [B_ * P_ * G4_];
__device__ __align__(16) __half g_gatesX[(T_ - 1) * B_ * G4_];
__device__ __align__(16) __half g_att1h[B_ * P_ * A_];
__device__ __align__(16) float  g_cbuf [2 * B_ * H_];
__device__ __align__(16) float  g_ghp  [8 * B_ * NCAT];
__device__ __align__(16) float  g_bh0c0[2048];
__device__ __align__(16) float  g_bsum [G4_];

// ---------------- setup conversions (4 elems / thread) ----------------
#define T0 (V_ * H_)
#define T1 (T0 + A_ * ENC_)
#define T2 (T1 + 2048 * ENC_)
#define T3 (T2 + B_ * P_ * ENC_)
#define T4 (T3 + G4_ * E_)
#define T5 (T4 + G4_ * ENC_)
#define T6 (T5 + NCAT * H_)
#define T7 (T6 + 2048)
#define T8 (T7 + G4_)

__device__ __forceinline__ void cvt4(__half* d, const float* s) {
    float4 v = *(const float4*)s;
    __half2* d2 = (__half2*)d;
    d2[0] = __floats2half2_rn(v.x, v.y);
    d2[1] = __floats2half2_rn(v.z, v.w);
}

__global__ void cvt_all(const float* __restrict__ Wo, const float* __restrict__ We,
                        const float* __restrict__ Wh0, const float* __restrict__ Wc0,
                        const float* __restrict__ enc, const float* __restrict__ Wih,
                        const float* __restrict__ Whh, const float* __restrict__ Wd,
                        const float* __restrict__ bh0, const float* __restrict__ bc0,
                        const float* __restrict__ bih, const float* __restrict__ bhh)
{
    int i = (blockIdx.x * 256 + threadIdx.x) * 4;
    if (i >= T8) return;
    if (i < T0) { cvt4(g_Wout + i, Wo + i); return; }
    if (i < T1) { cvt4(g_Weatt + (i - T0), We + (i - T0)); return; }
    if (i < T2) {
        int j = i - T1; int r = j / ENC_, c = j % ENC_;
        cvt4(g_Wh0c0 + j, (r < 1024 ? Wh0 + (size_t)r * ENC_ : Wc0 + (size_t)(r - 1024) * ENC_) + c);
        return;
    }
    if (i < T3) { cvt4(g_ench + (i - T2), enc + (i - T2)); return; }
    if (i < T4) {
        int j = i - T3; int r = j / E_, c = j % E_;
        cvt4(g_Wihx + j, Wih + (size_t)r * WIH_LD + c);
        return;
    }
    if (i < T5) {
        int j = i - T4; int r = j / ENC_, c = j % ENC_;
        cvt4(g_Wihc + j, Wih + (size_t)r * WIH_LD + E_ + c);
        return;
    }
    if (i < T6) {
        int j = i - T5; int r = j / H_, c = j % H_;
        cvt4(g_Wcat + j, (r < G4_ ? Whh + (size_t)r * H_ : Wd + (size_t)(r - G4_) * H_) + c);
        return;
    }
    if (i < T7) {
        int j = i - T6;
        *(float4*)(g_bh0c0 + j) = (j < 1024) ? *(const float4*)(bh0 + j)
                                             : *(const float4*)(bc0 + (j - 1024));
        return;
    }
    int j = i - T7;
    float4 a = *(const float4*)(bih + j), bv = *(const float4*)(bhh + j);
    *(float4*)(g_bsum + j) = make_float4(a.x + bv.x, a.y + bv.y, a.z + bv.z, a.w + bv.w);
}

__global__ void mean_kernel(const float* __restrict__ enc) {
    int i = blockIdx.x * blockDim.x + threadIdx.x;
    if (i >= B_ * ENC_) return;
    int b = i / ENC_, e = i % ENC_;
    const float* p = enc + (size_t)b * P_ * ENC_ + e;
    float s = 0.f;
#pragma unroll 7
    for (int k = 0; k < P_; k++) s += p[k * ENC_];
    g_meanh[i] = __float2half(s * (1.0f / P_));
}

__global__ void embx_kernel(const int* __restrict__ captions,
                            const float* __restrict__ embed)
{
    int i = (blockIdx.x * 256 + threadIdx.x) * 4;
    if (i >= (T_ - 1) * B_ * E_) return;
    int r = i / E_, c = i % E_;
    int t = r / B_, b = r % B_;
    int cap = captions[b * T_ + t];
    cvt4(g_embX + i, embed + (size_t)cap * E_ + c);
}

// ============ gemm64: 64x128 tile, 256 thr (M=64 GEMMs) =====================
__device__ __forceinline__ void issue_tile64(
    const __half* __restrict__ A, int lda,
    const __half* __restrict__ B, int ldb,
    int bm, int bn, int N, int kt,
    __half* as, __half* bs, int tid)
{
#pragma unroll
    for (int i = 0; i < 2; i++) {
        int idx = i * 256 + tid;
        int r = idx >> 3, c = idx & 7;
        uint32_t da = (uint32_t)__cvta_generic_to_shared(as + sw(r, c));
        const __half* pa = A + (size_t)(bm + r) * lda + kt + c * 8;
        asm volatile("cp.async.cg.shared.global [%0], [%1], 16;" :: "r"(da), "l"(pa));
    }
#pragma unroll
    for (int i = 0; i < 4; i++) {
        int idx = i * 256 + tid;
        int r = idx >> 3, c = idx & 7;
        int n = bn + r;
        uint32_t db = (uint32_t)__cvta_generic_to_shared(bs + sw(r, c));
        const __half* pb = B + (size_t)(n < N ? n : 0) * ldb + kt + c * 8;
        int sz = (n < N) ? 16 : 0;
        asm volatile("cp.async.cg.shared.global [%0], [%1], 16, %2;" :: "r"(db), "l"(pb), "r"(sz));
    }
    asm volatile("cp.async.commit_group;");
}

// mode: 0 = fp32 split-K partials, 3 = h0c0 split
__device__ __forceinline__ void gemm_core64(
    const __half* __restrict__ A, int lda,
    const __half* __restrict__ Bm, int ldb,
    float* __restrict__ Cf, int ldc, int partStride, int N, int kChunk,
    int bm, int by, int z, int mode)
{
    extern __shared__ __half sm[];
    __half* Asm = sm;
    __half* Bsm = sm + STG64 * 64 * 64;

    const int tid = threadIdx.x;
    const int warp = tid >> 5, lane = tid & 31;
    const int wm = warp >> 2, wn = warp & 3;
    const int bn = by * 128;
    const int k0 = z * kChunk;
    const int nk = kChunk / BK;

    float acc[2][4][4];
#pragma unroll
    for (int i = 0; i < 2; i++)
#pragma unroll
        for (int j = 0; j < 4; j++)
#pragma unroll
            for (int q = 0; q < 4; q++) acc[i][j][q] = 0.f;

    const int a_row_l = (lane & 7) + ((lane >> 3) & 1) * 8;
    const int a_chk_l = (lane >> 4) & 1;
    const int b_row_l = (lane & 7) + ((lane >> 4) & 1) * 8;
    const int b_chk_l = (lane >> 3) & 1;

#pragma unroll
    for (int s = 0; s < STG64 - 1; s++) {
        if (s < nk) issue_tile64(A, lda, Bm, ldb, bm, bn, N, k0 + s * BK,
                                 Asm + s * 64 * 64, Bsm + s * 128 * 64, tid);
        else asm volatile("cp.async.commit_group;");
    }

    for (int i = 0; i < nk; i++) {
        asm volatile("cp.async.wait_group %0;" :: "n"(STG64 - 2));
        __syncthreads();

        int ntile = i + STG64 - 1;
        if (ntile < nk) {
            int slot = ntile % STG64;
            issue_tile64(A, lda, Bm, ldb, bm, bn, N, k0 + ntile * BK,
                         Asm + slot * 64 * 64, Bsm + slot * 128 * 64, tid);
        } else {
            asm volatile("cp.async.commit_group;");
        }

        const __half* at = Asm + (i % STG64) * 64 * 64;
        const __half* bt = Bsm + (i % STG64) * 128 * 64;

#pragma unroll
        for (int ks = 0; ks < 4; ks++) {
            uint32_t a[2][4], b[4][2];
#pragma unroll
            for (int mt = 0; mt < 2; mt++) {
                int row = wm * 32 + mt * 16 + a_row_l;
                uint32_t ad = (uint32_t)__cvta_generic_to_shared(at + sw(row, ks * 2 + a_chk_l));
                asm volatile("ldmatrix.sync.aligned.m8n8.x4.shared.b16 {%0,%1,%2,%3}, [%4];"
                             : "=r"(a[mt][0]), "=r"(a[mt][1]), "=r"(a[mt][2]), "=r"(a[mt][3])
                             : "r"(ad));
            }
#pragma unroll
            for (int ntp = 0; ntp < 2; ntp++) {
                int row = wn * 32 + ntp * 16 + b_row_l;
                uint32_t bd = (uint32_t)__cvta_generic_to_shared(bt + sw(row, ks * 2 + b_chk_l));
                asm volatile("ldmatrix.sync.aligned.m8n8.x4.shared.b16 {%0,%1,%2,%3}, [%4];"
                             : "=r"(b[2 * ntp][0]), "=r"(b[2 * ntp][1]),
                               "=r"(b[2 * ntp + 1][0]), "=r"(b[2 * ntp + 1][1])
                             : "r"(bd));
            }
#pragma unroll
            for (int mt = 0; mt < 2; mt++)
#pragma unroll
                for (int nt = 0; nt < 4; nt++)
                    asm volatile(
                        "mma.sync.aligned.m16n8k16.row.col.f32.f16.f16.f32 "
                        "{%0,%1,%2,%3}, {%4,%5,%6,%7}, {%8,%9}, {%0,%1,%2,%3};"
                        : "+f"(acc[mt][nt][0]), "+f"(acc[mt][nt][1]),
                          "+f"(acc[mt][nt][2]), "+f"(acc[mt][nt][3])
                        : "r"(a[mt][0]), "r"(a[mt][1]), "r"(a[mt][2]), "r"(a[mt][3]),
                          "r"(b[nt][0]), "r"(b[nt][1]));
        }
    }

    float* Cz = Cf + (size_t)z * partStride;
#pragma unroll
    for (int mt = 0; mt < 2; mt++) {
        int r0 = bm + wm * 32 + mt * 16 + (lane >> 2);
        int r1 = r0 + 8;
#pragma unroll
        for (int nt = 0; nt < 4; nt++) {
            int cg = bn + wn * 32 + nt * 8 + (lane & 3) * 2;
            float v00 = acc[mt][nt][0], v01 = acc[mt][nt][1];
            float v10 = acc[mt][nt][2], v11 = acc[mt][nt][3];
            if (mode == 3) {
#pragma unroll
                for (int e = 0; e < 2; e++) {
                    int c = cg + e;
                    float va = e ? v01 : v00, vb = e ? v11 : v10;
                    float bb = g_bh0c0[c];
                    if (c < 1024) {
                        g_hall[r0 * H_ + c] = __float2half(va + bb);
                        g_hall[r1 * H_ + c] = __float2half(vb + bb);
                    } else {
                        g_cbuf[r0 * H_ + c - 1024] = va + bb;
                        g_cbuf[r1 * H_ + c - 1024] = vb + bb;
                    }
                }
            } else {
                if (cg < N) {
                    Cz[(size_t)r0 * ldc + cg] = v00;
                    Cz[(size_t)r1 * ldc + cg] = v10;
                }
                if (cg + 1 < N) {
                    Cz[(size_t)r0 * ldc + cg + 1] = v01;
                    Cz[(size_t)r1 * ldc + cg + 1] = v11;
                }
            }
        }
    }
}

// ============ gemm128: 128x128 tile, 256 thr, warp-tile 32x64 ===============
__device__ __forceinline__ void issue_tile128(
    const __half* __restrict__ A, int lda,
    const __half* __restrict__ B, int ldb,
    int bm, int bn, int N, int kt,
    __half* as, __half* bs, int tid)
{
#pragma unroll
    for (int i = 0; i < 4; i++) {
        int idx = i * 256 + tid;
        int r = idx >> 3, c = idx & 7;
        uint32_t da = (uint32_t)__cvta_generic_to_shared(as + sw(r, c));
        const __half* pa = A + (size_t)(bm + r) * lda + kt + c * 8;
        asm volatile("cp.async.cg.shared.global [%0], [%1], 16;" :: "r"(da), "l"(pa));
    }
#pragma unroll
    for (int i = 0; i < 4; i++) {
        int idx = i * 256 + tid;
        int r = idx >> 3, c = idx & 7;
        int n = bn + r;
        uint32_t db = (uint32_t)__cvta_generic_to_shared(bs + sw(r, c));
        const __half* pb = B + (size_t)(n < N ? n : 0) * ldb + kt + c * 8;
        int sz = (n < N) ? 16 : 0;
        asm volatile("cp.async.cg.shared.global [%0], [%1], 16, %2;" :: "r"(db), "l"(pb), "r"(sz));
    }
    asm volatile("cp.async.commit_group;");
}

// mode: 1 = fp16 out (+bias), 2 = logits capmap (+bias)
__device__ __forceinline__ void gemm_core128(
    const __half* __restrict__ A, int lda,
    const __half* __restrict__ Bm, int ldb,
    const float* __restrict__ bias,
    float* __restrict__ Cf, __half* __restrict__ Ch,
    int ldc, int M, int N, int K,
    int bm, int by, int mode)
{
    extern __shared__ __half sm[];
    __half* Asm = sm;
    __half* Bsm = sm + STG128 * 128 * 64;

    const int tid = threadIdx.x;
    const int warp = tid >> 5, lane = tid & 31;
    const int wm = warp >> 1, wn = warp & 1;
    const int bn = by * 128;
    const int nk = K / BK;

    float acc[2][8][4];
#pragma unroll
    for (int i = 0; i < 2; i++)
#pragma unroll
        for (int j = 0; j < 8; j++)
#pragma unroll
            for (int q = 0; q < 4; q++) acc[i][j][q] = 0.f;

    const int a_row_l = (lane & 7) + ((lane >> 3) & 1) * 8;
    const int a_chk_l = (lane >> 4) & 1;
    const int b_row_l = (lane & 7) + ((lane >> 4) & 1) * 8;
    const int b_chk_l = (lane >> 3) & 1;

#pragma unroll
    for (int s = 0; s < STG128 - 1; s++) {
        if (s < nk) issue_tile128(A, lda, Bm, ldb, bm, bn, N, s * BK,
                                  Asm + s * 128 * 64, Bsm + s * 128 * 64, tid);
        else asm volatile("cp.async.commit_group;");
    }

    for (int i = 0; i < nk; i++) {
        asm volatile("cp.async.wait_group %0;" :: "n"(STG128 - 2));
        __syncthreads();

        int ntile = i + STG128 - 1;
        if (ntile < nk) {
            int slot = ntile % STG128;
            issue_tile128(A, lda, Bm, ldb, bm, bn, N, ntile * BK,
                          Asm + slot * 128 * 64, Bsm + slot * 128 * 64, tid);
        } else {
            asm volatile("cp.async.commit_group;");
        }

        const __half* at = Asm + (i % STG128) * 128 * 64;
        const __half* bt = Bsm + (i % STG128) * 128 * 64;

#pragma unroll
        for (int ks = 0; ks < 4; ks++) {
            uint32_t a[2][4], b[8][2];
#pragma unroll
            for (int mt = 0; mt < 2; mt++) {
                int row = wm * 32 + mt * 16 + a_row_l;
                uint32_t ad = (uint32_t)__cvta_generic_to_shared(at + sw(row, ks * 2 + a_chk_l));
                asm volatile("ldmatrix.sync.aligned.m8n8.x4.shared.b16 {%0,%1,%2,%3}, [%4];"
                             : "=r"(a[mt][0]), "=r"(a[mt][1]), "=r"(a[mt][2]), "=r"(a[mt][3])
                             : "r"(ad));
            }
#pragma unroll
            for (int ntp = 0; ntp < 4; ntp++) {
                int row = wn * 64 + ntp * 16 + b_row_l;
                uint32_t bd = (uint32_t)__cvta_generic_to_shared(bt + sw(row, ks * 2 + b_chk_l));
                asm volatile("ldmatrix.sync.aligned.m8n8.x4.shared.b16 {%0,%1,%2,%3}, [%4];"
                             : "=r"(b[2 * ntp][0]), "=r"(b[2 * ntp][1]),
                               "=r"(b[2 * ntp + 1][0]), "=r"(b[2 * ntp + 1][1])
                             : "r"(bd));
            }
#pragma unroll
            for (int mt = 0; mt < 2; mt++)
#pragma unroll
                for (int nt = 0; nt < 8; nt++)
                    asm volatile(
                        "mma.sync.aligned.m16n8k16.row.col.f32.f16.f16.f32 "
                        "{%0,%1,%2,%3}, {%4,%5,%6,%7}, {%8,%9}, {%0,%1,%2,%3};"
                        : "+f"(acc[mt][nt][0]), "+f"(acc[mt][nt][1]),
                          "+f"(acc[mt][nt][2]), "+f"(acc[mt][nt][3])
                        : "r"(a[mt][0]), "r"(a[mt][1]), "r"(a[mt][2]), "r"(a[mt][3]),
                          "r"(b[nt][0]), "r"(b[nt][1]));
        }
    }

#pragma unroll
    for (int mt = 0; mt < 2; mt++) {
        int r0 = bm + wm * 32 + mt * 16 + (lane >> 2);
        int r1 = r0 + 8;
#pragma unroll
        for (int nt = 0; nt < 8; nt++) {
            int cg = bn + wn * 64 + nt * 8 + (lane & 3) * 2;
            float bv0 = 0.f, bv1 = 0.f;
            if (bias) {
                if (cg < N) bv0 = bias[cg];
                if (cg + 1 < N) bv1 = bias[cg + 1];
            }
            float v00 = acc[mt][nt][0] + bv0, v01 = acc[mt][nt][1] + bv1;
            float v10 = acc[mt][nt][2] + bv0, v11 = acc[mt][nt][3] + bv1;
            if (mode == 2) {
                float* p0 = Cf + (size_t)(r0 & 63) * ((T_ - 1) * V_) + (size_t)(r0 >> 6) * V_;
                float* p1 = Cf + (size_t)(r1 & 63) * ((T_ - 1) * V_) + (size_t)(r1 >> 6) * V_;
                if (cg < N) {
                    if (r0 < M) p0[cg] = v00;
                    if (r1 < M) p1[cg] = v10;
                }
                if (cg + 1 < N) {
                    if (r0 < M) p0[cg + 1] = v01;
                    if (r1 < M) p1[cg + 1] = v11;
                }
            } else {
                if (cg < N) {
                    if (r0 < M) Ch[(size_t)r0 * ldc + cg] = __float2half(v00);
                    if (r1 < M) Ch[(size_t)r1 * ldc + cg] = __float2half(v10);
                }
                if (cg + 1 < N) {
                    if (r0 < M) Ch[(size_t)r0 * ldc + cg + 1] = __float2half(v01);
                    if (r1 < M) Ch[(size_t)r1 * ldc + cg + 1] = __float2half(v11);
                }
            }
        }
    }
}

// setup: h0c0 [16] + att1 [100] + gatesX [384] + encW [800] = 1300 blocks
#define CB0 16
#define CB1 (CB0 + 25 * 4)
#define CB2 (CB1 + 12 * 32)
#define CB3 (CB2 + 25 * 32)

__global__ void __launch_bounds__(256)
setup_combo(const float* __restrict__ b_eatt)
{
    int bi = blockIdx.x;
    if (bi < CB0) {
        gemm_core64(g_meanh, ENC_, g_Wh0c0, ENC_, nullptr,
                    0, 0, 2048, ENC_, 0, bi, 0, 3);
    } else if (bi < CB1) {
        int i = bi - CB0;
        gemm_core128(g_ench, ENC_, g_Weatt, ENC_, b_eatt, nullptr, g_att1h,
                     A_, B_ * P_, A_, ENC_, (i % 25) * 128, i / 25, 1);
    } else if (bi < CB2) {
        int i = bi - CB1;
        gemm_core128(g_embX, E_, g_Wihx, E_, nullptr, nullptr, g_gatesX,
                     G4_, (T_ - 1) * B_, G4_, E_, (i % 12) * 128, i / 12, 1);
    } else {
        int i = bi - CB2;
        gemm_core128(g_ench, ENC_, g_Wihc, ENC_, nullptr, nullptr, g_encW,
                     G4_, B_ * P_, G4_, ENC_, (i % 25) * 128, i / 25, 1);
    }
}

// per-step fused GEMM: h_t @ [W_hh | W_datt]^T -> ghp partials (split-K 8)
__global__ void __launch_bounds__(256)
hw_kernel(const __half* __restrict__ h)
{
    gemm_core64(h, H_, g_Wcat, H_, g_ghp,
                NCAT, B_ * NCAT, NCAT, H_ / 8, 0, blockIdx.x, blockIdx.y, 0);
}

// batched logits: M=1536, N=10000, K=1024 — grid (12, 79)
__global__ void __launch_bounds__(256)
logits_kernel(const float* __restrict__ b_out, float* __restrict__ out)
{
    gemm_core128(g_hall + B_ * H_, H_, g_Wout, H_, b_out, out, nullptr,
                 0, 1536, V_, H_, blockIdx.x * 128, blockIdx.y, 2);
}

// ---------------- gate+LSTM: 4 stripes x 64 b = 256 blocks ------------------
__global__ void __launch_bounds__(256)
gatelstm_kernel(const float* __restrict__ b_datt,
                const float* __restrict__ W_fatt,
                const float* __restrict__ b_fatt,
                int t)
{
    const int z = blockIdx.x;
    const int b = blockIdx.y;
    const int tid = threadIdx.x;
    const int warp = tid >> 5, lane = tid & 31;

    __shared__ float att2s[A_];
    __shared__ float alpha[P_];

    for (int a = tid; a < A_; a += 256) {
        float s = b_datt[a];
#pragma unroll
        for (int zz = 0; zz < 8; zz++)
            s += g_ghp[(size_t)zz * B_ * NCAT + b * NCAT + G4_ + a];
        att2s[a] = s;
    }
    __syncthreads();

    const __half* att1b = g_att1h + (size_t)b * P_ * A_;
#pragma unroll 7
    for (int p = warp; p < P_; p += 8) {
        float s = 0.f;
#pragma unroll
        for (int a = lane; a < A_; a += 32) {
            float v = __half2float(att1b[p * A_ + a]) + att2s[a];
            s += fmaxf(v, 0.f) * W_fatt[a];
        }
#pragma unroll
        for (int o = 16; o; o >>= 1) s += __shfl_xor_sync(0xffffffffu, s, o);
        if (lane == 0) alpha[p] = s + b_fatt[0];
    }
    __syncthreads();

    if (warp == 0) {
        float v0 = (lane < P_) ? alpha[lane] : -1e30f;
        float v1 = (lane + 32 < P_) ? alpha[lane + 32] : -1e30f;
        float m = fmaxf(v0, v1);
#pragma unroll
        for (int o = 16; o; o >>= 1) m = fmaxf(m, __shfl_xor_sync(0xffffffffu, m, o));
        float e0 = (lane < P_) ? __expf(v0 - m) : 0.f;
        float e1 = (lane + 32 < P_) ? __expf(v1 - m) : 0.f;
        float s = e0 + e1;
#pragma unroll
        for (int o = 16; o; o >>= 1) s += __shfl_xor_sync(0xffffffffu, s, o);
        float inv = 1.0f / s;
        if (lane < P_) alpha[lane] = e0 * inv;
        if (lane + 32 < P_) alpha[lane + 32] = e1 * inv;
    }
    __syncthreads();

    const int j = z * 256 + tid;
    const __half* encWb = g_encW + (size_t)b * P_ * G4_;
    float gi = 0.f, gf = 0.f, gg = 0.f, go = 0.f;
#pragma unroll 7
    for (int p = 0; p < P_; p++) {
        const __half* row = encWb + (size_t)p * G4_;
        float ap = alpha[p];
        gi += ap * __half2float(row[j]);
        gf += ap * __half2float(row[H_ + j]);
        gg += ap * __half2float(row[2 * H_ + j]);
        go += ap * __half2float(row[3 * H_ + j]);
    }
    const __half* gx = g_gatesX + ((size_t)t * B_ + b) * G4_;
    gi += __half2float(gx[j])          + g_bsum[j];
    gf += __half2float(gx[H_ + j])     + g_bsum[H_ + j];
    gg += __half2float(gx[2 * H_ + j]) + g_bsum[2 * H_ + j];
    go += __half2float(gx[3 * H_ + j]) + g_bsum[3 * H_ + j];
#pragma unroll
    for (int zz = 0; zz < 8; zz++) {
        const float* gp = g_ghp + (size_t)zz * B_ * NCAT + b * NCAT;
        gi += gp[j]; gf += gp[H_ + j]; gg += gp[2 * H_ + j]; go += gp[3 * H_ + j];
    }

    const float* c_cur = g_cbuf + (t & 1) * B_ * H_;
    float* c_nxt = g_cbuf + ((t + 1) & 1) * B_ * H_;
    __half* h_nxt = g_hall + (size_t)(t + 1) * B_ * H_;
    float si = 1.f / (1.f + __expf(-gi));
    float sf = 1.f / (1.f + __expf(-gf));
    float so = 1.f / (1.f + __expf(-go));
    float tg = tanhf(gg);
    float c  = sf * c_cur[b * H_ + j] + si * tg;
    c_nxt[b * H_ + j] = c;
    h_nxt[b * H_ + j] = __float2half(so * tanhf(c));
}

// ---------------- host ----------------
extern "C" void kernel_launch(void* const* d_in, const int* in_sizes, int n_in,
                              void* d_out, int out_size)
{
    const float* enc    = (const float*)d_in[0];
    const int*   caps   = (const int*)  d_in[1];
    const float* embed  = (const float*)d_in[2];
    const float* W_eatt = (const float*)d_in[3];
    const float* b_eatt = (const float*)d_in[4];
    const float* W_datt = (const float*)d_in[5];
    const float* b_datt = (const float*)d_in[6];
    const float* W_fatt = (const float*)d_in[7];
    const float* b_fatt = (const float*)d_in[8];
    const float* W_ih   = (const float*)d_in[9];
    const float* b_ih   = (const float*)d_in[10];
    const float* W_hh   = (const float*)d_in[11];
    const float* b_hh   = (const float*)d_in[12];
    const float* W_h0   = (const float*)d_in[13];
    const float* b_h0   = (const float*)d_in[14];
    const float* W_c0   = (const float*)d_in[15];
    const float* b_c0   = (const float*)d_in[16];
    const float* W_out  = (const float*)d_in[17];
    const float* b_out  = (const float*)d_in[18];
    float* out = (float*)d_out;

    cudaFuncSetAttribute(setup_combo, cudaFuncAttributeMaxDynamicSharedMemorySize, SMEM_BYTES);
    cudaFuncSetAttribute(hw_kernel, cudaFuncAttributeMaxDynamicSharedMemorySize, SMEM_BYTES);
    cudaFuncSetAttribute(logits_kernel, cudaFuncAttributeMaxDynamicSharedMemorySize, SMEM_BYTES);

    void* hall_p = nullptr;
    cudaGetSymbolAddress(&hall_p, g_hall);
    __half* hall = (__half*)hall_p;

    // ---- one-time setup ----
    mean_kernel<<<(B_ * ENC_ + 255) / 256, 256>>>(enc);
    cvt_all<<<(T8 / 4 + 255) / 256, 256>>>(W_out, W_eatt, W_h0, W_c0, enc, W_ih, W_hh,
                                           W_datt, b_h0, b_c0, b_ih, b_hh);
    embx_kernel<<<((T_ - 1) * B_ * E_ / 4 + 255) / 256, 256>>>(caps, embed);

    setup_combo<<<CB3, 256, SMEM_BYTES>>>(b_eatt);

    // ---- recurrent loop: 2 launches per step ----
    for (int t = 0; t < T_ - 1; t++) {
        hw_kernel<<<dim3(NCAT / 128, 8, 1), 256, SMEM_BYTES>>>(hall + (size_t)t * B_ * H_);
        gatelstm_kernel<<<dim3(4, B_, 1), 256>>>(b_datt, W_fatt, b_fatt, t);
    }

    // ---- batched logits: grid (12, ceil(10000/128)=79) ----
    logits_kernel<<<dim3(12, (V_ + 127) / 128, 1), 256, SMEM_BYTES>>>(b_out, out);
}

// round 12
// speedup vs baseline: 2.3185x; 1.0520x over previous
#include <cuda_runtime.h>
#include <cuda_fp16.h>
#include <cstdint>

#define B_    64
#define P_    49
#define ENC_  1280
#define T_    25
#define V_    10000
#define E_    512
#define H_    1024
#define A_    512
#define G4_   4096
#define NCAT  4608           /* 4*H + A */
#define WIH_LD 1792

#define BK 64
#define STG64  4
#define STG128 3
#define SMEM_BYTES 98304     /* = 4*(64+128)*64*2 = 3*(128+128)*64*2 */

// swizzled smem offset (halves): row r, 16B-chunk c (0..7)
__device__ __forceinline__ int sw(int r, int c) {
    return r * 64 + (((c ^ r) & 7) << 3) + ((c & ~7) << 3);
}

// ---------------- static scratch ----------------
__device__ __align__(16) __half g_Wout [V_ * H_];
__device__ __align__(16) __half g_Weatt[A_ * ENC_];
__device__ __align__(16) __half g_Wh0c0[2048 * ENC_];
__device__ __align__(16) __half g_Wihx [G4_ * E_];
__device__ __align__(16) __half g_Wihc [G4_ * ENC_];
__device__ __align__(16) __half g_Wcat [NCAT * H_];
__device__ __align__(16) __half g_ench [(B_ * P_ + 64) * ENC_];   /* +64 pad rows */
__device__ __align__(16) __half g_meanh[B_ * ENC_];
__device__ __align__(16) __half g_embX [(T_ - 1) * B_ * E_];
__device__ __align__(16) __half g_hall [T_ * B_ * H_];
__device__ __align__(16) __half g_encW [B_ * P_ * G4_];
__device__ __align__(16) __half g_gatesX[(T_ - 1) * B_ * G4_];
__device__ __align__(16) __half g_att1h[B_ * P_ * A_];
__device__ __align__(16) float  g_cbuf [2 * B_ * H_];
__device__ __align__(16) float  g_ghp  [8 * B_ * NCAT];
__device__ __align__(16) float  g_bh0c0[2048];
__device__ __align__(16) float  g_bsum [G4_];

// ---------------- setup conversions (4 elems / thread) ----------------
#define T0 (V_ * H_)
#define T1 (T0 + A_ * ENC_)
#define T2 (T1 + 2048 * ENC_)
#define T3 (T2 + B_ * P_ * ENC_)
#define T4 (T3 + G4_ * E_)
#define T5 (T4 + G4_ * ENC_)
#define T6 (T5 + NCAT * H_)
#define T7 (T6 + 2048)
#define T8 (T7 + G4_)

__device__ __forceinline__ void cvt4(__half* d, const float* s) {
    float4 v = *(const float4*)s;
    __half2* d2 = (__half2*)d;
    d2[0] = __floats2half2_rn(v.x, v.y);
    d2[1] = __floats2half2_rn(v.z, v.w);
}

__global__ void cvt_all(const float* __restrict__ Wo, const float* __restrict__ We,
                        const float* __restrict__ Wh0, const float* __restrict__ Wc0,
                        const float* __restrict__ enc, const float* __restrict__ Wih,
                        const float* __restrict__ Whh, const float* __restrict__ Wd,
                        const float* __restrict__ bh0, const float* __restrict__ bc0,
                        const float* __restrict__ bih, const float* __restrict__ bhh)
{
    int i = (blockIdx.x * 256 + threadIdx.x) * 4;
    if (i >= T8) return;
    if (i < T0) { cvt4(g_Wout + i, Wo + i); return; }
    if (i < T1) { cvt4(g_Weatt + (i - T0), We + (i - T0)); return; }
    if (i < T2) {
        int j = i - T1; int r = j / ENC_, c = j % ENC_;
        cvt4(g_Wh0c0 + j, (r < 1024 ? Wh0 + (size_t)r * ENC_ : Wc0 + (size_t)(r - 1024) * ENC_) + c);
        return;
    }
    if (i < T3) { cvt4(g_ench + (i - T2), enc + (i - T2)); return; }
    if (i < T4) {
        int j = i - T3; int r = j / E_, c = j % E_;
        cvt4(g_Wihx + j, Wih + (size_t)r * WIH_LD + c);
        return;
    }
    if (i < T5) {
        int j = i - T4; int r = j / ENC_, c = j % ENC_;
        cvt4(g_Wihc + j, Wih + (size_t)r * WIH_LD + E_ + c);
        return;
    }
    if (i < T6) {
        int j = i - T5; int r = j / H_, c = j % H_;
        cvt4(g_Wcat + j, (r < G4_ ? Whh + (size_t)r * H_ : Wd + (size_t)(r - G4_) * H_) + c);
        return;
    }
    if (i < T7) {
        int j = i - T6;
        *(float4*)(g_bh0c0 + j) = (j < 1024) ? *(const float4*)(bh0 + j)
                                             : *(const float4*)(bc0 + (j - 1024));
        return;
    }
    int j = i - T7;
    float4 a = *(const float4*)(bih + j), bv = *(const float4*)(bhh + j);
    *(float4*)(g_bsum + j) = make_float4(a.x + bv.x, a.y + bv.y, a.z + bv.z, a.w + bv.w);
}

__global__ void mean_kernel(const float* __restrict__ enc) {
    int i = blockIdx.x * blockDim.x + threadIdx.x;
    if (i >= B_ * ENC_) return;
    int b = i / ENC_, e = i % ENC_;
    const float* p = enc + (size_t)b * P_ * ENC_ + e;
    float s = 0.f;
#pragma unroll 7
    for (int k = 0; k < P_; k++) s += p[k * ENC_];
    g_meanh[i] = __float2half(s * (1.0f / P_));
}

__global__ void embx_kernel(const int* __restrict__ captions,
                            const float* __restrict__ embed)
{
    int i = (blockIdx.x * 256 + threadIdx.x) * 4;
    if (i >= (T_ - 1) * B_ * E_) return;
    int r = i / E_, c = i % E_;
    int t = r / B_, b = r % B_;
    int cap = captions[b * T_ + t];
    cvt4(g_embX + i, embed + (size_t)cap * E_ + c);
}

// ============ gemm64: 64x128 tile, 256 thr (M=64 GEMMs) =====================
__device__ __forceinline__ void issue_tile64(
    const __half* __restrict__ A, int lda,
    const __half* __restrict__ B, int ldb,
    int bm, int bn, int N, int kt,
    __half* as, __half* bs, int tid)
{
#pragma unroll
    for (int i = 0; i < 2; i++) {
        int idx = i * 256 + tid;
        int r = idx >> 3, c = idx & 7;
        uint32_t da = (uint32_t)__cvta_generic_to_shared(as + sw(r, c));
        const __half* pa = A + (size_t)(bm + r) * lda + kt + c * 8;
        asm volatile("cp.async.cg.shared.global [%0], [%1], 16;" :: "r"(da), "l"(pa));
    }
#pragma unroll
    for (int i = 0; i < 4; i++) {
        int idx = i * 256 + tid;
        int r = idx >> 3, c = idx & 7;
        int n = bn + r;
        uint32_t db = (uint32_t)__cvta_generic_to_shared(bs + sw(r, c));
        const __half* pb = B + (size_t)(n < N ? n : 0) * ldb + kt + c * 8;
        int sz = (n < N) ? 16 : 0;
        asm volatile("cp.async.cg.shared.global [%0], [%1], 16, %2;" :: "r"(db), "l"(pb), "r"(sz));
    }
    asm volatile("cp.async.commit_group;");
}

// mode: 0 = fp32 split-K partials, 3 = h0c0 split
__device__ __forceinline__ void gemm_core64(
    const __half* __restrict__ A, int lda,
    const __half* __restrict__ Bm, int ldb,
    float* __restrict__ Cf, int ldc, int partStride, int N, int kChunk,
    int bm, int by, int z, int mode)
{
    extern __shared__ __half sm[];
    __half* Asm = sm;
    __half* Bsm = sm + STG64 * 64 * 64;

    const int tid = threadIdx.x;
    const int warp = tid >> 5, lane = tid & 31;
    const int wm = warp >> 2, wn = warp & 3;
    const int bn = by * 128;
    const int k0 = z * kChunk;
    const int nk = kChunk / BK;

    float acc[2][4][4];
#pragma unroll
    for (int i = 0; i < 2; i++)
#pragma unroll
        for (int j = 0; j < 4; j++)
#pragma unroll
            for (int q = 0; q < 4; q++) acc[i][j][q] = 0.f;

    const int a_row_l = (lane & 7) + ((lane >> 3) & 1) * 8;
    const int a_chk_l = (lane >> 4) & 1;
    const int b_row_l = (lane & 7) + ((lane >> 4) & 1) * 8;
    const int b_chk_l = (lane >> 3) & 1;

#pragma unroll
    for (int s = 0; s < STG64 - 1; s++) {
        if (s < nk) issue_tile64(A, lda, Bm, ldb, bm, bn, N, k0 + s * BK,
                                 Asm + s * 64 * 64, Bsm + s * 128 * 64, tid);
        else asm volatile("cp.async.commit_group;");
    }

    for (int i = 0; i < nk; i++) {
        asm volatile("cp.async.wait_group %0;" :: "n"(STG64 - 2));
        __syncthreads();

        int ntile = i + STG64 - 1;
        if (ntile < nk) {
            int slot = ntile % STG64;
            issue_tile64(A, lda, Bm, ldb, bm, bn, N, k0 + ntile * BK,
                         Asm + slot * 64 * 64, Bsm + slot * 128 * 64, tid);
        } else {
            asm volatile("cp.async.commit_group;");
        }

        const __half* at = Asm + (i % STG64) * 64 * 64;
        const __half* bt = Bsm + (i % STG64) * 128 * 64;

#pragma unroll
        for (int ks = 0; ks < 4; ks++) {
            uint32_t a[2][4], b[4][2];
#pragma unroll
            for (int mt = 0; mt < 2; mt++) {
                int row = wm * 32 + mt * 16 + a_row_l;
                uint32_t ad = (uint32_t)__cvta_generic_to_shared(at + sw(row, ks * 2 + a_chk_l));
                asm volatile("ldmatrix.sync.aligned.m8n8.x4.shared.b16 {%0,%1,%2,%3}, [%4];"
                             : "=r"(a[mt][0]), "=r"(a[mt][1]), "=r"(a[mt][2]), "=r"(a[mt][3])
                             : "r"(ad));
            }
#pragma unroll
            for (int ntp = 0; ntp < 2; ntp++) {
                int row = wn * 32 + ntp * 16 + b_row_l;
                uint32_t bd = (uint32_t)__cvta_generic_to_shared(bt + sw(row, ks * 2 + b_chk_l));
                asm volatile("ldmatrix.sync.aligned.m8n8.x4.shared.b16 {%0,%1,%2,%3}, [%4];"
                             : "=r"(b[2 * ntp][0]), "=r"(b[2 * ntp][1]),
                               "=r"(b[2 * ntp + 1][0]), "=r"(b[2 * ntp + 1][1])
                             : "r"(bd));
            }
#pragma unroll
            for (int mt = 0; mt < 2; mt++)
#pragma unroll
                for (int nt = 0; nt < 4; nt++)
                    asm volatile(
                        "mma.sync.aligned.m16n8k16.row.col.f32.f16.f16.f32 "
                        "{%0,%1,%2,%3}, {%4,%5,%6,%7}, {%8,%9}, {%0,%1,%2,%3};"
                        : "+f"(acc[mt][nt][0]), "+f"(acc[mt][nt][1]),
                          "+f"(acc[mt][nt][2]), "+f"(acc[mt][nt][3])
                        : "r"(a[mt][0]), "r"(a[mt][1]), "r"(a[mt][2]), "r"(a[mt][3]),
                          "r"(b[nt][0]), "r"(b[nt][1]));
        }
    }

    float* Cz = Cf + (size_t)z * partStride;
#pragma unroll
    for (int mt = 0; mt < 2; mt++) {
        int r0 = bm + wm * 32 + mt * 16 + (lane >> 2);
        int r1 = r0 + 8;
#pragma unroll
        for (int nt = 0; nt < 4; nt++) {
            int cg = bn + wn * 32 + nt * 8 + (lane & 3) * 2;
            float v00 = acc[mt][nt][0], v01 = acc[mt][nt][1];
            float v10 = acc[mt][nt][2], v11 = acc[mt][nt][3];
            if (mode == 3) {
#pragma unroll
                for (int e = 0; e < 2; e++) {
                    int c = cg + e;
                    float va = e ? v01 : v00, vb = e ? v11 : v10;
                    float bb = g_bh0c0[c];
                    if (c < 1024) {
                        g_hall[r0 * H_ + c] = __float2half(va + bb);
                        g_hall[r1 * H_ + c] = __float2half(vb + bb);
                    } else {
                        g_cbuf[r0 * H_ + c - 1024] = va + bb;
                        g_cbuf[r1 * H_ + c - 1024] = vb + bb;
                    }
                }
            } else {
                if (cg < N) {
                    Cz[(size_t)r0 * ldc + cg] = v00;
                    Cz[(size_t)r1 * ldc + cg] = v10;
                }
                if (cg + 1 < N) {
                    Cz[(size_t)r0 * ldc + cg + 1] = v01;
                    Cz[(size_t)r1 * ldc + cg + 1] = v11;
                }
            }
        }
    }
}

// ============ gemm128: 128x128 tile, 256 thr, warp-tile 32x64 ===============
__device__ __forceinline__ void issue_tile128(
    const __half* __restrict__ A, int lda,
    const __half* __restrict__ B, int ldb,
    int bm, int bn, int N, int kt,
    __half* as, __half* bs, int tid)
{
#pragma unroll
    for (int i = 0; i < 4; i++) {
        int idx = i * 256 + tid;
        int r = idx >> 3, c = idx & 7;
        uint32_t da = (uint32_t)__cvta_generic_to_shared(as + sw(r, c));
        const __half* pa = A + (size_t)(bm + r) * lda + kt + c * 8;
        asm volatile("cp.async.cg.shared.global [%0], [%1], 16;" :: "r"(da), "l"(pa));
    }
#pragma unroll
    for (int i = 0; i < 4; i++) {
        int idx = i * 256 + tid;
        int r = idx >> 3, c = idx & 7;
        int n = bn + r;
        uint32_t db = (uint32_t)__cvta_generic_to_shared(bs + sw(r, c));
        const __half* pb = B + (size_t)(n < N ? n : 0) * ldb + kt + c * 8;
        int sz = (n < N) ? 16 : 0;
        asm volatile("cp.async.cg.shared.global [%0], [%1], 16, %2;" :: "r"(db), "l"(pb), "r"(sz));
    }
    asm volatile("cp.async.commit_group;");
}

// mode: 1 = fp16 out (+bias), 2 = logits capmap (+bias)
__device__ __forceinline__ void gemm_core128(
    const __half* __restrict__ A, int lda,
    const __half* __restrict__ Bm, int ldb,
    const float* __restrict__ bias,
    float* __restrict__ Cf, __half* __restrict__ Ch,
    int ldc, int M, int N, int K,
    int bm, int by, int mode)
{
    extern __shared__ __half sm[];
    __half* Asm = sm;
    __half* Bsm = sm + STG128 * 128 * 64;

    const int tid = threadIdx.x;
    const int warp = tid >> 5, lane = tid & 31;
    const int wm = warp >> 1, wn = warp & 1;
    const int bn = by * 128;
    const int nk = K / BK;

    float acc[2][8][4];
#pragma unroll
    for (int i = 0; i < 2; i++)
#pragma unroll
        for (int j = 0; j < 8; j++)
#pragma unroll
            for (int q = 0; q < 4; q++) acc[i][j][q] = 0.f;

    const int a_row_l = (lane & 7) + ((lane >> 3) & 1) * 8;
    const int a_chk_l = (lane >> 4) & 1;
    const int b_row_l = (lane & 7) + ((lane >> 4) & 1) * 8;
    const int b_chk_l = (lane >> 3) & 1;

#pragma unroll
    for (int s = 0; s < STG128 - 1; s++) {
        if (s < nk) issue_tile128(A, lda, Bm, ldb, bm, bn, N, s * BK,
                                  Asm + s * 128 * 64, Bsm + s * 128 * 64, tid);
        else asm volatile("cp.async.commit_group;");
    }

    for (int i = 0; i < nk; i++) {
        asm volatile("cp.async.wait_group %0;" :: "n"(STG128 - 2));
        __syncthreads();

        int ntile = i + STG128 - 1;
        if (ntile < nk) {
            int slot = ntile % STG128;
            issue_tile128(A, lda, Bm, ldb, bm, bn, N, ntile * BK,
                          Asm + slot * 128 * 64, Bsm + slot * 128 * 64, tid);
        } else {
            asm volatile("cp.async.commit_group;");
        }

        const __half* at = Asm + (i % STG128) * 128 * 64;
        const __half* bt = Bsm + (i % STG128) * 128 * 64;

#pragma unroll
        for (int ks = 0; ks < 4; ks++) {
            uint32_t a[2][4], b[8][2];
#pragma unroll
            for (int mt = 0; mt < 2; mt++) {
                int row = wm * 32 + mt * 16 + a_row_l;
                uint32_t ad = (uint32_t)__cvta_generic_to_shared(at + sw(row, ks * 2 + a_chk_l));
                asm volatile("ldmatrix.sync.aligned.m8n8.x4.shared.b16 {%0,%1,%2,%3}, [%4];"
                             : "=r"(a[mt][0]), "=r"(a[mt][1]), "=r"(a[mt][2]), "=r"(a[mt][3])
                             : "r"(ad));
            }
#pragma unroll
            for (int ntp = 0; ntp < 4; ntp++) {
                int row = wn * 64 + ntp * 16 + b_row_l;
                uint32_t bd = (uint32_t)__cvta_generic_to_shared(bt + sw(row, ks * 2 + b_chk_l));
                asm volatile("ldmatrix.sync.aligned.m8n8.x4.shared.b16 {%0,%1,%2,%3}, [%4];"
                             : "=r"(b[2 * ntp][0]), "=r"(b[2 * ntp][1]),
                               "=r"(b[2 * ntp + 1][0]), "=r"(b[2 * ntp + 1][1])
                             : "r"(bd));
            }
#pragma unroll
            for (int mt = 0; mt < 2; mt++)
#pragma unroll
                for (int nt = 0; nt < 8; nt++)
                    asm volatile(
                        "mma.sync.aligned.m16n8k16.row.col.f32.f16.f16.f32 "
                        "{%0,%1,%2,%3}, {%4,%5,%6,%7}, {%8,%9}, {%0,%1,%2,%3};"
                        : "+f"(acc[mt][nt][0]), "+f"(acc[mt][nt][1]),
                          "+f"(acc[mt][nt][2]), "+f"(acc[mt][nt][3])
                        : "r"(a[mt][0]), "r"(a[mt][1]), "r"(a[mt][2]), "r"(a[mt][3]),
                          "r"(b[nt][0]), "r"(b[nt][1]));
        }
    }

#pragma unroll
    for (int mt = 0; mt < 2; mt++) {
        int r0 = bm + wm * 32 + mt * 16 + (lane >> 2);
        int r1 = r0 + 8;
#pragma unroll
        for (int nt = 0; nt < 8; nt++) {
            int cg = bn + wn * 64 + nt * 8 + (lane & 3) * 2;
            float bv0 = 0.f, bv1 = 0.f;
            if (bias) {
                if (cg < N) bv0 = bias[cg];
                if (cg + 1 < N) bv1 = bias[cg + 1];
            }
            float v00 = acc[mt][nt][0] + bv0, v01 = acc[mt][nt][1] + bv1;
            float v10 = acc[mt][nt][2] + bv0, v11 = acc[mt][nt][3] + bv1;
            if (mode == 2) {
                float* p0 = Cf + (size_t)(r0 & 63) * ((T_ - 1) * V_) + (size_t)(r0 >> 6) * V_;
                float* p1 = Cf + (size_t)(r1 & 63) * ((T_ - 1) * V_) + (size_t)(r1 >> 6) * V_;
                if (cg < N) {
                    if (r0 < M) p0[cg] = v00;
                    if (r1 < M) p1[cg] = v10;
                }
                if (cg + 1 < N) {
                    if (r0 < M) p0[cg + 1] = v01;
                    if (r1 < M) p1[cg + 1] = v11;
                }
            } else {
                if (cg < N) {
                    if (r0 < M) Ch[(size_t)r0 * ldc + cg] = __float2half(v00);
                    if (r1 < M) Ch[(size_t)r1 * ldc + cg] = __float2half(v10);
                }
                if (cg + 1 < N) {
                    if (r0 < M) Ch[(size_t)r0 * ldc + cg + 1] = __float2half(v01);
                    if (r1 < M) Ch[(size_t)r1 * ldc + cg + 1] = __float2half(v11);
                }
            }
        }
    }
}

// setup: h0c0 [16] + att1 [100] + gatesX [384] + encW [800] = 1300 blocks
#define CB0 16
#define CB1 (CB0 + 25 * 4)
#define CB2 (CB1 + 12 * 32)
#define CB3 (CB2 + 25 * 32)

__global__ void __launch_bounds__(256, 2)
setup_combo(const float* __restrict__ b_eatt)
{
    int bi = blockIdx.x;
    if (bi < CB0) {
        gemm_core64(g_meanh, ENC_, g_Wh0c0, ENC_, nullptr,
                    0, 0, 2048, ENC_, 0, bi, 0, 3);
    } else if (bi < CB1) {
        int i = bi - CB0;
        gemm_core128(g_ench, ENC_, g_Weatt, ENC_, b_eatt, nullptr, g_att1h,
                     A_, B_ * P_, A_, ENC_, (i % 25) * 128, i / 25, 1);
    } else if (bi < CB2) {
        int i = bi - CB1;
        gemm_core128(g_embX, E_, g_Wihx, E_, nullptr, nullptr, g_gatesX,
                     G4_, (T_ - 1) * B_, G4_, E_, (i % 12) * 128, i / 12, 1);
    } else {
        int i = bi - CB2;
        gemm_core128(g_ench, ENC_, g_Wihc, ENC_, nullptr, nullptr, g_encW,
                     G4_, B_ * P_, G4_, ENC_, (i % 25) * 128, i / 25, 1);
    }
}

// per-step fused GEMM: h_t @ [W_hh | W_datt]^T -> ghp partials (split-K 8)
__global__ void __launch_bounds__(256, 2)
hw_kernel(const __half* __restrict__ h)
{
    gemm_core64(h, H_, g_Wcat, H_, g_ghp,
                NCAT, B_ * NCAT, NCAT, H_ / 8, 0, blockIdx.x, blockIdx.y, 0);
}

// batched logits: M=1536, N=10000, K=1024 — grid (12, 79)
__global__ void __launch_bounds__(256, 2)
logits_kernel(const float* __restrict__ b_out, float* __restrict__ out)
{
    gemm_core128(g_hall + B_ * H_, H_, g_Wout, H_, b_out, out, nullptr,
                 0, 1536, V_, H_, blockIdx.x * 128, blockIdx.y, 2);
}

// ---------------- gate+LSTM: 4 stripes x 64 b = 256 blocks ------------------
__global__ void __launch_bounds__(256)
gatelstm_kernel(const float* __restrict__ b_datt,
                const float* __restrict__ W_fatt,
                const float* __restrict__ b_fatt,
                int t)
{
    const int z = blockIdx.x;
    const int b = blockIdx.y;
    const int tid = threadIdx.x;
    const int warp = tid >> 5, lane = tid & 31;

    __shared__ float att2s[A_];
    __shared__ float alpha[P_];

    for (int a = tid; a < A_; a += 256) {
        float s = b_datt[a];
#pragma unroll
        for (int zz = 0; zz < 8; zz++)
            s += g_ghp[(size_t)zz * B_ * NCAT + b * NCAT + G4_ + a];
        att2s[a] = s;
    }
    __syncthreads();

    const __half* att1b = g_att1h + (size_t)b * P_ * A_;
#pragma unroll 7
    for (int p = warp; p < P_; p += 8) {
        float s = 0.f;
#pragma unroll
        for (int a = lane; a < A_; a += 32) {
            float v = __half2float(att1b[p * A_ + a]) + att2s[a];
            s += fmaxf(v, 0.f) * W_fatt[a];
        }
#pragma unroll
        for (int o = 16; o; o >>= 1) s += __shfl_xor_sync(0xffffffffu, s, o);
        if (lane == 0) alpha[p] = s + b_fatt[0];
    }
    __syncthreads();

    if (warp == 0) {
        float v0 = (lane < P_) ? alpha[lane] : -1e30f;
        float v1 = (lane + 32 < P_) ? alpha[lane + 32] : -1e30f;
        float m = fmaxf(v0, v1);
#pragma unroll
        for (int o = 16; o; o >>= 1) m = fmaxf(m, __shfl_xor_sync(0xffffffffu, m, o));
        float e0 = (lane < P_) ? __expf(v0 - m) : 0.f;
        float e1 = (lane + 32 < P_) ? __expf(v1 - m) : 0.f;
        float s = e0 + e1;
#pragma unroll
        for (int o = 16; o; o >>= 1) s += __shfl_xor_sync(0xffffffffu, s, o);
        float inv = 1.0f / s;
        if (lane < P_) alpha[lane] = e0 * inv;
        if (lane + 32 < P_) alpha[lane + 32] = e1 * inv;
    }
    __syncthreads();

    const int j = z * 256 + tid;
    const __half* encWb = g_encW + (size_t)b * P_ * G4_;
    float gi = 0.f, gf = 0.f, gg = 0.f, go = 0.f;
#pragma unroll 7
    for (int p = 0; p < P_; p++) {
        const __half* row = encWb + (size_t)p * G4_;
        float ap = alpha[p];
        gi += ap * __half2float(row[j]);
        gf += ap * __half2float(row[H_ + j]);
        gg += ap * __half2float(row[2 * H_ + j]);
        go += ap * __half2float(row[3 * H_ + j]);
    }
    const __half* gx = g_gatesX + ((size_t)t * B_ + b) * G4_;
    gi += __half2float(gx[j])          + g_bsum[j];
    gf += __half2float(gx[H_ + j])     + g_bsum[H_ + j];
    gg += __half2float(gx[2 * H_ + j]) + g_bsum[2 * H_ + j];
    go += __half2float(gx[3 * H_ + j]) + g_bsum[3 * H_ + j];
#pragma unroll
    for (int zz = 0; zz < 8; zz++) {
        const float* gp = g_ghp + (size_t)zz * B_ * NCAT + b * NCAT;
        gi += gp[j]; gf += gp[H_ + j]; gg += gp[2 * H_ + j]; go += gp[3 * H_ + j];
    }

    const float* c_cur = g_cbuf + (t & 1) * B_ * H_;
    float* c_nxt = g_cbuf + ((t + 1) & 1) * B_ * H_;
    __half* h_nxt = g_hall + (size_t)(t + 1) * B_ * H_;
    float si = 1.f / (1.f + __expf(-gi));
    float sf = 1.f / (1.f + __expf(-gf));
    float so = 1.f / (1.f + __expf(-go));
    float tg = tanhf(gg);
    float c  = sf * c_cur[b * H_ + j] + si * tg;
    c_nxt[b * H_ + j] = c;
    h_nxt[b * H_ + j] = __float2half(so * tanhf(c));
}

// ---------------- host ----------------
extern "C" void kernel_launch(void* const* d_in, const int* in_sizes, int n_in,
                              void* d_out, int out_size)
{
    const float* enc    = (const float*)d_in[0];
    const int*   caps   = (const int*)  d_in[1];
    const float* embed  = (const float*)d_in[2];
    const float* W_eatt = (const float*)d_in[3];
    const float* b_eatt = (const float*)d_in[4];
    const float* W_datt = (const float*)d_in[5];
    const float* b_datt = (const float*)d_in[6];
    const float* W_fatt = (const float*)d_in[7];
    const float* b_fatt = (const float*)d_in[8];
    const float* W_ih   = (const float*)d_in[9];
    const float* b_ih   = (const float*)d_in[10];
    const float* W_hh   = (const float*)d_in[11];
    const float* b_hh   = (const float*)d_in[12];
    const float* W_h0   = (const float*)d_in[13];
    const float* b_h0   = (const float*)d_in[14];
    const float* W_c0   = (const float*)d_in[15];
    const float* b_c0   = (const float*)d_in[16];
    const float* W_out  = (const float*)d_in[17];
    const float* b_out  = (const float*)d_in[18];
    float* out = (float*)d_out;

    cudaFuncSetAttribute(setup_combo, cudaFuncAttributeMaxDynamicSharedMemorySize, SMEM_BYTES);
    cudaFuncSetAttribute(hw_kernel, cudaFuncAttributeMaxDynamicSharedMemorySize, SMEM_BYTES);
    cudaFuncSetAttribute(logits_kernel, cudaFuncAttributeMaxDynamicSharedMemorySize, SMEM_BYTES);

    void* hall_p = nullptr;
    cudaGetSymbolAddress(&hall_p, g_hall);
    __half* hall = (__half*)hall_p;

    // ---- one-time setup ----
    mean_kernel<<<(B_ * ENC_ + 255) / 256, 256>>>(enc);
    cvt_all<<<(T8 / 4 + 255) / 256, 256>>>(W_out, W_eatt, W_h0, W_c0, enc, W_ih, W_hh,
                                           W_datt, b_h0, b_c0, b_ih, b_hh);
    embx_kernel<<<((T_ - 1) * B_ * E_ / 4 + 255) / 256, 256>>>(caps, embed);

    setup_combo<<<CB3, 256, SMEM_BYTES>>>(b_eatt);

    // ---- recurrent loop: 2 launches per step ----
    for (int t = 0; t < T_ - 1; t++) {
        hw_kernel<<<dim3(NCAT / 128, 8, 1), 256, SMEM_BYTES>>>(hall + (size_t)t * B_ * H_);
        gatelstm_kernel<<<dim3(4, B_, 1), 256>>>(b_datt, W_fatt, b_fatt, t);
    }

    // ---- batched logits: grid (12, ceil(10000/128)=79) ----
    logits_kernel<<<dim3(12, (V_ + 127) / 128, 1), 256, SMEM_BYTES>>>(b_out, out);
}